// round 5
// baseline (speedup 1.0000x reference)
#include <cuda_runtime.h>
#include <math.h>
#include <stdint.h>

#define NTOK 1024
#define DINV 512
#define NFV  4
#define NHV  8
#define HDV  64

// -------- scratch (device globals; no allocation allowed) --------
__device__ float g_cm[2][NFV][DINV];               // [qkv|proj][f][d]
__device__ float g_q[NHV * NFV * NTOK * HDV];      // [h][f][n][d], tf32, pre-scaled hd^-0.5
__device__ float g_k[NHV * NFV * NTOK * HDV];      // tf32
__device__ float g_v[NHV * NFV * NTOK * HDV];      // tf32
__device__ float g_yhat[NFV * NTOK * DINV];        // [f][n][h*64+d]
__device__ float g_callT[NTOK * NFV];              // [c][f] transposed compat

// ============================================================
// helpers
// ============================================================
__device__ __forceinline__ float to_tf32(float x) {
    uint32_t u;
    asm("cvt.rna.tf32.f32 %0, %1;" : "=r"(u) : "f"(x));
    return __uint_as_float(u);
}

__device__ __forceinline__ void mma_tf32(float* d, uint32_t a0, uint32_t a1,
                                         uint32_t a2, uint32_t a3,
                                         uint32_t b0, uint32_t b1) {
    asm volatile(
        "mma.sync.aligned.m16n8k8.row.col.f32.tf32.tf32.f32 "
        "{%0,%1,%2,%3}, {%4,%5,%6,%7}, {%8,%9}, {%0,%1,%2,%3};"
        : "+f"(d[0]), "+f"(d[1]), "+f"(d[2]), "+f"(d[3])
        : "r"(a0), "r"(a1), "r"(a2), "r"(a3), "r"(b0), "r"(b1));
}

__device__ __forceinline__ uint32_t smem_u32(const void* p) {
    uint32_t a;
    asm("{ .reg .u64 t; cvta.to.shared.u64 t, %1; cvt.u32.u64 %0, t; }" : "=r"(a) : "l"(p));
    return a;
}

__device__ __forceinline__ void cp_async16(uint32_t dst, const void* src) {
    asm volatile("cp.async.cg.shared.global [%0], [%1], 16;" :: "r"(dst), "l"(src) : "memory");
}
#define CP_COMMIT() asm volatile("cp.async.commit_group;" ::: "memory")
#define CP_WAIT0()  asm volatile("cp.async.wait_group 0;" ::: "memory")
#define CP_WAIT1()  asm volatile("cp.async.wait_group 1;" ::: "memory")

// stage one 128x64 fp32 tile into smem with row stride 68 (16B chunks), NT threads
template <int NT>
__device__ __forceinline__ void stage_kv(uint32_t dstbase, const float* src, int tid) {
    #pragma unroll
    for (int i = tid; i < 2048; i += NT) {
        int row = i >> 4, c4 = (i & 15) << 2;
        cp_async16(dstbase + (uint32_t)(row * 68 + c4) * 4, src + row * 64 + c4);
    }
}

// ============================================================
// K1: code_mod = LayerNorm((w_c @ code).T) * g + b, both variants
// ============================================================
__global__ __launch_bounds__(512) void code_mod_kernel(
    const float* __restrict__ wc, const float* __restrict__ code,
    const float* __restrict__ gq, const float* __restrict__ bq,
    const float* __restrict__ gp, const float* __restrict__ bp)
{
    int d = threadIdx.x;
    float t[NFV] = {0.f, 0.f, 0.f, 0.f};
    for (int k = 0; k < 128; k++) {
        float w = wc[d * 128 + k];
        #pragma unroll
        for (int f = 0; f < NFV; f++) t[f] += w * code[k * NFV + f];
    }
    __shared__ float red[512];
    float gqd = gq[d], bqd = bq[d], gpd = gp[d], bpd = bp[d];
    for (int f = 0; f < NFV; f++) {
        red[d] = t[f];
        __syncthreads();
        for (int s = 256; s > 0; s >>= 1) {
            if (d < s) red[d] += red[d + s];
            __syncthreads();
        }
        float mu = red[0] * (1.f / 512.f);
        __syncthreads();
        float dv = t[f] - mu;
        red[d] = dv * dv;
        __syncthreads();
        for (int s = 256; s > 0; s >>= 1) {
            if (d < s) red[d] += red[d + s];
            __syncthreads();
        }
        float var = red[0] * (1.f / 512.f);
        __syncthreads();
        float nrm = dv * rsqrtf(var + 1e-5f);
        g_cm[0][f][d] = nrm * gqd + bqd;
        g_cm[1][f][d] = nrm * gpd + bpd;
    }
}

// tiny: transpose compat into [c][f]
__global__ __launch_bounds__(256) void prep_callT(const float* __restrict__ cin) {
    int c = blockIdx.x * 256 + threadIdx.x;
    float4 v = make_float4(cin[c], cin[NTOK + c], cin[2 * NTOK + c], cin[3 * NTOK + c]);
    *(float4*)&g_callT[c * 4] = v;
}

// ============================================================
// QKV GEMM (128x128 tile, BK=32, tf32 mma): outputs tf32-rounded q/k/v
// 2 blocks/SM (74.5KB smem each) for cross-block load/MMA overlap.
// ============================================================
#define GA0   0
#define GA1   4608
#define GB0   9216
#define GB1   13824
#define GSC   18432
#define GBIAS 18944
#define GEMM_SMEM_FLOATS 19072

__global__ __launch_bounds__(256, 2) void gemm_qkv(
    const float* __restrict__ Ain, const float* __restrict__ Bw,
    const float* __restrict__ bias)
{
    extern __shared__ float sm[];
    const int f   = blockIdx.z;
    const int bm0 = blockIdx.y * 128;
    const int bn0 = blockIdx.x * 128;
    const int tid = threadIdx.x;
    const int warp = tid >> 5, lane = tid & 31;
    const int gid = lane >> 2, tig = lane & 3;
    const int wm = warp >> 2, wn = warp & 3;
    const float* A = Ain;

    sm[GSC + tid]       = g_cm[0][f][tid];
    sm[GSC + tid + 256] = g_cm[0][f][tid + 256];
    if (tid < 128) sm[GBIAS + tid] = bias[bn0 + tid];

    const int rb = tid >> 3;
    const int k4 = (tid & 7) * 4;

    float4 ra[4], rbv[4];
    #pragma unroll
    for (int it = 0; it < 4; it++) {
        ra[it]  = *(const float4*)(A  + (size_t)(bm0 + rb + 32 * it) * 512 + k4);
        rbv[it] = *(const float4*)(Bw + (size_t)(bn0 + rb + 32 * it) * 512 + k4);
    }
    __syncthreads();
    {
        float s0 = sm[GSC + k4], s1 = sm[GSC + k4 + 1],
              s2 = sm[GSC + k4 + 2], s3 = sm[GSC + k4 + 3];
        #pragma unroll
        for (int it = 0; it < 4; it++) {
            int row = rb + 32 * it;
            float* pa = sm + GA0 + row * 36 + k4;
            pa[0] = to_tf32(ra[it].x * s0); pa[1] = to_tf32(ra[it].y * s1);
            pa[2] = to_tf32(ra[it].z * s2); pa[3] = to_tf32(ra[it].w * s3);
            float* pb = sm + GB0 + row * 36 + k4;
            pb[0] = to_tf32(rbv[it].x); pb[1] = to_tf32(rbv[it].y);
            pb[2] = to_tf32(rbv[it].z); pb[3] = to_tf32(rbv[it].w);
        }
    }
    __syncthreads();

    float d[4][4][4];
    #pragma unroll
    for (int mt = 0; mt < 4; mt++)
        #pragma unroll
        for (int nt = 0; nt < 4; nt++)
            #pragma unroll
            for (int q = 0; q < 4; q++) d[mt][nt][q] = 0.f;

    for (int c = 0; c < 16; c++) {
        int cb = c & 1;
        if (c < 15) {
            int k0 = (c + 1) * 32;
            #pragma unroll
            for (int it = 0; it < 4; it++) {
                ra[it]  = *(const float4*)(A  + (size_t)(bm0 + rb + 32 * it) * 512 + k0 + k4);
                rbv[it] = *(const float4*)(Bw + (size_t)(bn0 + rb + 32 * it) * 512 + k0 + k4);
            }
        }
        const float* Ab = sm + (cb ? GA1 : GA0);
        const float* Bb = sm + (cb ? GB1 : GB0);
        #pragma unroll
        for (int kk = 0; kk < 4; kk++) {
            uint32_t aa[4][4], bb[4][2];
            #pragma unroll
            for (int mt = 0; mt < 4; mt++) {
                const float* p = Ab + (wm * 64 + mt * 16) * 36 + kk * 8;
                aa[mt][0] = __float_as_uint(p[gid * 36 + tig]);
                aa[mt][1] = __float_as_uint(p[(gid + 8) * 36 + tig]);
                aa[mt][2] = __float_as_uint(p[gid * 36 + tig + 4]);
                aa[mt][3] = __float_as_uint(p[(gid + 8) * 36 + tig + 4]);
            }
            #pragma unroll
            for (int nt = 0; nt < 4; nt++) {
                const float* p = Bb + (wn * 32 + nt * 8 + gid) * 36 + kk * 8;
                bb[nt][0] = __float_as_uint(p[tig]);
                bb[nt][1] = __float_as_uint(p[tig + 4]);
            }
            #pragma unroll
            for (int mt = 0; mt < 4; mt++)
                #pragma unroll
                for (int nt = 0; nt < 4; nt++)
                    mma_tf32(d[mt][nt], aa[mt][0], aa[mt][1], aa[mt][2], aa[mt][3],
                             bb[nt][0], bb[nt][1]);
        }
        __syncthreads();
        if (c < 15) {
            int k0 = (c + 1) * 32;
            float s0 = sm[GSC + k0 + k4], s1 = sm[GSC + k0 + k4 + 1],
                  s2 = sm[GSC + k0 + k4 + 2], s3 = sm[GSC + k0 + k4 + 3];
            float* Ad = sm + ((cb ^ 1) ? GA1 : GA0);
            float* Bd = sm + ((cb ^ 1) ? GB1 : GB0);
            #pragma unroll
            for (int it = 0; it < 4; it++) {
                int row = rb + 32 * it;
                float* pa = Ad + row * 36 + k4;
                pa[0] = to_tf32(ra[it].x * s0); pa[1] = to_tf32(ra[it].y * s1);
                pa[2] = to_tf32(ra[it].z * s2); pa[3] = to_tf32(ra[it].w * s3);
                float* pb = Bd + row * 36 + k4;
                pb[0] = to_tf32(rbv[it].x); pb[1] = to_tf32(rbv[it].y);
                pb[2] = to_tf32(rbv[it].z); pb[3] = to_tf32(rbv[it].w);
            }
            __syncthreads();
        }
    }

    const int jb = bn0 + wn * 32;
    int tt = jb >> 9;
    int h  = (jb >> 6) & 7;
    int db = jb & 63;
    float mul = (tt == 0) ? 0.125f : 1.0f;
    float* base = (tt == 0 ? g_q : tt == 1 ? g_k : g_v)
                  + (size_t)((h * NFV + f) * NTOK) * HDV;
    #pragma unroll
    for (int mt = 0; mt < 4; mt++) {
        int m0 = bm0 + wm * 64 + mt * 16 + gid;
        #pragma unroll
        for (int nt = 0; nt < 4; nt++) {
            int dc = db + nt * 8 + tig * 2;
            float b0 = sm[GBIAS + wn * 32 + nt * 8 + tig * 2];
            float b1 = sm[GBIAS + wn * 32 + nt * 8 + tig * 2 + 1];
            float2 v0 = {to_tf32((d[mt][nt][0] + b0) * mul), to_tf32((d[mt][nt][1] + b1) * mul)};
            float2 v1 = {to_tf32((d[mt][nt][2] + b0) * mul), to_tf32((d[mt][nt][3] + b1) * mul)};
            *(float2*)(base + (size_t)m0 * HDV + dc)       = v0;
            *(float2*)(base + (size_t)(m0 + 8) * HDV + dc) = v1;
        }
    }
}

// ============================================================
// proj GEMM: 64x128 tile, 2 blocks/SM
// ============================================================
#define H64_A0   0
#define H64_A1   2304
#define H64_B0   4608
#define H64_B1   9216
#define H64_SC   13824
#define H64_BIAS 14336
#define H64_FLOATS 14464

__global__ __launch_bounds__(256, 2) void gemm_proj(
    const float* __restrict__ Bw, const float* __restrict__ bias,
    float* __restrict__ Out)
{
    extern __shared__ float sm[];
    const int f   = blockIdx.z;
    const int bm0 = blockIdx.y * 64;
    const int bn0 = blockIdx.x * 128;
    const int tid = threadIdx.x;
    const int warp = tid >> 5, lane = tid & 31;
    const int gid = lane >> 2, tig = lane & 3;
    const int wm = warp >> 2, wn = warp & 3;
    const float* A = g_yhat + (size_t)f * NTOK * DINV;

    sm[H64_SC + tid]       = g_cm[1][f][tid];
    sm[H64_SC + tid + 256] = g_cm[1][f][tid + 256];
    if (tid < 128) sm[H64_BIAS + tid] = bias[bn0 + tid];

    const int rb = tid >> 3;
    const int k4 = (tid & 7) * 4;

    float4 ra[2], rbv[4];
    #pragma unroll
    for (int it = 0; it < 2; it++)
        ra[it] = *(const float4*)(A + (size_t)(bm0 + rb + 32 * it) * 512 + k4);
    #pragma unroll
    for (int it = 0; it < 4; it++)
        rbv[it] = *(const float4*)(Bw + (size_t)(bn0 + rb + 32 * it) * 512 + k4);
    __syncthreads();
    {
        float s0 = sm[H64_SC + k4], s1 = sm[H64_SC + k4 + 1],
              s2 = sm[H64_SC + k4 + 2], s3 = sm[H64_SC + k4 + 3];
        #pragma unroll
        for (int it = 0; it < 2; it++) {
            float* pa = sm + H64_A0 + (rb + 32 * it) * 36 + k4;
            pa[0] = to_tf32(ra[it].x * s0); pa[1] = to_tf32(ra[it].y * s1);
            pa[2] = to_tf32(ra[it].z * s2); pa[3] = to_tf32(ra[it].w * s3);
        }
        #pragma unroll
        for (int it = 0; it < 4; it++) {
            float* pb = sm + H64_B0 + (rb + 32 * it) * 36 + k4;
            pb[0] = to_tf32(rbv[it].x); pb[1] = to_tf32(rbv[it].y);
            pb[2] = to_tf32(rbv[it].z); pb[3] = to_tf32(rbv[it].w);
        }
    }
    __syncthreads();

    float d[2][4][4];
    #pragma unroll
    for (int mt = 0; mt < 2; mt++)
        #pragma unroll
        for (int nt = 0; nt < 4; nt++)
            #pragma unroll
            for (int q = 0; q < 4; q++) d[mt][nt][q] = 0.f;

    for (int c = 0; c < 16; c++) {
        int cb = c & 1;
        if (c < 15) {
            int k0 = (c + 1) * 32;
            #pragma unroll
            for (int it = 0; it < 2; it++)
                ra[it] = *(const float4*)(A + (size_t)(bm0 + rb + 32 * it) * 512 + k0 + k4);
            #pragma unroll
            for (int it = 0; it < 4; it++)
                rbv[it] = *(const float4*)(Bw + (size_t)(bn0 + rb + 32 * it) * 512 + k0 + k4);
        }
        const float* Ab = sm + (cb ? H64_A1 : H64_A0);
        const float* Bb = sm + (cb ? H64_B1 : H64_B0);
        #pragma unroll
        for (int kk = 0; kk < 4; kk++) {
            uint32_t aa[2][4], bb[4][2];
            #pragma unroll
            for (int mt = 0; mt < 2; mt++) {
                const float* p = Ab + (wm * 32 + mt * 16) * 36 + kk * 8;
                aa[mt][0] = __float_as_uint(p[gid * 36 + tig]);
                aa[mt][1] = __float_as_uint(p[(gid + 8) * 36 + tig]);
                aa[mt][2] = __float_as_uint(p[gid * 36 + tig + 4]);
                aa[mt][3] = __float_as_uint(p[(gid + 8) * 36 + tig + 4]);
            }
            #pragma unroll
            for (int nt = 0; nt < 4; nt++) {
                const float* p = Bb + (wn * 32 + nt * 8 + gid) * 36 + kk * 8;
                bb[nt][0] = __float_as_uint(p[tig]);
                bb[nt][1] = __float_as_uint(p[tig + 4]);
            }
            #pragma unroll
            for (int mt = 0; mt < 2; mt++)
                #pragma unroll
                for (int nt = 0; nt < 4; nt++)
                    mma_tf32(d[mt][nt], aa[mt][0], aa[mt][1], aa[mt][2], aa[mt][3],
                             bb[nt][0], bb[nt][1]);
        }
        __syncthreads();
        if (c < 15) {
            int k0 = (c + 1) * 32;
            float s0 = sm[H64_SC + k0 + k4], s1 = sm[H64_SC + k0 + k4 + 1],
                  s2 = sm[H64_SC + k0 + k4 + 2], s3 = sm[H64_SC + k0 + k4 + 3];
            float* Ad = sm + ((cb ^ 1) ? H64_A1 : H64_A0);
            float* Bd = sm + ((cb ^ 1) ? H64_B1 : H64_B0);
            #pragma unroll
            for (int it = 0; it < 2; it++) {
                float* pa = Ad + (rb + 32 * it) * 36 + k4;
                pa[0] = to_tf32(ra[it].x * s0); pa[1] = to_tf32(ra[it].y * s1);
                pa[2] = to_tf32(ra[it].z * s2); pa[3] = to_tf32(ra[it].w * s3);
            }
            #pragma unroll
            for (int it = 0; it < 4; it++) {
                float* pb = Bd + (rb + 32 * it) * 36 + k4;
                pb[0] = to_tf32(rbv[it].x); pb[1] = to_tf32(rbv[it].y);
                pb[2] = to_tf32(rbv[it].z); pb[3] = to_tf32(rbv[it].w);
            }
            __syncthreads();
        }
    }

    float* outp = Out + (size_t)f * NTOK * DINV;
    #pragma unroll
    for (int mt = 0; mt < 2; mt++) {
        int m0 = bm0 + wm * 32 + mt * 16 + gid;
        #pragma unroll
        for (int nt = 0; nt < 4; nt++) {
            int j = bn0 + wn * 32 + nt * 8 + tig * 2;
            float b0 = sm[H64_BIAS + wn * 32 + nt * 8 + tig * 2];
            float b1 = sm[H64_BIAS + wn * 32 + nt * 8 + tig * 2 + 1];
            float2 v0 = {d[mt][nt][0] + b0, d[mt][nt][1] + b1};
            float2 v1 = {d[mt][nt][2] + b0, d[mt][nt][3] + b1};
            *(float2*)(outp + (size_t)m0 * 512 + j)       = v0;
            *(float2*)(outp + (size_t)(m0 + 8) * 512 + j) = v1;
        }
    }
}

// ============================================================
// attention: 512 threads (16 warps), cp.async double-buffered K/V
// smem: S 0 (32x1036) | QS 33152 | KV0 35328 | KV1 44032 | CROW 52736
//       RMAX 52864 (32x8) | INV2 53120 | total 53152 floats (~208KB)
// ============================================================
#define SSTR    1036
#define AO_QS   33152
#define AO_KV0  35328
#define AO_KV1  44032
#define AO_CROW 52736
#define AO_RMAX 52864
#define AO_INV2 53120
#define ATTN_SMEM_FLOATS 53152

__global__ __launch_bounds__(512) void attn_kernel(const float* __restrict__ cin)
{
    extern __shared__ float sm[];
    float* S    = sm;
    float* Qs   = sm + AO_QS;
    float* crow = sm + AO_CROW;
    float* rmax = sm + AO_RMAX;
    float* inv2 = sm + AO_INV2;

    const int tid = threadIdx.x;
    const int warp = tid >> 5, lane = tid & 31;
    const int gid = lane >> 2, tig = lane & 3;
    const int n0  = blockIdx.x * 32;
    const int hf  = blockIdx.y;
    const int h   = hf >> 2, f = hf & 3;
    const size_t hb = (size_t)hf * NTOK * HDV;

    uint32_t sb  = smem_u32(sm);
    uint32_t kv0 = sb + AO_KV0 * 4;
    uint32_t kv1 = sb + AO_KV1 * 4;
    const float* Kp = g_k + hb;
    const float* Vp = g_v + hb;

    // prefetch K tile 0
    stage_kv<512>(kv0, Kp, tid);
    CP_COMMIT();

    // Q block (already tf32): 512 float4
    if (tid < 512) {
        int r = tid >> 4, c4 = (tid & 15) << 2;
        *(float4*)&Qs[r * 68 + c4] =
            *(const float4*)(g_q + hb + (size_t)(n0 + r) * HDV + c4);
    }
    if (tid < 128) crow[tid] = cin[(tid >> 5) * NTOK + n0 + (tid & 31)];
    __syncthreads();

    const int rg = warp & 1;        // 2 row groups of 16
    const int cg = warp >> 1;       // 8 col groups of 16 (score phase)

    uint32_t aq0[8], aq1[8], aq2[8], aq3[8];
    {
        const float* q0 = Qs + (rg * 16 + gid) * 68;
        const float* q1 = Qs + (rg * 16 + gid + 8) * 68;
        #pragma unroll
        for (int k0 = 0; k0 < 8; k0++) {
            aq0[k0] = __float_as_uint(q0[k0 * 8 + tig]);
            aq1[k0] = __float_as_uint(q1[k0 * 8 + tig]);
            aq2[k0] = __float_as_uint(q0[k0 * 8 + tig + 4]);
            aq3[k0] = __float_as_uint(q1[k0 * 8 + tig + 4]);
        }
    }

    float smax0 = -1e30f, smax1 = -1e30f;

    // ---- scores, double-buffered: each warp 16 rows x 16 cols ----
    for (int mt = 0; mt < 8; mt++) {
        if (mt < 7) {
            stage_kv<512>((mt & 1) ? kv0 : kv1, Kp + (mt + 1) * 8192, tid);
            CP_COMMIT();
            CP_WAIT1();
        } else {
            CP_WAIT0();
        }
        __syncthreads();
        const float* KB = sm + ((mt & 1) ? AO_KV1 : AO_KV0);

        float sacc[2][4];
        #pragma unroll
        for (int nt = 0; nt < 2; nt++)
            #pragma unroll
            for (int q = 0; q < 4; q++) sacc[nt][q] = 0.f;
        #pragma unroll
        for (int k0 = 0; k0 < 8; k0++) {
            #pragma unroll
            for (int nt = 0; nt < 2; nt++) {
                const float* p = KB + (cg * 16 + nt * 8 + gid) * 68 + k0 * 8;
                mma_tf32(sacc[nt], aq0[k0], aq1[k0], aq2[k0], aq3[k0],
                         __float_as_uint(p[tig]), __float_as_uint(p[tig + 4]));
            }
        }
        int row0 = rg * 16 + gid;
        #pragma unroll
        for (int nt = 0; nt < 2; nt++) {
            smax0 = fmaxf(smax0, fmaxf(sacc[nt][0], sacc[nt][1]));
            smax1 = fmaxf(smax1, fmaxf(sacc[nt][2], sacc[nt][3]));
            int col = mt * 128 + cg * 16 + nt * 8 + tig * 2;
            *(float2*)&S[row0 * SSTR + col]       = make_float2(sacc[nt][0], sacc[nt][1]);
            *(float2*)&S[(row0 + 8) * SSTR + col] = make_float2(sacc[nt][2], sacc[nt][3]);
        }
        __syncthreads();
    }

    // row-max partials (reduce over tig quad); rmax[row][cg]
    smax0 = fmaxf(smax0, __shfl_xor_sync(0xffffffffu, smax0, 1));
    smax0 = fmaxf(smax0, __shfl_xor_sync(0xffffffffu, smax0, 2));
    smax1 = fmaxf(smax1, __shfl_xor_sync(0xffffffffu, smax1, 1));
    smax1 = fmaxf(smax1, __shfl_xor_sync(0xffffffffu, smax1, 2));
    if (tig == 0) {
        rmax[(rg * 16 + gid) * 8 + cg]     = smax0;
        rmax[(rg * 16 + gid + 8) * 8 + cg] = smax1;
    }

    // prefetch V tile 0 (overlaps softmax)
    stage_kv<512>(kv0, Vp, tid);
    CP_COMMIT();
    __syncthreads();

    // ---- double softmax (warp -> 2 rows) ----
    {
        const float4* cT = (const float4*)g_callT;
        int r0 = warp * 2;
        float cr[2][4];
        #pragma unroll
        for (int rr = 0; rr < 2; rr++)
            #pragma unroll
            for (int ff = 0; ff < 4; ff++) cr[rr][ff] = crow[ff * 32 + r0 + rr];

        float mx[2], s1[2], um[2];
        #pragma unroll
        for (int rr = 0; rr < 2; rr++) {
            float4 m4a = *(float4*)&rmax[(r0 + rr) * 8];
            float4 m4b = *(float4*)&rmax[(r0 + rr) * 8 + 4];
            mx[rr] = fmaxf(fmaxf(fmaxf(m4a.x, m4a.y), fmaxf(m4a.z, m4a.w)),
                           fmaxf(fmaxf(m4b.x, m4b.y), fmaxf(m4b.z, m4b.w)));
            s1[rr] = 0.f; um[rr] = 0.f;
        }

        #pragma unroll 2
        for (int i = 0; i < 8; i++) {
            int c = i * 128 + lane * 4;
            float4 w0 = cT[c], w1 = cT[c + 1], w2 = cT[c + 2], w3 = cT[c + 3];
            #pragma unroll
            for (int rr = 0; rr < 2; rr++) {
                float4 v = *(float4*)&S[(r0 + rr) * SSTR + c];
                float e0 = __expf(v.x - mx[rr]);
                float e1 = __expf(v.y - mx[rr]);
                float e2 = __expf(v.z - mx[rr]);
                float e3 = __expf(v.w - mx[rr]);
                float p0 = cr[rr][0] * w0.x + cr[rr][1] * w0.y + cr[rr][2] * w0.z + cr[rr][3] * w0.w;
                float p1 = cr[rr][0] * w1.x + cr[rr][1] * w1.y + cr[rr][2] * w1.z + cr[rr][3] * w1.w;
                float p2 = cr[rr][0] * w2.x + cr[rr][1] * w2.y + cr[rr][2] * w2.z + cr[rr][3] * w2.w;
                float p3 = cr[rr][0] * w3.x + cr[rr][1] * w3.y + cr[rr][2] * w3.z + cr[rr][3] * w3.w;
                float u0 = e0 * p0, u1 = e1 * p1, u2 = e2 * p2, u3 = e3 * p3;
                s1[rr] += (e0 + e1) + (e2 + e3);
                um[rr] = fmaxf(um[rr], fmaxf(fmaxf(u0, u1), fmaxf(u2, u3)));
                *(float4*)&S[(r0 + rr) * SSTR + c] = make_float4(u0, u1, u2, u3);
            }
        }
        #pragma unroll
        for (int rr = 0; rr < 2; rr++) {
            #pragma unroll
            for (int o = 16; o; o >>= 1) {
                s1[rr] += __shfl_xor_sync(0xffffffffu, s1[rr], o);
                um[rr]  = fmaxf(um[rr], __shfl_xor_sync(0xffffffffu, um[rr], o));
            }
        }
        float inv1[2], m2[2], s2[2];
        #pragma unroll
        for (int rr = 0; rr < 2; rr++) {
            inv1[rr] = 1.f / s1[rr];
            m2[rr] = um[rr] * inv1[rr];
            s2[rr] = 0.f;
        }
        #pragma unroll 2
        for (int i = 0; i < 8; i++) {
            int c = i * 128 + lane * 4;
            #pragma unroll
            for (int rr = 0; rr < 2; rr++) {
                float4 u = *(float4*)&S[(r0 + rr) * SSTR + c];
                float p0 = __expf(u.x * inv1[rr] - m2[rr]);
                float p1 = __expf(u.y * inv1[rr] - m2[rr]);
                float p2 = __expf(u.z * inv1[rr] - m2[rr]);
                float p3 = __expf(u.w * inv1[rr] - m2[rr]);
                s2[rr] += (p0 + p1) + (p2 + p3);
                *(float4*)&S[(r0 + rr) * SSTR + c] =
                    make_float4(to_tf32(p0), to_tf32(p1), to_tf32(p2), to_tf32(p3));
            }
        }
        #pragma unroll
        for (int rr = 0; rr < 2; rr++) {
            #pragma unroll
            for (int o = 16; o; o >>= 1) s2[rr] += __shfl_xor_sync(0xffffffffu, s2[rr], o);
        }
        if (lane == 0) {
            #pragma unroll
            for (int rr = 0; rr < 2; rr++) inv2[r0 + rr] = 1.f / s2[rr];
        }
    }
    __syncthreads();

    // ---- PV, double-buffered: each warp 16 rows x 8 cols ----
    const int cg2 = warp >> 1;       // 8 col groups of 8
    float o[4];
    o[0] = o[1] = o[2] = o[3] = 0.f;

    for (int mt = 0; mt < 8; mt++) {
        if (mt < 7) {
            stage_kv<512>((mt & 1) ? kv0 : kv1, Vp + (mt + 1) * 8192, tid);
            CP_COMMIT();
            CP_WAIT1();
        } else {
            CP_WAIT0();
        }
        __syncthreads();
        const float* VB = sm + ((mt & 1) ? AO_KV1 : AO_KV0);
        const float* Sr0 = S + (rg * 16 + gid) * SSTR + mt * 128;
        const float* Sr1 = Sr0 + 8 * SSTR;
        #pragma unroll
        for (int k0 = 0; k0 < 16; k0++) {
            uint32_t a0 = __float_as_uint(Sr0[k0 * 8 + tig]);
            uint32_t a1 = __float_as_uint(Sr1[k0 * 8 + tig]);
            uint32_t a2 = __float_as_uint(Sr0[k0 * 8 + tig + 4]);
            uint32_t a3 = __float_as_uint(Sr1[k0 * 8 + tig + 4]);
            const float* p = VB + (k0 * 8 + tig) * 68 + cg2 * 8 + gid;
            mma_tf32(o, a0, a1, a2, a3,
                     __float_as_uint(p[0]), __float_as_uint(p[4 * 68]));
        }
        __syncthreads();
    }

    {
        int r0e = rg * 16 + gid;
        float isa = inv2[r0e], isb = inv2[r0e + 8];
        float* yp0 = g_yhat + (size_t)f * NTOK * DINV + (size_t)(n0 + r0e) * DINV + h * HDV;
        float* yp1 = yp0 + 8 * DINV;
        int dc = cg2 * 8 + tig * 2;
        *(float2*)(yp0 + dc) = make_float2(o[0] * isa, o[1] * isa);
        *(float2*)(yp1 + dc) = make_float2(o[2] * isb, o[3] * isb);
    }
}

// ============================================================
extern "C" void kernel_launch(void* const* d_in, const int* in_sizes, int n_in,
                              void* d_out, int out_size)
{
    const float* x      = (const float*)d_in[0];
    const float* compat = (const float*)d_in[1];
    const float* code   = (const float*)d_in[2];
    const float* wc     = (const float*)d_in[3];
    const float* Wqkv   = (const float*)d_in[4];
    const float* bqkv   = (const float*)d_in[5];
    const float* Wproj  = (const float*)d_in[6];
    const float* bproj  = (const float*)d_in[7];
    const float* lnqg   = (const float*)d_in[8];
    const float* lnqb   = (const float*)d_in[9];
    const float* lnpg   = (const float*)d_in[10];
    const float* lnpb   = (const float*)d_in[11];
    float* out = (float*)d_out;

    cudaFuncSetAttribute(attn_kernel,
                         cudaFuncAttributeMaxDynamicSharedMemorySize, ATTN_SMEM_FLOATS * 4);
    cudaFuncSetAttribute(gemm_qkv,
                         cudaFuncAttributeMaxDynamicSharedMemorySize, GEMM_SMEM_FLOATS * 4);
    cudaFuncSetAttribute(gemm_proj,
                         cudaFuncAttributeMaxDynamicSharedMemorySize, H64_FLOATS * 4);

    code_mod_kernel<<<1, 512>>>(wc, code, lnqg, lnqb, lnpg, lnpb);
    prep_callT<<<4, 256>>>(compat);
    gemm_qkv<<<dim3(12, 8, 4), 256, GEMM_SMEM_FLOATS * 4>>>(x, Wqkv, bqkv);
    attn_kernel<<<dim3(32, 32), 512, ATTN_SMEM_FLOATS * 4>>>(compat);
    gemm_proj<<<dim3(4, 16, 4), 256, H64_FLOATS * 4>>>(Wproj, bproj, out);
}

// round 6
// speedup vs baseline: 1.3967x; 1.3967x over previous
#include <cuda_runtime.h>
#include <cuda_fp16.h>
#include <math.h>
#include <stdint.h>

#define NTOK 1024
#define DINV 512
#define NFV  4
#define NHV  8
#define HDV  64

// -------- scratch (device globals; no allocation allowed) --------
__device__ float  g_cm[2][NFV][DINV];                // [qkv|proj][f][d]
__device__ __half g_qh[NHV * NFV * NTOK * HDV];      // [hf][n][d], pre-scaled hd^-0.5
__device__ __half g_kh[NHV * NFV * NTOK * HDV];      // [hf][n][d]
__device__ __half g_vT[NHV * NFV * HDV * NTOK];      // [hf][d][n] transposed
__device__ float  g_yhat[NFV * NTOK * DINV];         // [f][n][h*64+d]
__device__ float  g_callT[NTOK * NFV];               // [c][f] transposed compat

// ============================================================
// helpers
// ============================================================
__device__ __forceinline__ float to_tf32(float x) {
    uint32_t u;
    asm("cvt.rna.tf32.f32 %0, %1;" : "=r"(u) : "f"(x));
    return __uint_as_float(u);
}

__device__ __forceinline__ void mma_tf32(float* d, uint32_t a0, uint32_t a1,
                                         uint32_t a2, uint32_t a3,
                                         uint32_t b0, uint32_t b1) {
    asm volatile(
        "mma.sync.aligned.m16n8k8.row.col.f32.tf32.tf32.f32 "
        "{%0,%1,%2,%3}, {%4,%5,%6,%7}, {%8,%9}, {%0,%1,%2,%3};"
        : "+f"(d[0]), "+f"(d[1]), "+f"(d[2]), "+f"(d[3])
        : "r"(a0), "r"(a1), "r"(a2), "r"(a3), "r"(b0), "r"(b1));
}

__device__ __forceinline__ void mma_f16(float* d, uint32_t a0, uint32_t a1,
                                        uint32_t a2, uint32_t a3,
                                        uint32_t b0, uint32_t b1) {
    asm volatile(
        "mma.sync.aligned.m16n8k16.row.col.f32.f16.f16.f32 "
        "{%0,%1,%2,%3}, {%4,%5,%6,%7}, {%8,%9}, {%0,%1,%2,%3};"
        : "+f"(d[0]), "+f"(d[1]), "+f"(d[2]), "+f"(d[3])
        : "r"(a0), "r"(a1), "r"(a2), "r"(a3), "r"(b0), "r"(b1));
}

__device__ __forceinline__ uint32_t smem_u32(const void* p) {
    uint32_t a;
    asm("{ .reg .u64 t; cvta.to.shared.u64 t, %1; cvt.u32.u64 %0, t; }" : "=r"(a) : "l"(p));
    return a;
}

__device__ __forceinline__ void cp_async16(uint32_t dst, const void* src) {
    asm volatile("cp.async.cg.shared.global [%0], [%1], 16;" :: "r"(dst), "l"(src) : "memory");
}
#define CP_COMMIT() asm volatile("cp.async.commit_group;" ::: "memory")
#define CP_WAIT0()  asm volatile("cp.async.wait_group 0;" ::: "memory")
#define CP_WAIT1()  asm volatile("cp.async.wait_group 1;" ::: "memory")

// stage K tile: 128 keys x 64 half dims, smem row stride 72 halves
__device__ __forceinline__ void stage_k(uint32_t dstbase, const __half* src, int tid) {
    #pragma unroll
    for (int i = tid; i < 1024; i += 256) {
        int r = i >> 3, c8 = (i & 7) << 3;
        cp_async16(dstbase + (uint32_t)(r * 144 + c8 * 2), src + r * 64 + c8);
    }
}
// stage V tile (transposed): 64 dim-rows x 128 half keys, smem row stride 136 halves
__device__ __forceinline__ void stage_v(uint32_t dstbase, const __half* srcT, int tid) {
    #pragma unroll
    for (int i = tid; i < 1024; i += 256) {
        int r = i >> 4, c16 = (i & 15) << 3;
        cp_async16(dstbase + (uint32_t)(r * 272 + c16 * 2), srcT + (size_t)r * NTOK + c16);
    }
}

// ============================================================
// K1: code_mod = LayerNorm((w_c @ code).T) * g + b, both variants
// ============================================================
__global__ __launch_bounds__(512) void code_mod_kernel(
    const float* __restrict__ wc, const float* __restrict__ code,
    const float* __restrict__ gq, const float* __restrict__ bq,
    const float* __restrict__ gp, const float* __restrict__ bp)
{
    int d = threadIdx.x;
    float t[NFV] = {0.f, 0.f, 0.f, 0.f};
    for (int k = 0; k < 128; k++) {
        float w = wc[d * 128 + k];
        #pragma unroll
        for (int f = 0; f < NFV; f++) t[f] += w * code[k * NFV + f];
    }
    __shared__ float red[512];
    float gqd = gq[d], bqd = bq[d], gpd = gp[d], bpd = bp[d];
    for (int f = 0; f < NFV; f++) {
        red[d] = t[f];
        __syncthreads();
        for (int s = 256; s > 0; s >>= 1) {
            if (d < s) red[d] += red[d + s];
            __syncthreads();
        }
        float mu = red[0] * (1.f / 512.f);
        __syncthreads();
        float dv = t[f] - mu;
        red[d] = dv * dv;
        __syncthreads();
        for (int s = 256; s > 0; s >>= 1) {
            if (d < s) red[d] += red[d + s];
            __syncthreads();
        }
        float var = red[0] * (1.f / 512.f);
        __syncthreads();
        float nrm = dv * rsqrtf(var + 1e-5f);
        g_cm[0][f][d] = nrm * gqd + bqd;
        g_cm[1][f][d] = nrm * gpd + bpd;
    }
}

__global__ __launch_bounds__(256) void prep_callT(const float* __restrict__ cin) {
    int c = blockIdx.x * 256 + threadIdx.x;
    float4 v = make_float4(cin[c], cin[NTOK + c], cin[2 * NTOK + c], cin[3 * NTOK + c]);
    *(float4*)&g_callT[c * 4] = v;
}

// ============================================================
// QKV GEMM (128x128 tile, BK=32, tf32 mma) -> half q/k, transposed half v
// ============================================================
#define GA0   0
#define GA1   4608
#define GB0   9216
#define GB1   13824
#define GSC   18432
#define GBIAS 18944
#define GEMM_SMEM_FLOATS 19072

__global__ __launch_bounds__(256) void gemm_qkv(
    const float* __restrict__ Ain, const float* __restrict__ Bw,
    const float* __restrict__ bias)
{
    extern __shared__ float sm[];
    const int f   = blockIdx.z;
    const int bm0 = blockIdx.y * 128;
    const int bn0 = blockIdx.x * 128;
    const int tid = threadIdx.x;
    const int warp = tid >> 5, lane = tid & 31;
    const int gid = lane >> 2, tig = lane & 3;
    const int wm = warp >> 2, wn = warp & 3;
    const float* A = Ain;

    sm[GSC + tid]       = g_cm[0][f][tid];
    sm[GSC + tid + 256] = g_cm[0][f][tid + 256];
    if (tid < 128) sm[GBIAS + tid] = bias[bn0 + tid];

    const int rb = tid >> 3;
    const int k4 = (tid & 7) * 4;

    float4 ra[4], rbv[4];
    #pragma unroll
    for (int it = 0; it < 4; it++) {
        ra[it]  = *(const float4*)(A  + (size_t)(bm0 + rb + 32 * it) * 512 + k4);
        rbv[it] = *(const float4*)(Bw + (size_t)(bn0 + rb + 32 * it) * 512 + k4);
    }
    __syncthreads();
    {
        float s0 = sm[GSC + k4], s1 = sm[GSC + k4 + 1],
              s2 = sm[GSC + k4 + 2], s3 = sm[GSC + k4 + 3];
        #pragma unroll
        for (int it = 0; it < 4; it++) {
            int row = rb + 32 * it;
            float* pa = sm + GA0 + row * 36 + k4;
            pa[0] = to_tf32(ra[it].x * s0); pa[1] = to_tf32(ra[it].y * s1);
            pa[2] = to_tf32(ra[it].z * s2); pa[3] = to_tf32(ra[it].w * s3);
            float* pb = sm + GB0 + row * 36 + k4;
            pb[0] = to_tf32(rbv[it].x); pb[1] = to_tf32(rbv[it].y);
            pb[2] = to_tf32(rbv[it].z); pb[3] = to_tf32(rbv[it].w);
        }
    }
    __syncthreads();

    float d[4][4][4];
    #pragma unroll
    for (int mt = 0; mt < 4; mt++)
        #pragma unroll
        for (int nt = 0; nt < 4; nt++)
            #pragma unroll
            for (int q = 0; q < 4; q++) d[mt][nt][q] = 0.f;

    for (int c = 0; c < 16; c++) {
        int cb = c & 1;
        if (c < 15) {
            int k0 = (c + 1) * 32;
            #pragma unroll
            for (int it = 0; it < 4; it++) {
                ra[it]  = *(const float4*)(A  + (size_t)(bm0 + rb + 32 * it) * 512 + k0 + k4);
                rbv[it] = *(const float4*)(Bw + (size_t)(bn0 + rb + 32 * it) * 512 + k0 + k4);
            }
        }
        const float* Ab = sm + (cb ? GA1 : GA0);
        const float* Bb = sm + (cb ? GB1 : GB0);
        #pragma unroll
        for (int kk = 0; kk < 4; kk++) {
            uint32_t aa[4][4], bb[4][2];
            #pragma unroll
            for (int mt = 0; mt < 4; mt++) {
                const float* p = Ab + (wm * 64 + mt * 16) * 36 + kk * 8;
                aa[mt][0] = __float_as_uint(p[gid * 36 + tig]);
                aa[mt][1] = __float_as_uint(p[(gid + 8) * 36 + tig]);
                aa[mt][2] = __float_as_uint(p[gid * 36 + tig + 4]);
                aa[mt][3] = __float_as_uint(p[(gid + 8) * 36 + tig + 4]);
            }
            #pragma unroll
            for (int nt = 0; nt < 4; nt++) {
                const float* p = Bb + (wn * 32 + nt * 8 + gid) * 36 + kk * 8;
                bb[nt][0] = __float_as_uint(p[tig]);
                bb[nt][1] = __float_as_uint(p[tig + 4]);
            }
            #pragma unroll
            for (int mt = 0; mt < 4; mt++)
                #pragma unroll
                for (int nt = 0; nt < 4; nt++)
                    mma_tf32(d[mt][nt], aa[mt][0], aa[mt][1], aa[mt][2], aa[mt][3],
                             bb[nt][0], bb[nt][1]);
        }
        __syncthreads();
        if (c < 15) {
            int k0 = (c + 1) * 32;
            float s0 = sm[GSC + k0 + k4], s1 = sm[GSC + k0 + k4 + 1],
                  s2 = sm[GSC + k0 + k4 + 2], s3 = sm[GSC + k0 + k4 + 3];
            float* Ad = sm + ((cb ^ 1) ? GA1 : GA0);
            float* Bd = sm + ((cb ^ 1) ? GB1 : GB0);
            #pragma unroll
            for (int it = 0; it < 4; it++) {
                int row = rb + 32 * it;
                float* pa = Ad + row * 36 + k4;
                pa[0] = to_tf32(ra[it].x * s0); pa[1] = to_tf32(ra[it].y * s1);
                pa[2] = to_tf32(ra[it].z * s2); pa[3] = to_tf32(ra[it].w * s3);
                float* pb = Bd + row * 36 + k4;
                pb[0] = to_tf32(rbv[it].x); pb[1] = to_tf32(rbv[it].y);
                pb[2] = to_tf32(rbv[it].z); pb[3] = to_tf32(rbv[it].w);
            }
            __syncthreads();
        }
    }

    // epilogue: half q/k ([n][d]); half v transposed ([d][n])
    const int jb = bn0 + wn * 32;
    int tt = jb >> 9;
    int h  = (jb >> 6) & 7;
    int db = jb & 63;
    if (tt < 2) {
        float mul = (tt == 0) ? 0.125f : 1.0f;
        __half* base = (tt == 0 ? g_qh : g_kh) + (size_t)((h * NFV + f) * NTOK) * HDV;
        #pragma unroll
        for (int mt = 0; mt < 4; mt++) {
            int m0 = bm0 + wm * 64 + mt * 16 + gid;
            #pragma unroll
            for (int nt = 0; nt < 4; nt++) {
                int dc = db + nt * 8 + tig * 2;
                float b0 = sm[GBIAS + wn * 32 + nt * 8 + tig * 2];
                float b1 = sm[GBIAS + wn * 32 + nt * 8 + tig * 2 + 1];
                __half2 h0 = __floats2half2_rn((d[mt][nt][0] + b0) * mul,
                                               (d[mt][nt][1] + b1) * mul);
                __half2 h1 = __floats2half2_rn((d[mt][nt][2] + b0) * mul,
                                               (d[mt][nt][3] + b1) * mul);
                *(__half2*)(base + (size_t)m0 * HDV + dc)       = h0;
                *(__half2*)(base + (size_t)(m0 + 8) * HDV + dc) = h1;
            }
        }
    } else {
        __half* baseT = g_vT + (size_t)(h * NFV + f) * HDV * NTOK;
        #pragma unroll
        for (int mt = 0; mt < 4; mt++) {
            int m0 = bm0 + wm * 64 + mt * 16 + gid;
            #pragma unroll
            for (int nt = 0; nt < 4; nt++) {
                int dc = db + nt * 8 + tig * 2;
                float b0 = sm[GBIAS + wn * 32 + nt * 8 + tig * 2];
                float b1 = sm[GBIAS + wn * 32 + nt * 8 + tig * 2 + 1];
                baseT[(size_t)dc * NTOK + m0]           = __float2half_rn(d[mt][nt][0] + b0);
                baseT[(size_t)(dc + 1) * NTOK + m0]     = __float2half_rn(d[mt][nt][1] + b1);
                baseT[(size_t)dc * NTOK + m0 + 8]       = __float2half_rn(d[mt][nt][2] + b0);
                baseT[(size_t)(dc + 1) * NTOK + m0 + 8] = __float2half_rn(d[mt][nt][3] + b1);
            }
        }
    }
}

// ============================================================
// proj GEMM: 64x128 tile, 2 blocks/SM
// ============================================================
#define H64_A0   0
#define H64_A1   2304
#define H64_B0   4608
#define H64_B1   9216
#define H64_SC   13824
#define H64_BIAS 14336
#define H64_FLOATS 14464

__global__ __launch_bounds__(256, 2) void gemm_proj(
    const float* __restrict__ Bw, const float* __restrict__ bias,
    float* __restrict__ Out)
{
    extern __shared__ float sm[];
    const int f   = blockIdx.z;
    const int bm0 = blockIdx.y * 64;
    const int bn0 = blockIdx.x * 128;
    const int tid = threadIdx.x;
    const int warp = tid >> 5, lane = tid & 31;
    const int gid = lane >> 2, tig = lane & 3;
    const int wm = warp >> 2, wn = warp & 3;
    const float* A = g_yhat + (size_t)f * NTOK * DINV;

    sm[H64_SC + tid]       = g_cm[1][f][tid];
    sm[H64_SC + tid + 256] = g_cm[1][f][tid + 256];
    if (tid < 128) sm[H64_BIAS + tid] = bias[bn0 + tid];

    const int rb = tid >> 3;
    const int k4 = (tid & 7) * 4;

    float4 ra[2], rbv[4];
    #pragma unroll
    for (int it = 0; it < 2; it++)
        ra[it] = *(const float4*)(A + (size_t)(bm0 + rb + 32 * it) * 512 + k4);
    #pragma unroll
    for (int it = 0; it < 4; it++)
        rbv[it] = *(const float4*)(Bw + (size_t)(bn0 + rb + 32 * it) * 512 + k4);
    __syncthreads();
    {
        float s0 = sm[H64_SC + k4], s1 = sm[H64_SC + k4 + 1],
              s2 = sm[H64_SC + k4 + 2], s3 = sm[H64_SC + k4 + 3];
        #pragma unroll
        for (int it = 0; it < 2; it++) {
            float* pa = sm + H64_A0 + (rb + 32 * it) * 36 + k4;
            pa[0] = to_tf32(ra[it].x * s0); pa[1] = to_tf32(ra[it].y * s1);
            pa[2] = to_tf32(ra[it].z * s2); pa[3] = to_tf32(ra[it].w * s3);
        }
        #pragma unroll
        for (int it = 0; it < 4; it++) {
            float* pb = sm + H64_B0 + (rb + 32 * it) * 36 + k4;
            pb[0] = to_tf32(rbv[it].x); pb[1] = to_tf32(rbv[it].y);
            pb[2] = to_tf32(rbv[it].z); pb[3] = to_tf32(rbv[it].w);
        }
    }
    __syncthreads();

    float d[2][4][4];
    #pragma unroll
    for (int mt = 0; mt < 2; mt++)
        #pragma unroll
        for (int nt = 0; nt < 4; nt++)
            #pragma unroll
            for (int q = 0; q < 4; q++) d[mt][nt][q] = 0.f;

    for (int c = 0; c < 16; c++) {
        int cb = c & 1;
        if (c < 15) {
            int k0 = (c + 1) * 32;
            #pragma unroll
            for (int it = 0; it < 2; it++)
                ra[it] = *(const float4*)(A + (size_t)(bm0 + rb + 32 * it) * 512 + k0 + k4);
            #pragma unroll
            for (int it = 0; it < 4; it++)
                rbv[it] = *(const float4*)(Bw + (size_t)(bn0 + rb + 32 * it) * 512 + k0 + k4);
        }
        const float* Ab = sm + (cb ? H64_A1 : H64_A0);
        const float* Bb = sm + (cb ? H64_B1 : H64_B0);
        #pragma unroll
        for (int kk = 0; kk < 4; kk++) {
            uint32_t aa[2][4], bb[4][2];
            #pragma unroll
            for (int mt = 0; mt < 2; mt++) {
                const float* p = Ab + (wm * 32 + mt * 16) * 36 + kk * 8;
                aa[mt][0] = __float_as_uint(p[gid * 36 + tig]);
                aa[mt][1] = __float_as_uint(p[(gid + 8) * 36 + tig]);
                aa[mt][2] = __float_as_uint(p[gid * 36 + tig + 4]);
                aa[mt][3] = __float_as_uint(p[(gid + 8) * 36 + tig + 4]);
            }
            #pragma unroll
            for (int nt = 0; nt < 4; nt++) {
                const float* p = Bb + (wn * 32 + nt * 8 + gid) * 36 + kk * 8;
                bb[nt][0] = __float_as_uint(p[tig]);
                bb[nt][1] = __float_as_uint(p[tig + 4]);
            }
            #pragma unroll
            for (int mt = 0; mt < 2; mt++)
                #pragma unroll
                for (int nt = 0; nt < 4; nt++)
                    mma_tf32(d[mt][nt], aa[mt][0], aa[mt][1], aa[mt][2], aa[mt][3],
                             bb[nt][0], bb[nt][1]);
        }
        __syncthreads();
        if (c < 15) {
            int k0 = (c + 1) * 32;
            float s0 = sm[H64_SC + k0 + k4], s1 = sm[H64_SC + k0 + k4 + 1],
                  s2 = sm[H64_SC + k0 + k4 + 2], s3 = sm[H64_SC + k0 + k4 + 3];
            float* Ad = sm + ((cb ^ 1) ? H64_A1 : H64_A0);
            float* Bd = sm + ((cb ^ 1) ? H64_B1 : H64_B0);
            #pragma unroll
            for (int it = 0; it < 2; it++) {
                float* pa = Ad + (rb + 32 * it) * 36 + k4;
                pa[0] = to_tf32(ra[it].x * s0); pa[1] = to_tf32(ra[it].y * s1);
                pa[2] = to_tf32(ra[it].z * s2); pa[3] = to_tf32(ra[it].w * s3);
            }
            #pragma unroll
            for (int it = 0; it < 4; it++) {
                float* pb = Bd + (rb + 32 * it) * 36 + k4;
                pb[0] = to_tf32(rbv[it].x); pb[1] = to_tf32(rbv[it].y);
                pb[2] = to_tf32(rbv[it].z); pb[3] = to_tf32(rbv[it].w);
            }
            __syncthreads();
        }
    }

    float* outp = Out + (size_t)f * NTOK * DINV;
    #pragma unroll
    for (int mt = 0; mt < 2; mt++) {
        int m0 = bm0 + wm * 32 + mt * 16 + gid;
        #pragma unroll
        for (int nt = 0; nt < 4; nt++) {
            int j = bn0 + wn * 32 + nt * 8 + tig * 2;
            float b0 = sm[H64_BIAS + wn * 32 + nt * 8 + tig * 2];
            float b1 = sm[H64_BIAS + wn * 32 + nt * 8 + tig * 2 + 1];
            float2 v0 = {d[mt][nt][0] + b0, d[mt][nt][1] + b1};
            float2 v1 = {d[mt][nt][2] + b0, d[mt][nt][3] + b1};
            *(float2*)(outp + (size_t)m0 * 512 + j)       = v0;
            *(float2*)(outp + (size_t)(m0 + 8) * 512 + j) = v1;
        }
    }
}

// ============================================================
// attention fp16: 256 threads, m16n8k16, cp.async double-buffered K/V,
// P stored as half aliasing the fp32 S panel.
// float offsets: S 0 (32x1036) | QS 33152 (half @66304) | KV0 34304 (half)
//                KV1 38912 | CROW 43520 | RMAX 43648 | INV2 43776 | tot 43808
// ============================================================
#define SSTR     1036
#define SSTRH    2072
#define FO_QS    33152
#define FO_KV0   34304
#define FO_KV1   38912
#define FO_CROW  43520
#define FO_RMAX  43648
#define FO_INV2  43776
#define ATTN_SMEM_FLOATS 43808

__global__ __launch_bounds__(256) void attn_kernel(const float* __restrict__ cin)
{
    extern __shared__ float sm[];
    float*  S    = sm;
    __half* Sh   = (__half*)sm;
    __half* Qs   = (__half*)(sm + FO_QS);
    float*  crow = sm + FO_CROW;
    float*  rmax = sm + FO_RMAX;
    float*  inv2 = sm + FO_INV2;

    const int tid = threadIdx.x;
    const int warp = tid >> 5, lane = tid & 31;
    const int gid = lane >> 2, tig = lane & 3;
    const int n0  = blockIdx.x * 32;
    const int hf  = blockIdx.y;
    const int h   = hf >> 2, f = hf & 3;
    const size_t hb  = (size_t)hf * NTOK * HDV;

    uint32_t sb  = smem_u32(sm);
    uint32_t kv0 = sb + FO_KV0 * 4;
    uint32_t kv1 = sb + FO_KV1 * 4;
    const __half* Kp  = g_kh + hb;
    const __half* VTp = g_vT + (size_t)hf * HDV * NTOK;

    // prefetch K tile 0
    stage_k(kv0, Kp, tid);
    CP_COMMIT();

    // Q block: 32 rows x 64 halves -> stride 72
    {
        int r = tid >> 3, c8 = (tid & 7) << 3;
        uint4 v = *(const uint4*)(g_qh + hb + (size_t)(n0 + r) * HDV + c8);
        *(uint4*)((char*)Qs + r * 144 + c8 * 2) = v;
    }
    if (tid < 128) crow[tid] = cin[(tid >> 5) * NTOK + n0 + (tid & 31)];
    __syncthreads();

    const int rg = warp & 1;        // 2 row groups of 16
    const int cg = warp >> 1;       // 4 col groups of 32 (score phase)

    // preload Q fragments: kk = 0..3 (k16 steps)
    uint32_t aq0[4], aq1[4], aq2[4], aq3[4];
    {
        const __half* q0 = Qs + (rg * 16 + gid) * 72;
        const __half* q1 = q0 + 8 * 72;
        #pragma unroll
        for (int kk = 0; kk < 4; kk++) {
            aq0[kk] = *(const uint32_t*)&q0[kk * 16 + tig * 2];
            aq1[kk] = *(const uint32_t*)&q1[kk * 16 + tig * 2];
            aq2[kk] = *(const uint32_t*)&q0[kk * 16 + tig * 2 + 8];
            aq3[kk] = *(const uint32_t*)&q1[kk * 16 + tig * 2 + 8];
        }
    }

    float smax0 = -1e30f, smax1 = -1e30f;

    // ---- scores, double-buffered: warp = 16 rows x 32 cols ----
    for (int mt = 0; mt < 8; mt++) {
        if (mt < 7) {
            stage_k((mt & 1) ? kv0 : kv1, Kp + (size_t)(mt + 1) * 128 * HDV, tid);
            CP_COMMIT();
            CP_WAIT1();
        } else {
            CP_WAIT0();
        }
        __syncthreads();
        const __half* KB = (const __half*)(sm + ((mt & 1) ? FO_KV1 : FO_KV0));

        float sacc[4][4];
        #pragma unroll
        for (int nt = 0; nt < 4; nt++)
            #pragma unroll
            for (int q = 0; q < 4; q++) sacc[nt][q] = 0.f;
        #pragma unroll
        for (int kk = 0; kk < 4; kk++) {
            #pragma unroll
            for (int nt = 0; nt < 4; nt++) {
                const __half* p = KB + (cg * 32 + nt * 8 + gid) * 72 + kk * 16 + tig * 2;
                mma_f16(sacc[nt], aq0[kk], aq1[kk], aq2[kk], aq3[kk],
                        *(const uint32_t*)p, *(const uint32_t*)(p + 8));
            }
        }
        int row0 = rg * 16 + gid;
        #pragma unroll
        for (int nt = 0; nt < 4; nt++) {
            smax0 = fmaxf(smax0, fmaxf(sacc[nt][0], sacc[nt][1]));
            smax1 = fmaxf(smax1, fmaxf(sacc[nt][2], sacc[nt][3]));
            int col = mt * 128 + cg * 32 + nt * 8 + tig * 2;
            *(float2*)&S[row0 * SSTR + col]       = make_float2(sacc[nt][0], sacc[nt][1]);
            *(float2*)&S[(row0 + 8) * SSTR + col] = make_float2(sacc[nt][2], sacc[nt][3]);
        }
        __syncthreads();
    }

    // row-max partials
    smax0 = fmaxf(smax0, __shfl_xor_sync(0xffffffffu, smax0, 1));
    smax0 = fmaxf(smax0, __shfl_xor_sync(0xffffffffu, smax0, 2));
    smax1 = fmaxf(smax1, __shfl_xor_sync(0xffffffffu, smax1, 1));
    smax1 = fmaxf(smax1, __shfl_xor_sync(0xffffffffu, smax1, 2));
    if (tig == 0) {
        rmax[(rg * 16 + gid) * 4 + cg]     = smax0;
        rmax[(rg * 16 + gid + 8) * 4 + cg] = smax1;
    }

    // prefetch V tile 0 (overlaps softmax)
    stage_v(kv0, VTp, tid);
    CP_COMMIT();
    __syncthreads();

    // ---- double softmax (warp -> 4 rows); pass2 writes half P in-place ----
    {
        const float4* cT = (const float4*)g_callT;
        int r0 = warp * 4;
        float cr[4][4];
        #pragma unroll
        for (int rr = 0; rr < 4; rr++)
            #pragma unroll
            for (int ff = 0; ff < 4; ff++) cr[rr][ff] = crow[ff * 32 + r0 + rr];

        float mx[4], s1[4], um[4];
        #pragma unroll
        for (int rr = 0; rr < 4; rr++) {
            float4 m4 = *(float4*)&rmax[(r0 + rr) * 4];
            mx[rr] = fmaxf(fmaxf(m4.x, m4.y), fmaxf(m4.z, m4.w));
            s1[rr] = 0.f; um[rr] = 0.f;
        }

        #pragma unroll 2
        for (int i = 0; i < 8; i++) {
            int c = i * 128 + lane * 4;
            float4 w0 = cT[c], w1 = cT[c + 1], w2 = cT[c + 2], w3 = cT[c + 3];
            #pragma unroll
            for (int rr = 0; rr < 4; rr++) {
                float4 v = *(float4*)&S[(r0 + rr) * SSTR + c];
                float e0 = __expf(v.x - mx[rr]);
                float e1 = __expf(v.y - mx[rr]);
                float e2 = __expf(v.z - mx[rr]);
                float e3 = __expf(v.w - mx[rr]);
                float p0 = cr[rr][0] * w0.x + cr[rr][1] * w0.y + cr[rr][2] * w0.z + cr[rr][3] * w0.w;
                float p1 = cr[rr][0] * w1.x + cr[rr][1] * w1.y + cr[rr][2] * w1.z + cr[rr][3] * w1.w;
                float p2 = cr[rr][0] * w2.x + cr[rr][1] * w2.y + cr[rr][2] * w2.z + cr[rr][3] * w2.w;
                float p3 = cr[rr][0] * w3.x + cr[rr][1] * w3.y + cr[rr][2] * w3.z + cr[rr][3] * w3.w;
                float u0 = e0 * p0, u1 = e1 * p1, u2 = e2 * p2, u3 = e3 * p3;
                s1[rr] += (e0 + e1) + (e2 + e3);
                um[rr] = fmaxf(um[rr], fmaxf(fmaxf(u0, u1), fmaxf(u2, u3)));
                *(float4*)&S[(r0 + rr) * SSTR + c] = make_float4(u0, u1, u2, u3);
            }
        }
        #pragma unroll
        for (int rr = 0; rr < 4; rr++) {
            #pragma unroll
            for (int o = 16; o; o >>= 1) {
                s1[rr] += __shfl_xor_sync(0xffffffffu, s1[rr], o);
                um[rr]  = fmaxf(um[rr], __shfl_xor_sync(0xffffffffu, um[rr], o));
            }
        }
        float inv1[4], m2[4], s2[4];
        #pragma unroll
        for (int rr = 0; rr < 4; rr++) {
            inv1[rr] = 1.f / s1[rr];
            m2[rr] = um[rr] * inv1[rr];
            s2[rr] = 0.f;
        }
        // pass 2: read fp32 u, write half P in place (2c < 4c, alias-safe)
        #pragma unroll 2
        for (int i = 0; i < 8; i++) {
            int c = i * 128 + lane * 4;
            #pragma unroll
            for (int rr = 0; rr < 4; rr++) {
                float4 u = *(float4*)&S[(r0 + rr) * SSTR + c];
                float p0 = __expf(u.x * inv1[rr] - m2[rr]);
                float p1 = __expf(u.y * inv1[rr] - m2[rr]);
                float p2 = __expf(u.z * inv1[rr] - m2[rr]);
                float p3 = __expf(u.w * inv1[rr] - m2[rr]);
                s2[rr] += (p0 + p1) + (p2 + p3);
                __half2 hA = __floats2half2_rn(p0, p1);
                __half2 hB = __floats2half2_rn(p2, p3);
                *(__half2*)&Sh[(r0 + rr) * SSTRH + c]     = hA;
                *(__half2*)&Sh[(r0 + rr) * SSTRH + c + 2] = hB;
            }
        }
        #pragma unroll
        for (int rr = 0; rr < 4; rr++) {
            #pragma unroll
            for (int o = 16; o; o >>= 1) s2[rr] += __shfl_xor_sync(0xffffffffu, s2[rr], o);
        }
        if (lane == 0) {
            #pragma unroll
            for (int rr = 0; rr < 4; rr++) inv2[r0 + rr] = 1.f / s2[rr];
        }
    }
    __syncthreads();

    // ---- PV, double-buffered: warp = 16 rows x 16 dims ----
    const int cg2 = warp >> 1;
    float o[2][4];
    #pragma unroll
    for (int nt = 0; nt < 2; nt++)
        #pragma unroll
        for (int q = 0; q < 4; q++) o[nt][q] = 0.f;

    for (int mt = 0; mt < 8; mt++) {
        if (mt < 7) {
            stage_v((mt & 1) ? kv0 : kv1, VTp + (mt + 1) * 128, tid);
            CP_COMMIT();
            CP_WAIT1();
        } else {
            CP_WAIT0();
        }
        __syncthreads();
        const __half* VB  = (const __half*)(sm + ((mt & 1) ? FO_KV1 : FO_KV0));
        const __half* Sr0 = Sh + (rg * 16 + gid) * SSTRH + mt * 128;
        const __half* Sr1 = Sr0 + 8 * SSTRH;
        #pragma unroll
        for (int k0 = 0; k0 < 8; k0++) {
            uint32_t a0 = *(const uint32_t*)&Sr0[k0 * 16 + tig * 2];
            uint32_t a1 = *(const uint32_t*)&Sr1[k0 * 16 + tig * 2];
            uint32_t a2 = *(const uint32_t*)&Sr0[k0 * 16 + tig * 2 + 8];
            uint32_t a3 = *(const uint32_t*)&Sr1[k0 * 16 + tig * 2 + 8];
            #pragma unroll
            for (int nt = 0; nt < 2; nt++) {
                const __half* p = VB + (cg2 * 16 + nt * 8 + gid) * 136 + k0 * 16 + tig * 2;
                mma_f16(o[nt], a0, a1, a2, a3,
                        *(const uint32_t*)p, *(const uint32_t*)(p + 8));
            }
        }
        __syncthreads();
    }

    {
        int r0e = rg * 16 + gid;
        float isa = inv2[r0e], isb = inv2[r0e + 8];
        float* yp0 = g_yhat + (size_t)f * NTOK * DINV + (size_t)(n0 + r0e) * DINV + h * HDV;
        float* yp1 = yp0 + 8 * DINV;
        #pragma unroll
        for (int nt = 0; nt < 2; nt++) {
            int dc = cg2 * 16 + nt * 8 + tig * 2;
            *(float2*)(yp0 + dc) = make_float2(o[nt][0] * isa, o[nt][1] * isa);
            *(float2*)(yp1 + dc) = make_float2(o[nt][2] * isb, o[nt][3] * isb);
        }
    }
}

// ============================================================
extern "C" void kernel_launch(void* const* d_in, const int* in_sizes, int n_in,
                              void* d_out, int out_size)
{
    const float* x      = (const float*)d_in[0];
    const float* compat = (const float*)d_in[1];
    const float* code   = (const float*)d_in[2];
    const float* wc     = (const float*)d_in[3];
    const float* Wqkv   = (const float*)d_in[4];
    const float* bqkv   = (const float*)d_in[5];
    const float* Wproj  = (const float*)d_in[6];
    const float* bproj  = (const float*)d_in[7];
    const float* lnqg   = (const float*)d_in[8];
    const float* lnqb   = (const float*)d_in[9];
    const float* lnpg   = (const float*)d_in[10];
    const float* lnpb   = (const float*)d_in[11];
    float* out = (float*)d_out;

    cudaFuncSetAttribute(attn_kernel,
                         cudaFuncAttributeMaxDynamicSharedMemorySize, ATTN_SMEM_FLOATS * 4);
    cudaFuncSetAttribute(gemm_qkv,
                         cudaFuncAttributeMaxDynamicSharedMemorySize, GEMM_SMEM_FLOATS * 4);
    cudaFuncSetAttribute(gemm_proj,
                         cudaFuncAttributeMaxDynamicSharedMemorySize, H64_FLOATS * 4);

    code_mod_kernel<<<1, 512>>>(wc, code, lnqg, lnqb, lnpg, lnpb);
    prep_callT<<<4, 256>>>(compat);
    gemm_qkv<<<dim3(12, 8, 4), 256, GEMM_SMEM_FLOATS * 4>>>(x, Wqkv, bqkv);
    attn_kernel<<<dim3(32, 32), 256, ATTN_SMEM_FLOATS * 4>>>(compat);
    gemm_proj<<<dim3(4, 16, 4), 256, H64_FLOATS * 4>>>(Wproj, bproj, out);
}

// round 7
// speedup vs baseline: 1.6060x; 1.1499x over previous
#include <cuda_runtime.h>
#include <cuda_fp16.h>
#include <math.h>
#include <stdint.h>

#define NTOK 1024
#define DINV 512
#define NFV  4
#define NHV  8
#define HDV  64

// -------- scratch (device globals; no allocation allowed) --------
__device__ float  g_cm[2][NFV][DINV];                // [qkv|proj][f][d]
__device__ __half g_xh[NFV * NTOK * DINV];           // x * cm0, fp16
__device__ __half g_wq_h[3 * DINV * DINV];           // W_qkv fp16
__device__ __half g_wp_h[DINV * DINV];               // W_proj fp16
__device__ __half g_qh[NHV * NFV * NTOK * HDV];      // [hf][n][d], pre-scaled hd^-0.5
__device__ __half g_kh[NHV * NFV * NTOK * HDV];      // [hf][n][d]
__device__ __half g_vT[NHV * NFV * HDV * NTOK];      // [hf][d][n] transposed
__device__ __half g_yh[NFV * NTOK * DINV];           // yhat * cm1, fp16
__device__ float  g_callT[NTOK * NFV];               // [c][f] transposed compat

// ============================================================
// helpers
// ============================================================
__device__ __forceinline__ void mma_f16(float* d, uint32_t a0, uint32_t a1,
                                        uint32_t a2, uint32_t a3,
                                        uint32_t b0, uint32_t b1) {
    asm volatile(
        "mma.sync.aligned.m16n8k16.row.col.f32.f16.f16.f32 "
        "{%0,%1,%2,%3}, {%4,%5,%6,%7}, {%8,%9}, {%0,%1,%2,%3};"
        : "+f"(d[0]), "+f"(d[1]), "+f"(d[2]), "+f"(d[3])
        : "r"(a0), "r"(a1), "r"(a2), "r"(a3), "r"(b0), "r"(b1));
}

__device__ __forceinline__ uint32_t smem_u32(const void* p) {
    uint32_t a;
    asm("{ .reg .u64 t; cvta.to.shared.u64 t, %1; cvt.u32.u64 %0, t; }" : "=r"(a) : "l"(p));
    return a;
}

__device__ __forceinline__ void cp_async16(uint32_t dst, const void* src) {
    asm volatile("cp.async.cg.shared.global [%0], [%1], 16;" :: "r"(dst), "l"(src) : "memory");
}
#define CP_COMMIT() asm volatile("cp.async.commit_group;" ::: "memory")
#define CP_WAIT0()  asm volatile("cp.async.wait_group 0;" ::: "memory")
#define CP_WAIT1()  asm volatile("cp.async.wait_group 1;" ::: "memory")

// attn: stage K tile (128 keys x 64 half dims, smem stride 72 halves)
__device__ __forceinline__ void stage_k(uint32_t dstbase, const __half* src, int tid) {
    #pragma unroll
    for (int i = tid; i < 1024; i += 256) {
        int r = i >> 3, c8 = (i & 7) << 3;
        cp_async16(dstbase + (uint32_t)(r * 144 + c8 * 2), src + r * 64 + c8);
    }
}
// attn: stage V tile (transposed: 64 dim-rows x 128 half keys, stride 136 halves)
__device__ __forceinline__ void stage_v(uint32_t dstbase, const __half* srcT, int tid) {
    #pragma unroll
    for (int i = tid; i < 1024; i += 256) {
        int r = i >> 4, c16 = (i & 15) << 3;
        cp_async16(dstbase + (uint32_t)(r * 272 + c16 * 2), srcT + (size_t)r * NTOK + c16);
    }
}
// gemm: stage 128x64 half tile from 512-stride row-major, smem stride 72 halves
__device__ __forceinline__ void stage_h(uint32_t dstbase, const __half* src, int tid) {
    #pragma unroll
    for (int t = 0; t < 4; t++) {
        int i = tid + t * 256;
        int r = i >> 3, c8 = (i & 7) << 3;
        cp_async16(dstbase + (uint32_t)(r * 144 + c8 * 2), src + (size_t)r * 512 + c8);
    }
}

// ============================================================
// K1: code_mod = LayerNorm((w_c @ code).T) * g + b, both variants
// ============================================================
__global__ __launch_bounds__(512) void code_mod_kernel(
    const float* __restrict__ wc, const float* __restrict__ code,
    const float* __restrict__ gq, const float* __restrict__ bq,
    const float* __restrict__ gp, const float* __restrict__ bp)
{
    int d = threadIdx.x;
    float t[NFV] = {0.f, 0.f, 0.f, 0.f};
    for (int k = 0; k < 128; k++) {
        float w = wc[d * 128 + k];
        #pragma unroll
        for (int f = 0; f < NFV; f++) t[f] += w * code[k * NFV + f];
    }
    __shared__ float red[512];
    float gqd = gq[d], bqd = bq[d], gpd = gp[d], bpd = bp[d];
    for (int f = 0; f < NFV; f++) {
        red[d] = t[f];
        __syncthreads();
        for (int s = 256; s > 0; s >>= 1) {
            if (d < s) red[d] += red[d + s];
            __syncthreads();
        }
        float mu = red[0] * (1.f / 512.f);
        __syncthreads();
        float dv = t[f] - mu;
        red[d] = dv * dv;
        __syncthreads();
        for (int s = 256; s > 0; s >>= 1) {
            if (d < s) red[d] += red[d + s];
            __syncthreads();
        }
        float var = red[0] * (1.f / 512.f);
        __syncthreads();
        float nrm = dv * rsqrtf(var + 1e-5f);
        g_cm[0][f][d] = nrm * gqd + bqd;
        g_cm[1][f][d] = nrm * gpd + bpd;
    }
}

__global__ __launch_bounds__(256) void prep_callT(const float* __restrict__ cin) {
    int c = blockIdx.x * 256 + threadIdx.x;
    float4 v = make_float4(cin[c], cin[NTOK + c], cin[2 * NTOK + c], cin[3 * NTOK + c]);
    *(float4*)&g_callT[c * 4] = v;
}

// x_h[f][n][d] = half(x[n][d] * cm0[f][d]);  grid (512, 4)
__global__ __launch_bounds__(256) void prep_xh(const float* __restrict__ x) {
    int f = blockIdx.y;
    int i = blockIdx.x * 256 + threadIdx.x;     // float4 index within f
    int n = i >> 7, c4 = (i & 127) << 2;
    float4 v = *(const float4*)(x + (size_t)n * 512 + c4);
    float4 s = *(const float4*)(&g_cm[0][f][c4]);
    __half* dst = g_xh + (size_t)f * NTOK * DINV + (size_t)n * 512 + c4;
    *(__half2*)(dst)     = __floats2half2_rn(v.x * s.x, v.y * s.y);
    *(__half2*)(dst + 2) = __floats2half2_rn(v.z * s.z, v.w * s.w);
}

// convert W_qkv + W_proj to fp16;  grid 1024
__global__ __launch_bounds__(256) void prep_w(const float* __restrict__ Wq,
                                              const float* __restrict__ Wp) {
    int i = blockIdx.x * 256 + threadIdx.x;     // float4 index
    if (i < 196608) {
        float4 v = *(const float4*)(Wq + (size_t)i * 4);
        __half* d = g_wq_h + (size_t)i * 4;
        *(__half2*)(d)     = __floats2half2_rn(v.x, v.y);
        *(__half2*)(d + 2) = __floats2half2_rn(v.z, v.w);
    } else {
        int j = i - 196608;
        float4 v = *(const float4*)(Wp + (size_t)j * 4);
        __half* d = g_wp_h + (size_t)j * 4;
        *(__half2*)(d)     = __floats2half2_rn(v.x, v.y);
        *(__half2*)(d + 2) = __floats2half2_rn(v.z, v.w);
    }
}

// ============================================================
// fp16 GEMM: C[m,j] = A_h[f][m,:] . B_h[j,:] + bias[j]
// 128x128 tile, BK=64, double-buffered cp.async, 2 blocks/SM.
// MODE 0: A = g_xh, B = g_wq_h, scatter -> q/k (half) / vT (smem transpose)
// MODE 1: A = g_yh, B = g_wp_h, out -> d_out (fp32)
// smem halves: A0 0 | A1 9216 | B0 18432 | B1 27648 | bias(fp32) @36864
// ============================================================
#define GH_BYTES (36864 * 2 + 512)

template <int MODE>
__global__ __launch_bounds__(256, 2) void gemm_h(
    const float* __restrict__ bias, float* __restrict__ Out)
{
    extern __shared__ __half smh[];
    float* sbias = (float*)(smh + 36864);
    const int f   = blockIdx.z;
    const int bm0 = blockIdx.y * 128;
    const int bn0 = blockIdx.x * 128;
    const int tid = threadIdx.x;
    const int warp = tid >> 5, lane = tid & 31;
    const int gid = lane >> 2, tig = lane & 3;
    const int wm = warp >> 2, wn = warp & 3;

    const __half* A  = (MODE == 0 ? g_xh : g_yh) + (size_t)f * NTOK * DINV + (size_t)bm0 * 512;
    const __half* Bw = (MODE == 0 ? g_wq_h : g_wp_h) + (size_t)bn0 * 512;

    uint32_t sb = smem_u32(smh);
    uint32_t Ab[2] = {sb, sb + 9216 * 2};
    uint32_t Bb[2] = {sb + 18432 * 2, sb + 27648 * 2};

    if (tid < 128) sbias[tid] = bias[bn0 + tid];

    // prologue: chunk 0 -> buf 0
    stage_h(Ab[0], A, tid);
    stage_h(Bb[0], Bw, tid);
    CP_COMMIT();

    float d[4][4][4];
    #pragma unroll
    for (int mt = 0; mt < 4; mt++)
        #pragma unroll
        for (int nt = 0; nt < 4; nt++)
            #pragma unroll
            for (int q = 0; q < 4; q++) d[mt][nt][q] = 0.f;

    for (int c = 0; c < 8; c++) {
        if (c < 7) {
            stage_h(Ab[(c + 1) & 1], A + (c + 1) * 64, tid);
            stage_h(Bb[(c + 1) & 1], Bw + (c + 1) * 64, tid);
            CP_COMMIT();
            CP_WAIT1();
        } else {
            CP_WAIT0();
        }
        __syncthreads();
        const __half* At = (const __half*)(smh + (size_t)((c & 1) ? 9216 : 0));
        const __half* Bt = (const __half*)(smh + (size_t)((c & 1) ? 27648 : 18432));
        #pragma unroll
        for (int kk = 0; kk < 4; kk++) {
            uint32_t aa[4][4], bb[4][2];
            #pragma unroll
            for (int mt = 0; mt < 4; mt++) {
                const __half* p = At + (wm * 64 + mt * 16 + gid) * 72 + kk * 16 + tig * 2;
                aa[mt][0] = *(const uint32_t*)p;
                aa[mt][1] = *(const uint32_t*)(p + 8 * 72);
                aa[mt][2] = *(const uint32_t*)(p + 8);
                aa[mt][3] = *(const uint32_t*)(p + 8 * 72 + 8);
            }
            #pragma unroll
            for (int nt = 0; nt < 4; nt++) {
                const __half* p = Bt + (wn * 32 + nt * 8 + gid) * 72 + kk * 16 + tig * 2;
                bb[nt][0] = *(const uint32_t*)p;
                bb[nt][1] = *(const uint32_t*)(p + 8);
            }
            #pragma unroll
            for (int mt = 0; mt < 4; mt++)
                #pragma unroll
                for (int nt = 0; nt < 4; nt++)
                    mma_f16(d[mt][nt], aa[mt][0], aa[mt][1], aa[mt][2], aa[mt][3],
                            bb[nt][0], bb[nt][1]);
        }
        __syncthreads();
    }

    if (MODE == 1) {
        float* outp = Out + (size_t)f * NTOK * DINV;
        #pragma unroll
        for (int mt = 0; mt < 4; mt++) {
            int m0 = bm0 + wm * 64 + mt * 16 + gid;
            #pragma unroll
            for (int nt = 0; nt < 4; nt++) {
                int jl = wn * 32 + nt * 8 + tig * 2;
                float b0 = sbias[jl], b1 = sbias[jl + 1];
                float2 v0 = {d[mt][nt][0] + b0, d[mt][nt][1] + b1};
                float2 v1 = {d[mt][nt][2] + b0, d[mt][nt][3] + b1};
                *(float2*)(outp + (size_t)m0 * 512 + bn0 + jl)       = v0;
                *(float2*)(outp + (size_t)(m0 + 8) * 512 + bn0 + jl) = v1;
            }
        }
    } else if (bn0 < 1024) {
        // q or k block (half, [n][d] layout)
        int jb = bn0 + wn * 32;
        int tt = jb >> 9;
        int h  = (jb >> 6) & 7;
        int db = jb & 63;
        float mul = (tt == 0) ? 0.125f : 1.0f;
        __half* base = (tt == 0 ? g_qh : g_kh) + (size_t)((h * NFV + f) * NTOK) * HDV;
        #pragma unroll
        for (int mt = 0; mt < 4; mt++) {
            int m0 = bm0 + wm * 64 + mt * 16 + gid;
            #pragma unroll
            for (int nt = 0; nt < 4; nt++) {
                int jl = wn * 32 + nt * 8 + tig * 2;
                int dc = db + nt * 8 + tig * 2;
                float b0 = sbias[jl], b1 = sbias[jl + 1];
                __half2 h0 = __floats2half2_rn((d[mt][nt][0] + b0) * mul,
                                               (d[mt][nt][1] + b1) * mul);
                __half2 h1 = __floats2half2_rn((d[mt][nt][2] + b0) * mul,
                                               (d[mt][nt][3] + b1) * mul);
                *(__half2*)(base + (size_t)m0 * HDV + dc)       = h0;
                *(__half2*)(base + (size_t)(m0 + 8) * HDV + dc) = h1;
            }
        }
    } else {
        // V block: smem transpose then coalesced store to g_vT
        __syncthreads();
        __half* T = smh;                       // 128 x 136 halves (27KB, fits in A region)
        #pragma unroll
        for (int mt = 0; mt < 4; mt++) {
            int mloc = wm * 64 + mt * 16 + gid;
            #pragma unroll
            for (int nt = 0; nt < 4; nt++) {
                int jl = wn * 32 + nt * 8 + tig * 2;
                float b0 = sbias[jl], b1 = sbias[jl + 1];
                T[jl * 136 + mloc]           = __float2half_rn(d[mt][nt][0] + b0);
                T[(jl + 1) * 136 + mloc]     = __float2half_rn(d[mt][nt][1] + b1);
                T[jl * 136 + mloc + 8]       = __float2half_rn(d[mt][nt][2] + b0);
                T[(jl + 1) * 136 + mloc + 8] = __float2half_rn(d[mt][nt][3] + b1);
            }
        }
        __syncthreads();
        int vbase = bn0 - 1024;
        #pragma unroll
        for (int t = 0; t < 8; t++) {
            int i = tid + t * 256;             // 2048 = 128 j-rows x 16 chunks
            int jl = i >> 4, c8 = (i & 15) << 3;
            uint4 v = *(uint4*)&T[jl * 136 + c8];
            int vcol = vbase + jl;
            __half* dst = g_vT + (size_t)(((vcol >> 6) * NFV + f) * HDV + (vcol & 63)) * NTOK
                          + bm0 + c8;
            *(uint4*)dst = v;
        }
    }
}

// ============================================================
// attention fp16: 256 threads, 4-buffer cp.async pipeline (1 sync/iter),
// no second-softmax max, yhat written fp16 pre-scaled by cm1.
// float offsets: S 0 (32x1036) | QS 33152 | KV 34304 (4 x 4608)
//                CROW 52736 | RMAX 52864 | INV2 52992 | tot 53024 (~207KB)
// ============================================================
#define SSTR     1036
#define SSTRH    2072
#define FO_QS    33152
#define FO_KV    34304
#define FO_CROW  52736
#define FO_RMAX  52864
#define FO_INV2  52992
#define ATTN_SMEM_FLOATS 53024

__global__ __launch_bounds__(256) void attn_kernel(const float* __restrict__ cin)
{
    extern __shared__ float sm[];
    float*  S    = sm;
    __half* Sh   = (__half*)sm;
    __half* Qs   = (__half*)(sm + FO_QS);
    float*  crow = sm + FO_CROW;
    float*  rmax = sm + FO_RMAX;
    float*  inv2 = sm + FO_INV2;

    const int tid = threadIdx.x;
    const int warp = tid >> 5, lane = tid & 31;
    const int gid = lane >> 2, tig = lane & 3;
    const int n0  = blockIdx.x * 32;
    const int hf  = blockIdx.y;
    const int h   = hf >> 2, f = hf & 3;
    const size_t hb  = (size_t)hf * NTOK * HDV;

    uint32_t sb = smem_u32(sm);
    uint32_t kvb[4];
    #pragma unroll
    for (int b = 0; b < 4; b++) kvb[b] = sb + (FO_KV + b * 4608) * 4;
    const __half* Kp  = g_kh + hb;
    const __half* VTp = g_vT + (size_t)hf * HDV * NTOK;

    // prologue: K tiles 0,1
    stage_k(kvb[0], Kp, tid);
    CP_COMMIT();
    stage_k(kvb[1], Kp + 8192, tid);
    CP_COMMIT();

    // Q block: 32 rows x 64 halves -> stride 72
    {
        int r = tid >> 3, c8 = (tid & 7) << 3;
        uint4 v = *(const uint4*)(g_qh + hb + (size_t)(n0 + r) * HDV + c8);
        *(uint4*)((char*)Qs + r * 144 + c8 * 2) = v;
    }
    if (tid < 128) crow[tid] = cin[(tid >> 5) * NTOK + n0 + (tid & 31)];
    __syncthreads();

    const int rg = warp & 1;        // 2 row groups of 16
    const int cg = warp >> 1;       // 4 col groups of 32

    uint32_t aq0[4], aq1[4], aq2[4], aq3[4];
    {
        const __half* q0 = Qs + (rg * 16 + gid) * 72;
        const __half* q1 = q0 + 8 * 72;
        #pragma unroll
        for (int kk = 0; kk < 4; kk++) {
            aq0[kk] = *(const uint32_t*)&q0[kk * 16 + tig * 2];
            aq1[kk] = *(const uint32_t*)&q1[kk * 16 + tig * 2];
            aq2[kk] = *(const uint32_t*)&q0[kk * 16 + tig * 2 + 8];
            aq3[kk] = *(const uint32_t*)&q1[kk * 16 + tig * 2 + 8];
        }
    }

    float smax0 = -1e30f, smax1 = -1e30f;

    // ---- scores, 4-buffer pipeline, 1 sync/iter ----
    for (int mt = 0; mt < 8; mt++) {
        if (mt < 6) { CP_WAIT1(); } else { CP_WAIT0(); }
        __syncthreads();
        if (mt < 6) {
            stage_k(kvb[(mt + 2) & 3], Kp + (size_t)(mt + 2) * 8192, tid);
            CP_COMMIT();
        }
        const __half* KB = (const __half*)(sm + FO_KV + (mt & 3) * 4608);

        float sacc[4][4];
        #pragma unroll
        for (int nt = 0; nt < 4; nt++)
            #pragma unroll
            for (int q = 0; q < 4; q++) sacc[nt][q] = 0.f;
        #pragma unroll
        for (int kk = 0; kk < 4; kk++) {
            #pragma unroll
            for (int nt = 0; nt < 4; nt++) {
                const __half* p = KB + (cg * 32 + nt * 8 + gid) * 72 + kk * 16 + tig * 2;
                mma_f16(sacc[nt], aq0[kk], aq1[kk], aq2[kk], aq3[kk],
                        *(const uint32_t*)p, *(const uint32_t*)(p + 8));
            }
        }
        int row0 = rg * 16 + gid;
        #pragma unroll
        for (int nt = 0; nt < 4; nt++) {
            smax0 = fmaxf(smax0, fmaxf(sacc[nt][0], sacc[nt][1]));
            smax1 = fmaxf(smax1, fmaxf(sacc[nt][2], sacc[nt][3]));
            int col = mt * 128 + cg * 32 + nt * 8 + tig * 2;
            *(float2*)&S[row0 * SSTR + col]       = make_float2(sacc[nt][0], sacc[nt][1]);
            *(float2*)&S[(row0 + 8) * SSTR + col] = make_float2(sacc[nt][2], sacc[nt][3]);
        }
    }

    // row-max partials
    smax0 = fmaxf(smax0, __shfl_xor_sync(0xffffffffu, smax0, 1));
    smax0 = fmaxf(smax0, __shfl_xor_sync(0xffffffffu, smax0, 2));
    smax1 = fmaxf(smax1, __shfl_xor_sync(0xffffffffu, smax1, 1));
    smax1 = fmaxf(smax1, __shfl_xor_sync(0xffffffffu, smax1, 2));
    if (tig == 0) {
        rmax[(rg * 16 + gid) * 4 + cg]     = smax0;
        rmax[(rg * 16 + gid + 8) * 4 + cg] = smax1;
    }

    // prefetch V tiles 0,1 (overlap softmax)
    stage_v(kvb[0], VTp, tid);
    CP_COMMIT();
    stage_v(kvb[1], VTp + 128, tid);
    CP_COMMIT();
    __syncthreads();

    // ---- double softmax (warp -> 4 rows); pass2 writes half P in-place ----
    {
        const float4* cT = (const float4*)g_callT;
        int r0 = warp * 4;
        float cr[4][4];
        #pragma unroll
        for (int rr = 0; rr < 4; rr++)
            #pragma unroll
            for (int ff = 0; ff < 4; ff++) cr[rr][ff] = crow[ff * 32 + r0 + rr];

        float mx[4], s1[4];
        #pragma unroll
        for (int rr = 0; rr < 4; rr++) {
            float4 m4 = *(float4*)&rmax[(r0 + rr) * 4];
            mx[rr] = fmaxf(fmaxf(m4.x, m4.y), fmaxf(m4.z, m4.w));
            s1[rr] = 0.f;
        }

        #pragma unroll 2
        for (int i = 0; i < 8; i++) {
            int c = i * 128 + lane * 4;
            float4 w0 = cT[c], w1 = cT[c + 1], w2 = cT[c + 2], w3 = cT[c + 3];
            #pragma unroll
            for (int rr = 0; rr < 4; rr++) {
                float4 v = *(float4*)&S[(r0 + rr) * SSTR + c];
                float e0 = __expf(v.x - mx[rr]);
                float e1 = __expf(v.y - mx[rr]);
                float e2 = __expf(v.z - mx[rr]);
                float e3 = __expf(v.w - mx[rr]);
                float p0 = cr[rr][0] * w0.x + cr[rr][1] * w0.y + cr[rr][2] * w0.z + cr[rr][3] * w0.w;
                float p1 = cr[rr][0] * w1.x + cr[rr][1] * w1.y + cr[rr][2] * w1.z + cr[rr][3] * w1.w;
                float p2 = cr[rr][0] * w2.x + cr[rr][1] * w2.y + cr[rr][2] * w2.z + cr[rr][3] * w2.w;
                float p3 = cr[rr][0] * w3.x + cr[rr][1] * w3.y + cr[rr][2] * w3.z + cr[rr][3] * w3.w;
                s1[rr] += (e0 + e1) + (e2 + e3);
                *(float4*)&S[(r0 + rr) * SSTR + c] =
                    make_float4(e0 * p0, e1 * p1, e2 * p2, e3 * p3);
            }
        }
        #pragma unroll
        for (int rr = 0; rr < 4; rr++) {
            #pragma unroll
            for (int o = 16; o; o >>= 1)
                s1[rr] += __shfl_xor_sync(0xffffffffu, s1[rr], o);
        }
        float inv1[4], s2[4];
        #pragma unroll
        for (int rr = 0; rr < 4; rr++) { inv1[rr] = 1.f / s1[rr]; s2[rr] = 0.f; }

        // pass 2: p = exp(u*inv1)  (bounded: u*inv1 in [0,4]); write half in place
        #pragma unroll 2
        for (int i = 0; i < 8; i++) {
            int c = i * 128 + lane * 4;
            #pragma unroll
            for (int rr = 0; rr < 4; rr++) {
                float4 u = *(float4*)&S[(r0 + rr) * SSTR + c];
                float p0 = __expf(u.x * inv1[rr]);
                float p1 = __expf(u.y * inv1[rr]);
                float p2 = __expf(u.z * inv1[rr]);
                float p3 = __expf(u.w * inv1[rr]);
                s2[rr] += (p0 + p1) + (p2 + p3);
                *(__half2*)&Sh[(r0 + rr) * SSTRH + c]     = __floats2half2_rn(p0, p1);
                *(__half2*)&Sh[(r0 + rr) * SSTRH + c + 2] = __floats2half2_rn(p2, p3);
            }
        }
        #pragma unroll
        for (int rr = 0; rr < 4; rr++) {
            #pragma unroll
            for (int o = 16; o; o >>= 1) s2[rr] += __shfl_xor_sync(0xffffffffu, s2[rr], o);
        }
        if (lane == 0) {
            #pragma unroll
            for (int rr = 0; rr < 4; rr++) inv2[r0 + rr] = 1.f / s2[rr];
        }
    }

    // ---- PV, 4-buffer pipeline: warp = 16 rows x 16 dims ----
    const int cg2 = warp >> 1;
    float o[2][4];
    #pragma unroll
    for (int nt = 0; nt < 2; nt++)
        #pragma unroll
        for (int q = 0; q < 4; q++) o[nt][q] = 0.f;

    for (int mt = 0; mt < 8; mt++) {
        if (mt < 6) { CP_WAIT1(); } else { CP_WAIT0(); }
        __syncthreads();
        if (mt < 6) {
            stage_v(kvb[(mt + 2) & 3], VTp + (mt + 2) * 128, tid);
            CP_COMMIT();
        }
        const __half* VB  = (const __half*)(sm + FO_KV + (mt & 3) * 4608);
        const __half* Sr0 = Sh + (rg * 16 + gid) * SSTRH + mt * 128;
        const __half* Sr1 = Sr0 + 8 * SSTRH;
        #pragma unroll
        for (int k0 = 0; k0 < 8; k0++) {
            uint32_t a0 = *(const uint32_t*)&Sr0[k0 * 16 + tig * 2];
            uint32_t a1 = *(const uint32_t*)&Sr1[k0 * 16 + tig * 2];
            uint32_t a2 = *(const uint32_t*)&Sr0[k0 * 16 + tig * 2 + 8];
            uint32_t a3 = *(const uint32_t*)&Sr1[k0 * 16 + tig * 2 + 8];
            #pragma unroll
            for (int nt = 0; nt < 2; nt++) {
                const __half* p = VB + (cg2 * 16 + nt * 8 + gid) * 136 + k0 * 16 + tig * 2;
                mma_f16(o[nt], a0, a1, a2, a3,
                        *(const uint32_t*)p, *(const uint32_t*)(p + 8));
            }
        }
    }
    __syncthreads();

    {
        int r0e = rg * 16 + gid;
        float isa = inv2[r0e], isb = inv2[r0e + 8];
        const float* cm1p = &g_cm[1][f][h * 64];
        __half* yp0 = g_yh + (size_t)f * NTOK * DINV + (size_t)(n0 + r0e) * DINV + h * HDV;
        __half* yp1 = yp0 + 8 * DINV;
        #pragma unroll
        for (int nt = 0; nt < 2; nt++) {
            int dc = cg2 * 16 + nt * 8 + tig * 2;
            float c0 = cm1p[dc], c1 = cm1p[dc + 1];
            *(__half2*)(yp0 + dc) = __floats2half2_rn(o[nt][0] * isa * c0, o[nt][1] * isa * c1);
            *(__half2*)(yp1 + dc) = __floats2half2_rn(o[nt][2] * isb * c0, o[nt][3] * isb * c1);
        }
    }
}

// ============================================================
extern "C" void kernel_launch(void* const* d_in, const int* in_sizes, int n_in,
                              void* d_out, int out_size)
{
    const float* x      = (const float*)d_in[0];
    const float* compat = (const float*)d_in[1];
    const float* code   = (const float*)d_in[2];
    const float* wc     = (const float*)d_in[3];
    const float* Wqkv   = (const float*)d_in[4];
    const float* bqkv   = (const float*)d_in[5];
    const float* Wproj  = (const float*)d_in[6];
    const float* bproj  = (const float*)d_in[7];
    const float* lnqg   = (const float*)d_in[8];
    const float* lnqb   = (const float*)d_in[9];
    const float* lnpg   = (const float*)d_in[10];
    const float* lnpb   = (const float*)d_in[11];
    float* out = (float*)d_out;

    cudaFuncSetAttribute(attn_kernel,
                         cudaFuncAttributeMaxDynamicSharedMemorySize, ATTN_SMEM_FLOATS * 4);
    cudaFuncSetAttribute(gemm_h<0>,
                         cudaFuncAttributeMaxDynamicSharedMemorySize, GH_BYTES);
    cudaFuncSetAttribute(gemm_h<1>,
                         cudaFuncAttributeMaxDynamicSharedMemorySize, GH_BYTES);

    code_mod_kernel<<<1, 512>>>(wc, code, lnqg, lnqb, lnpg, lnpb);
    prep_callT<<<4, 256>>>(compat);
    prep_w<<<1024, 256>>>(Wqkv, Wproj);
    prep_xh<<<dim3(512, 4), 256>>>(x);
    gemm_h<0><<<dim3(12, 8, 4), 256, GH_BYTES>>>(bqkv, nullptr);
    attn_kernel<<<dim3(32, 32), 256, ATTN_SMEM_FLOATS * 4>>>(compat);
    gemm_h<1><<<dim3(4, 8, 4), 256, GH_BYTES>>>(bproj, out);
}

// round 8
// speedup vs baseline: 1.8817x; 1.1716x over previous
#include <cuda_runtime.h>
#include <cuda_fp16.h>
#include <math.h>
#include <stdint.h>

#define NTOK 1024
#define DINV 512
#define NFV  4
#define NHV  8
#define HDV  64

// -------- scratch (device globals; no allocation allowed) --------
__device__ float  g_cm[2][NFV][DINV];                // [qkv|proj][f][d]
__device__ __half g_xh[NFV * NTOK * DINV];           // x * cm0, fp16
__device__ __half g_wq_h[3 * DINV * DINV];           // W_qkv fp16
__device__ __half g_wp_h[DINV * DINV];               // W_proj fp16
__device__ __half g_qh[NHV * NFV * NTOK * HDV];      // [hf][n][d], pre-scaled hd^-0.5
__device__ __half g_kh[NHV * NFV * NTOK * HDV];      // [hf][n][d]
__device__ __half g_vT[NHV * NFV * HDV * NTOK];      // [hf][d][n] transposed
__device__ __half g_yh[NFV * NTOK * DINV];           // yhat * cm1, fp16
__device__ float  g_callT[NTOK * NFV];               // [c][f] transposed compat

// ============================================================
// helpers
// ============================================================
__device__ __forceinline__ void mma_f16(float* d, uint32_t a0, uint32_t a1,
                                        uint32_t a2, uint32_t a3,
                                        uint32_t b0, uint32_t b1) {
    asm volatile(
        "mma.sync.aligned.m16n8k16.row.col.f32.f16.f16.f32 "
        "{%0,%1,%2,%3}, {%4,%5,%6,%7}, {%8,%9}, {%0,%1,%2,%3};"
        : "+f"(d[0]), "+f"(d[1]), "+f"(d[2]), "+f"(d[3])
        : "r"(a0), "r"(a1), "r"(a2), "r"(a3), "r"(b0), "r"(b1));
}

__device__ __forceinline__ uint32_t smem_u32(const void* p) {
    uint32_t a;
    asm("{ .reg .u64 t; cvta.to.shared.u64 t, %1; cvt.u32.u64 %0, t; }" : "=r"(a) : "l"(p));
    return a;
}

__device__ __forceinline__ void cp_async16(uint32_t dst, const void* src) {
    asm volatile("cp.async.cg.shared.global [%0], [%1], 16;" :: "r"(dst), "l"(src) : "memory");
}
#define CP_COMMIT() asm volatile("cp.async.commit_group;" ::: "memory")
#define CP_WAIT0()  asm volatile("cp.async.wait_group 0;" ::: "memory")
#define CP_WAIT1()  asm volatile("cp.async.wait_group 1;" ::: "memory")

// attn: stage K tile (128 keys x 64 half dims, smem stride 72 halves)
__device__ __forceinline__ void stage_k(uint32_t dstbase, const __half* src, int tid) {
    #pragma unroll
    for (int i = tid; i < 1024; i += 256) {
        int r = i >> 3, c8 = (i & 7) << 3;
        cp_async16(dstbase + (uint32_t)(r * 144 + c8 * 2), src + r * 64 + c8);
    }
}
// attn: stage V tile (transposed: 64 dim-rows x 128 half keys, stride 136 halves)
__device__ __forceinline__ void stage_v(uint32_t dstbase, const __half* srcT, int tid) {
    #pragma unroll
    for (int i = tid; i < 1024; i += 256) {
        int r = i >> 4, c16 = (i & 15) << 3;
        cp_async16(dstbase + (uint32_t)(r * 272 + c16 * 2), srcT + (size_t)r * NTOK + c16);
    }
}
// gemm: stage 128x64 half tile from 512-stride row-major, smem stride 72 halves
__device__ __forceinline__ void stage_h(uint32_t dstbase, const __half* src, int tid) {
    #pragma unroll
    for (int t = 0; t < 4; t++) {
        int i = tid + t * 256;
        int r = i >> 3, c8 = (i & 7) << 3;
        cp_async16(dstbase + (uint32_t)(r * 144 + c8 * 2), src + (size_t)r * 512 + c8);
    }
}

// ============================================================
// K1: code_mod = LayerNorm((w_c @ code).T) * g + b, both variants
// ============================================================
__global__ __launch_bounds__(512) void code_mod_kernel(
    const float* __restrict__ wc, const float* __restrict__ code,
    const float* __restrict__ gq, const float* __restrict__ bq,
    const float* __restrict__ gp, const float* __restrict__ bp)
{
    int d = threadIdx.x;
    float t[NFV] = {0.f, 0.f, 0.f, 0.f};
    for (int k = 0; k < 128; k++) {
        float w = wc[d * 128 + k];
        #pragma unroll
        for (int f = 0; f < NFV; f++) t[f] += w * code[k * NFV + f];
    }
    __shared__ float red[512];
    float gqd = gq[d], bqd = bq[d], gpd = gp[d], bpd = bp[d];
    for (int f = 0; f < NFV; f++) {
        red[d] = t[f];
        __syncthreads();
        for (int s = 256; s > 0; s >>= 1) {
            if (d < s) red[d] += red[d + s];
            __syncthreads();
        }
        float mu = red[0] * (1.f / 512.f);
        __syncthreads();
        float dv = t[f] - mu;
        red[d] = dv * dv;
        __syncthreads();
        for (int s = 256; s > 0; s >>= 1) {
            if (d < s) red[d] += red[d + s];
            __syncthreads();
        }
        float var = red[0] * (1.f / 512.f);
        __syncthreads();
        float nrm = dv * rsqrtf(var + 1e-5f);
        g_cm[0][f][d] = nrm * gqd + bqd;
        g_cm[1][f][d] = nrm * gpd + bpd;
    }
}

__global__ __launch_bounds__(256) void prep_callT(const float* __restrict__ cin) {
    int c = blockIdx.x * 256 + threadIdx.x;
    float4 v = make_float4(cin[c], cin[NTOK + c], cin[2 * NTOK + c], cin[3 * NTOK + c]);
    *(float4*)&g_callT[c * 4] = v;
}

__global__ __launch_bounds__(256) void prep_xh(const float* __restrict__ x) {
    int f = blockIdx.y;
    int i = blockIdx.x * 256 + threadIdx.x;
    int n = i >> 7, c4 = (i & 127) << 2;
    float4 v = *(const float4*)(x + (size_t)n * 512 + c4);
    float4 s = *(const float4*)(&g_cm[0][f][c4]);
    __half* dst = g_xh + (size_t)f * NTOK * DINV + (size_t)n * 512 + c4;
    *(__half2*)(dst)     = __floats2half2_rn(v.x * s.x, v.y * s.y);
    *(__half2*)(dst + 2) = __floats2half2_rn(v.z * s.z, v.w * s.w);
}

__global__ __launch_bounds__(256) void prep_w(const float* __restrict__ Wq,
                                              const float* __restrict__ Wp) {
    int i = blockIdx.x * 256 + threadIdx.x;
    if (i < 196608) {
        float4 v = *(const float4*)(Wq + (size_t)i * 4);
        __half* d = g_wq_h + (size_t)i * 4;
        *(__half2*)(d)     = __floats2half2_rn(v.x, v.y);
        *(__half2*)(d + 2) = __floats2half2_rn(v.z, v.w);
    } else {
        int j = i - 196608;
        float4 v = *(const float4*)(Wp + (size_t)j * 4);
        __half* d = g_wp_h + (size_t)j * 4;
        *(__half2*)(d)     = __floats2half2_rn(v.x, v.y);
        *(__half2*)(d + 2) = __floats2half2_rn(v.z, v.w);
    }
}

// ============================================================
// fp16 GEMM (unchanged from R7)
// ============================================================
#define GH_BYTES (36864 * 2 + 512)

template <int MODE>
__global__ __launch_bounds__(256, 2) void gemm_h(
    const float* __restrict__ bias, float* __restrict__ Out)
{
    extern __shared__ __half smh[];
    float* sbias = (float*)(smh + 36864);
    const int f   = blockIdx.z;
    const int bm0 = blockIdx.y * 128;
    const int bn0 = blockIdx.x * 128;
    const int tid = threadIdx.x;
    const int warp = tid >> 5, lane = tid & 31;
    const int gid = lane >> 2, tig = lane & 3;
    const int wm = warp >> 2, wn = warp & 3;

    const __half* A  = (MODE == 0 ? g_xh : g_yh) + (size_t)f * NTOK * DINV + (size_t)bm0 * 512;
    const __half* Bw = (MODE == 0 ? g_wq_h : g_wp_h) + (size_t)bn0 * 512;

    uint32_t sb = smem_u32(smh);
    uint32_t Ab[2] = {sb, sb + 9216 * 2};
    uint32_t Bb[2] = {sb + 18432 * 2, sb + 27648 * 2};

    if (tid < 128) sbias[tid] = bias[bn0 + tid];

    stage_h(Ab[0], A, tid);
    stage_h(Bb[0], Bw, tid);
    CP_COMMIT();

    float d[4][4][4];
    #pragma unroll
    for (int mt = 0; mt < 4; mt++)
        #pragma unroll
        for (int nt = 0; nt < 4; nt++)
            #pragma unroll
            for (int q = 0; q < 4; q++) d[mt][nt][q] = 0.f;

    for (int c = 0; c < 8; c++) {
        if (c < 7) {
            stage_h(Ab[(c + 1) & 1], A + (c + 1) * 64, tid);
            stage_h(Bb[(c + 1) & 1], Bw + (c + 1) * 64, tid);
            CP_COMMIT();
            CP_WAIT1();
        } else {
            CP_WAIT0();
        }
        __syncthreads();
        const __half* At = (const __half*)(smh + (size_t)((c & 1) ? 9216 : 0));
        const __half* Bt = (const __half*)(smh + (size_t)((c & 1) ? 27648 : 18432));
        #pragma unroll
        for (int kk = 0; kk < 4; kk++) {
            uint32_t aa[4][4], bb[4][2];
            #pragma unroll
            for (int mt = 0; mt < 4; mt++) {
                const __half* p = At + (wm * 64 + mt * 16 + gid) * 72 + kk * 16 + tig * 2;
                aa[mt][0] = *(const uint32_t*)p;
                aa[mt][1] = *(const uint32_t*)(p + 8 * 72);
                aa[mt][2] = *(const uint32_t*)(p + 8);
                aa[mt][3] = *(const uint32_t*)(p + 8 * 72 + 8);
            }
            #pragma unroll
            for (int nt = 0; nt < 4; nt++) {
                const __half* p = Bt + (wn * 32 + nt * 8 + gid) * 72 + kk * 16 + tig * 2;
                bb[nt][0] = *(const uint32_t*)p;
                bb[nt][1] = *(const uint32_t*)(p + 8);
            }
            #pragma unroll
            for (int mt = 0; mt < 4; mt++)
                #pragma unroll
                for (int nt = 0; nt < 4; nt++)
                    mma_f16(d[mt][nt], aa[mt][0], aa[mt][1], aa[mt][2], aa[mt][3],
                            bb[nt][0], bb[nt][1]);
        }
        __syncthreads();
    }

    if (MODE == 1) {
        float* outp = Out + (size_t)f * NTOK * DINV;
        #pragma unroll
        for (int mt = 0; mt < 4; mt++) {
            int m0 = bm0 + wm * 64 + mt * 16 + gid;
            #pragma unroll
            for (int nt = 0; nt < 4; nt++) {
                int jl = wn * 32 + nt * 8 + tig * 2;
                float b0 = sbias[jl], b1 = sbias[jl + 1];
                float2 v0 = {d[mt][nt][0] + b0, d[mt][nt][1] + b1};
                float2 v1 = {d[mt][nt][2] + b0, d[mt][nt][3] + b1};
                *(float2*)(outp + (size_t)m0 * 512 + bn0 + jl)       = v0;
                *(float2*)(outp + (size_t)(m0 + 8) * 512 + bn0 + jl) = v1;
            }
        }
    } else if (bn0 < 1024) {
        int jb = bn0 + wn * 32;
        int tt = jb >> 9;
        int h  = (jb >> 6) & 7;
        int db = jb & 63;
        float mul = (tt == 0) ? 0.125f : 1.0f;
        __half* base = (tt == 0 ? g_qh : g_kh) + (size_t)((h * NFV + f) * NTOK) * HDV;
        #pragma unroll
        for (int mt = 0; mt < 4; mt++) {
            int m0 = bm0 + wm * 64 + mt * 16 + gid;
            #pragma unroll
            for (int nt = 0; nt < 4; nt++) {
                int jl = wn * 32 + nt * 8 + tig * 2;
                int dc = db + nt * 8 + tig * 2;
                float b0 = sbias[jl], b1 = sbias[jl + 1];
                __half2 h0 = __floats2half2_rn((d[mt][nt][0] + b0) * mul,
                                               (d[mt][nt][1] + b1) * mul);
                __half2 h1 = __floats2half2_rn((d[mt][nt][2] + b0) * mul,
                                               (d[mt][nt][3] + b1) * mul);
                *(__half2*)(base + (size_t)m0 * HDV + dc)       = h0;
                *(__half2*)(base + (size_t)(m0 + 8) * HDV + dc) = h1;
            }
        }
    } else {
        __syncthreads();
        __half* T = smh;
        #pragma unroll
        for (int mt = 0; mt < 4; mt++) {
            int mloc = wm * 64 + mt * 16 + gid;
            #pragma unroll
            for (int nt = 0; nt < 4; nt++) {
                int jl = wn * 32 + nt * 8 + tig * 2;
                float b0 = sbias[jl], b1 = sbias[jl + 1];
                T[jl * 136 + mloc]           = __float2half_rn(d[mt][nt][0] + b0);
                T[(jl + 1) * 136 + mloc]     = __float2half_rn(d[mt][nt][1] + b1);
                T[jl * 136 + mloc + 8]       = __float2half_rn(d[mt][nt][2] + b0);
                T[(jl + 1) * 136 + mloc + 8] = __float2half_rn(d[mt][nt][3] + b1);
            }
        }
        __syncthreads();
        int vbase = bn0 - 1024;
        #pragma unroll
        for (int t = 0; t < 8; t++) {
            int i = tid + t * 256;
            int jl = i >> 4, c8 = (i & 15) << 3;
            uint4 v = *(uint4*)&T[jl * 136 + c8];
            int vcol = vbase + jl;
            __half* dst = g_vT + (size_t)(((vcol >> 6) * NFV + f) * HDV + (vcol & 63)) * NTOK
                          + bm0 + c8;
            *(uint4*)dst = v;
        }
    }
}

// ============================================================
// attention: flash-style, no S panel. 256 threads, 2 blocks/SM.
// Pass 1: QK^T streaming -> s1. Pass 2: recompute QK^T, p in regs -> PV.
// smem bytes: K0 0 | V0 18432 | K1 35840 | V1 54272 | Q 71680 |
//             CROW 76288 | INV1 76800 | LRED 76928 | INV2 77440 | tot 77568
// ored (32 rows x 66 x 4 cg fp32 = 33792B) aliases K0/V0 after compute.
// ============================================================
#define AB_K0   0
#define AB_V0   18432
#define AB_K1   35840
#define AB_V1   54272
#define AB_Q    71680
#define AB_CROW 76288
#define AB_INV1 76800
#define AB_LRED 76928
#define AB_INV2 77440
#define ATTN_SMEM_BYTES 77568

__global__ __launch_bounds__(256, 2) void attn_kernel(const float* __restrict__ cin)
{
    extern __shared__ char smc[];
    __half* Qs    = (__half*)(smc + AB_Q);
    float*  crow  = (float*)(smc + AB_CROW);
    float*  inv1s = (float*)(smc + AB_INV1);
    float*  lred  = (float*)(smc + AB_LRED);
    float*  inv2s = (float*)(smc + AB_INV2);
    float*  ored  = (float*)smc;

    const int tid = threadIdx.x;
    const int warp = tid >> 5, lane = tid & 31;
    const int gid = lane >> 2, tig = lane & 3;
    const int n0 = blockIdx.x * 32;
    const int hf = blockIdx.y;
    const int h = hf >> 2, f = hf & 3;
    const size_t hb = (size_t)hf * NTOK * HDV;

    uint32_t sb = smem_u32(smc);
    uint32_t kaddr[2] = {sb + AB_K0, sb + AB_K1};
    uint32_t vaddr[2] = {sb + AB_V0, sb + AB_V1};
    const __half* Kp  = g_kh + hb;
    const __half* VTp = g_vT + (size_t)hf * HDV * NTOK;

    // pass-1 prologue: K tiles 0,1
    stage_k(kaddr[0], Kp, tid);         CP_COMMIT();
    stage_k(kaddr[1], Kp + 8192, tid);  CP_COMMIT();

    {   // Q block (32 x 64 halves -> stride 72)
        int r = tid >> 3, c8 = (tid & 7) << 3;
        uint4 v = *(const uint4*)(g_qh + hb + (size_t)(n0 + r) * HDV + c8);
        *(uint4*)((char*)Qs + r * 144 + c8 * 2) = v;
    }
    if (tid < 128) crow[tid] = cin[(tid >> 5) * NTOK + n0 + (tid & 31)];
    __syncthreads();

    const int rg = warp & 1;             // 2 row groups of 16
    const int cg = warp >> 1;            // 4 col groups of 32
    const int r0 = rg * 16 + gid, r1 = r0 + 8;

    uint32_t aq0[4], aq1[4], aq2[4], aq3[4];
    {
        const __half* q0 = Qs + r0 * 72;
        const __half* q1 = Qs + r1 * 72;
        #pragma unroll
        for (int kk = 0; kk < 4; kk++) {
            aq0[kk] = *(const uint32_t*)&q0[kk * 16 + tig * 2];
            aq1[kk] = *(const uint32_t*)&q1[kk * 16 + tig * 2];
            aq2[kk] = *(const uint32_t*)&q0[kk * 16 + tig * 2 + 8];
            aq3[kk] = *(const uint32_t*)&q1[kk * 16 + tig * 2 + 8];
        }
    }
    float cr0[4], cr1[4];
    #pragma unroll
    for (int ff = 0; ff < 4; ff++) { cr0[ff] = crow[ff * 32 + r0]; cr1[ff] = crow[ff * 32 + r1]; }

    // ---- pass 1: s1 = sum exp(s) ----
    float l0 = 0.f, l1 = 0.f;
    for (int mt = 0; mt < 8; mt++) {
        if (mt < 6) { CP_WAIT1(); } else { CP_WAIT0(); }
        __syncthreads();
        const __half* KB = (const __half*)(smc + ((mt & 1) ? AB_K1 : AB_K0));
        float sacc[4][4];
        #pragma unroll
        for (int nt = 0; nt < 4; nt++)
            #pragma unroll
            for (int q = 0; q < 4; q++) sacc[nt][q] = 0.f;
        #pragma unroll
        for (int kk = 0; kk < 4; kk++)
            #pragma unroll
            for (int nt = 0; nt < 4; nt++) {
                const __half* p = KB + (cg * 32 + nt * 8 + gid) * 72 + kk * 16 + tig * 2;
                mma_f16(sacc[nt], aq0[kk], aq1[kk], aq2[kk], aq3[kk],
                        *(const uint32_t*)p, *(const uint32_t*)(p + 8));
            }
        #pragma unroll
        for (int nt = 0; nt < 4; nt++) {
            l0 += __expf(fminf(sacc[nt][0], 80.f)) + __expf(fminf(sacc[nt][1], 80.f));
            l1 += __expf(fminf(sacc[nt][2], 80.f)) + __expf(fminf(sacc[nt][3], 80.f));
        }
        __syncthreads();
        if (mt < 6) {
            stage_k(kaddr[mt & 1], Kp + (size_t)(mt + 2) * 8192, tid);
            CP_COMMIT();
        }
    }
    l0 += __shfl_xor_sync(0xffffffffu, l0, 1);
    l0 += __shfl_xor_sync(0xffffffffu, l0, 2);
    l1 += __shfl_xor_sync(0xffffffffu, l1, 1);
    l1 += __shfl_xor_sync(0xffffffffu, l1, 2);
    if (tig == 0) { lred[cg * 32 + r0] = l0; lred[cg * 32 + r1] = l1; }

    // pass-2 prologue: pair0 safe now (slot0 readers done at iter7 top sync)
    stage_k(kaddr[0], Kp, tid); stage_v(vaddr[0], VTp, tid); CP_COMMIT();
    __syncthreads();
    stage_k(kaddr[1], Kp + 8192, tid); stage_v(vaddr[1], VTp + 128, tid); CP_COMMIT();
    if (tid < 32)
        inv1s[tid] = 1.f / (lred[tid] + lred[32 + tid] + lred[64 + tid] + lred[96 + tid]);
    __syncthreads();

    const float i1r0 = inv1s[r0], i1r1 = inv1s[r1];
    const float4* cT = (const float4*)g_callT;

    // ---- pass 2: recompute scores, p in registers, PV ----
    float o[8][4];
    #pragma unroll
    for (int dt = 0; dt < 8; dt++)
        #pragma unroll
        for (int q = 0; q < 4; q++) o[dt][q] = 0.f;
    float s2l0 = 0.f, s2l1 = 0.f;

    for (int mt = 0; mt < 8; mt++) {
        if (mt < 6) { CP_WAIT1(); } else { CP_WAIT0(); }
        __syncthreads();
        const __half* KB = (const __half*)(smc + ((mt & 1) ? AB_K1 : AB_K0));
        const __half* VB = (const __half*)(smc + ((mt & 1) ? AB_V1 : AB_V0));

        float sacc[4][4];
        #pragma unroll
        for (int nt = 0; nt < 4; nt++)
            #pragma unroll
            for (int q = 0; q < 4; q++) sacc[nt][q] = 0.f;
        #pragma unroll
        for (int kk = 0; kk < 4; kk++)
            #pragma unroll
            for (int nt = 0; nt < 4; nt++) {
                const __half* p = KB + (cg * 32 + nt * 8 + gid) * 72 + kk * 16 + tig * 2;
                mma_f16(sacc[nt], aq0[kk], aq1[kk], aq2[kk], aq3[kk],
                        *(const uint32_t*)p, *(const uint32_t*)(p + 8));
            }

        uint32_t ph0[4], ph1[4];
        #pragma unroll
        for (int nt = 0; nt < 4; nt++) {
            int c = mt * 128 + cg * 32 + nt * 8 + tig * 2;
            float4 w0 = cT[c], w1 = cT[c + 1];
            float cA = cr0[0] * w0.x + cr0[1] * w0.y + cr0[2] * w0.z + cr0[3] * w0.w;
            float cB = cr0[0] * w1.x + cr0[1] * w1.y + cr0[2] * w1.z + cr0[3] * w1.w;
            float cC = cr1[0] * w0.x + cr1[1] * w0.y + cr1[2] * w0.z + cr1[3] * w0.w;
            float cD = cr1[0] * w1.x + cr1[1] * w1.y + cr1[2] * w1.z + cr1[3] * w1.w;
            float e0 = __expf(fminf(sacc[nt][0], 80.f));
            float e1 = __expf(fminf(sacc[nt][1], 80.f));
            float e2 = __expf(fminf(sacc[nt][2], 80.f));
            float e3 = __expf(fminf(sacc[nt][3], 80.f));
            float p00 = __expf(e0 * cA * i1r0);
            float p01 = __expf(e1 * cB * i1r0);
            float p10 = __expf(e2 * cC * i1r1);
            float p11 = __expf(e3 * cD * i1r1);
            s2l0 += p00 + p01;
            s2l1 += p10 + p11;
            __half2 hA = __floats2half2_rn(p00, p01);
            __half2 hB = __floats2half2_rn(p10, p11);
            ph0[nt] = *(uint32_t*)&hA;
            ph1[nt] = *(uint32_t*)&hB;
        }
        #pragma unroll
        for (int kb = 0; kb < 2; kb++) {
            uint32_t a0 = ph0[2 * kb], a1 = ph1[2 * kb];
            uint32_t a2 = ph0[2 * kb + 1], a3 = ph1[2 * kb + 1];
            #pragma unroll
            for (int dt = 0; dt < 8; dt++) {
                const __half* vp = VB + (dt * 8 + gid) * 136 + cg * 32 + kb * 16 + tig * 2;
                mma_f16(o[dt], a0, a1, a2, a3,
                        *(const uint32_t*)vp, *(const uint32_t*)(vp + 8));
            }
        }
        __syncthreads();
        if (mt < 6) {
            stage_k(kaddr[mt & 1], Kp + (size_t)(mt + 2) * 8192, tid);
            stage_v(vaddr[mt & 1], VTp + (mt + 2) * 128, tid);
            CP_COMMIT();
        }
    }

    // s2 reduce
    s2l0 += __shfl_xor_sync(0xffffffffu, s2l0, 1);
    s2l0 += __shfl_xor_sync(0xffffffffu, s2l0, 2);
    s2l1 += __shfl_xor_sync(0xffffffffu, s2l1, 1);
    s2l1 += __shfl_xor_sync(0xffffffffu, s2l1, 2);
    if (tig == 0) { lred[cg * 32 + r0] = s2l0; lred[cg * 32 + r1] = s2l1; }
    __syncthreads();                     // also frees K/V buffers for ored
    if (tid < 32)
        inv2s[tid] = 1.f / (lred[tid] + lred[32 + tid] + lred[64 + tid] + lred[96 + tid]);
    // write partial O (stride 66 to dodge bank conflicts)
    #pragma unroll
    for (int dt = 0; dt < 8; dt++) {
        float* dst0 = ored + cg * 2112 + r0 * 66 + dt * 8 + tig * 2;
        float* dst1 = ored + cg * 2112 + r1 * 66 + dt * 8 + tig * 2;
        dst0[0] = o[dt][0]; dst0[1] = o[dt][1];
        dst1[0] = o[dt][2]; dst1[1] = o[dt][3];
    }
    __syncthreads();

    // epilogue: reduce 4 cg partials, scale by inv2 and cm1, write fp16 yhat
    const float* cm1p = &g_cm[1][f][h * 64];
    #pragma unroll
    for (int k = 0; k < 8; k++) {
        int t = tid + k * 256;
        int row = t >> 6, dim = t & 63;
        float v = ored[row * 66 + dim] + ored[2112 + row * 66 + dim]
                + ored[4224 + row * 66 + dim] + ored[6336 + row * 66 + dim];
        v *= inv2s[row] * cm1p[dim];
        g_yh[(size_t)f * NTOK * DINV + (size_t)(n0 + row) * DINV + h * 64 + dim] =
            __float2half_rn(v);
    }
}

// ============================================================
extern "C" void kernel_launch(void* const* d_in, const int* in_sizes, int n_in,
                              void* d_out, int out_size)
{
    const float* x      = (const float*)d_in[0];
    const float* compat = (const float*)d_in[1];
    const float* code   = (const float*)d_in[2];
    const float* wc     = (const float*)d_in[3];
    const float* Wqkv   = (const float*)d_in[4];
    const float* bqkv   = (const float*)d_in[5];
    const float* Wproj  = (const float*)d_in[6];
    const float* bproj  = (const float*)d_in[7];
    const float* lnqg   = (const float*)d_in[8];
    const float* lnqb   = (const float*)d_in[9];
    const float* lnpg   = (const float*)d_in[10];
    const float* lnpb   = (const float*)d_in[11];
    float* out = (float*)d_out;

    cudaFuncSetAttribute(attn_kernel,
                         cudaFuncAttributeMaxDynamicSharedMemorySize, ATTN_SMEM_BYTES);
    cudaFuncSetAttribute(gemm_h<0>,
                         cudaFuncAttributeMaxDynamicSharedMemorySize, GH_BYTES);
    cudaFuncSetAttribute(gemm_h<1>,
                         cudaFuncAttributeMaxDynamicSharedMemorySize, GH_BYTES);

    code_mod_kernel<<<1, 512>>>(wc, code, lnqg, lnqb, lnpg, lnpb);
    prep_callT<<<4, 256>>>(compat);
    prep_w<<<1024, 256>>>(Wqkv, Wproj);
    prep_xh<<<dim3(512, 4), 256>>>(x);
    gemm_h<0><<<dim3(12, 8, 4), 256, GH_BYTES>>>(bqkv, nullptr);
    attn_kernel<<<dim3(32, 32), 256, ATTN_SMEM_BYTES>>>(compat);
    gemm_h<1><<<dim3(4, 8, 4), 256, GH_BYTES>>>(bproj, out);
}

// round 9
// speedup vs baseline: 1.9006x; 1.0101x over previous
#include <cuda_runtime.h>
#include <cuda_fp16.h>
#include <math.h>
#include <stdint.h>

#define NTOK 1024
#define DINV 512
#define NFV  4
#define NHV  8
#define HDV  64

// -------- scratch (device globals; no allocation allowed) --------
__device__ float  g_cm[2][NFV][DINV];                // [qkv|proj][f][d]
__device__ __half g_xh[NFV * NTOK * DINV];           // x * cm0, fp16
__device__ __half g_wq_h[3 * DINV * DINV];           // W_qkv fp16
__device__ __half g_wp_h[DINV * DINV];               // W_proj fp16
__device__ __half g_qh[NHV * NFV * NTOK * HDV];      // [hf][n][d], pre-scaled hd^-0.5
__device__ __half g_kh[NHV * NFV * NTOK * HDV];      // [hf][n][d]
__device__ __half g_vT[NHV * NFV * HDV * NTOK];      // [hf][d][n] transposed
__device__ __half g_yh[NFV * NTOK * DINV];           // yhat * cm1, fp16
__device__ float  g_callT[NTOK * NFV];               // [c][f] transposed compat

// ============================================================
// helpers
// ============================================================
__device__ __forceinline__ void mma_f16(float* d, uint32_t a0, uint32_t a1,
                                        uint32_t a2, uint32_t a3,
                                        uint32_t b0, uint32_t b1) {
    asm volatile(
        "mma.sync.aligned.m16n8k16.row.col.f32.f16.f16.f32 "
        "{%0,%1,%2,%3}, {%4,%5,%6,%7}, {%8,%9}, {%0,%1,%2,%3};"
        : "+f"(d[0]), "+f"(d[1]), "+f"(d[2]), "+f"(d[3])
        : "r"(a0), "r"(a1), "r"(a2), "r"(a3), "r"(b0), "r"(b1));
}

__device__ __forceinline__ uint32_t smem_u32(const void* p) {
    uint32_t a;
    asm("{ .reg .u64 t; cvta.to.shared.u64 t, %1; cvt.u32.u64 %0, t; }" : "=r"(a) : "l"(p));
    return a;
}

__device__ __forceinline__ void cp_async16(uint32_t dst, const void* src) {
    asm volatile("cp.async.cg.shared.global [%0], [%1], 16;" :: "r"(dst), "l"(src) : "memory");
}
#define CP_COMMIT() asm volatile("cp.async.commit_group;" ::: "memory")
#define CP_WAIT0()  asm volatile("cp.async.wait_group 0;" ::: "memory")
#define CP_WAIT1()  asm volatile("cp.async.wait_group 1;" ::: "memory")

// attn: stage K tile (128 keys x 64 half dims, smem stride 72 halves)
__device__ __forceinline__ void stage_k(uint32_t dstbase, const __half* src, int tid) {
    #pragma unroll
    for (int i = tid; i < 1024; i += 256) {
        int r = i >> 3, c8 = (i & 7) << 3;
        cp_async16(dstbase + (uint32_t)(r * 144 + c8 * 2), src + r * 64 + c8);
    }
}
// attn: stage V tile (transposed: 64 dim-rows x 128 half keys, stride 136 halves)
__device__ __forceinline__ void stage_v(uint32_t dstbase, const __half* srcT, int tid) {
    #pragma unroll
    for (int i = tid; i < 1024; i += 256) {
        int r = i >> 4, c16 = (i & 15) << 3;
        cp_async16(dstbase + (uint32_t)(r * 272 + c16 * 2), srcT + (size_t)r * NTOK + c16);
    }
}
// gemm: stage 128x64 half tile from 512-stride row-major, smem stride 72 halves
__device__ __forceinline__ void stage_h(uint32_t dstbase, const __half* src, int tid) {
    #pragma unroll
    for (int t = 0; t < 4; t++) {
        int i = tid + t * 256;
        int r = i >> 3, c8 = (i & 7) << 3;
        cp_async16(dstbase + (uint32_t)(r * 144 + c8 * 2), src + (size_t)r * 512 + c8);
    }
}

// ============================================================
// code_mod = LayerNorm((w_c @ code).T) * g + b, both variants
// ============================================================
__global__ __launch_bounds__(512) void code_mod_kernel(
    const float* __restrict__ wc, const float* __restrict__ code,
    const float* __restrict__ gq, const float* __restrict__ bq,
    const float* __restrict__ gp, const float* __restrict__ bp)
{
    int d = threadIdx.x;
    float t[NFV] = {0.f, 0.f, 0.f, 0.f};
    for (int k = 0; k < 128; k++) {
        float w = wc[d * 128 + k];
        #pragma unroll
        for (int f = 0; f < NFV; f++) t[f] += w * code[k * NFV + f];
    }
    __shared__ float red[512];
    float gqd = gq[d], bqd = bq[d], gpd = gp[d], bpd = bp[d];
    for (int f = 0; f < NFV; f++) {
        red[d] = t[f];
        __syncthreads();
        for (int s = 256; s > 0; s >>= 1) {
            if (d < s) red[d] += red[d + s];
            __syncthreads();
        }
        float mu = red[0] * (1.f / 512.f);
        __syncthreads();
        float dv = t[f] - mu;
        red[d] = dv * dv;
        __syncthreads();
        for (int s = 256; s > 0; s >>= 1) {
            if (d < s) red[d] += red[d + s];
            __syncthreads();
        }
        float var = red[0] * (1.f / 512.f);
        __syncthreads();
        float nrm = dv * rsqrtf(var + 1e-5f);
        g_cm[0][f][d] = nrm * gqd + bqd;
        g_cm[1][f][d] = nrm * gpd + bpd;
    }
}

// fused prep: callT (blocks 0..3), weight convert (4..1027), xh (1028..3075)
__global__ __launch_bounds__(256) void prep_all(
    const float* __restrict__ cin, const float* __restrict__ Wq,
    const float* __restrict__ Wp, const float* __restrict__ x)
{
    int b = blockIdx.x, tid = threadIdx.x;
    if (b < 4) {
        int c = b * 256 + tid;
        float4 v = make_float4(cin[c], cin[NTOK + c], cin[2 * NTOK + c], cin[3 * NTOK + c]);
        *(float4*)&g_callT[c * 4] = v;
    } else if (b < 1028) {
        int i = (b - 4) * 256 + tid;
        if (i < 196608) {
            float4 v = *(const float4*)(Wq + (size_t)i * 4);
            __half* d = g_wq_h + (size_t)i * 4;
            *(__half2*)(d)     = __floats2half2_rn(v.x, v.y);
            *(__half2*)(d + 2) = __floats2half2_rn(v.z, v.w);
        } else {
            int j = i - 196608;
            float4 v = *(const float4*)(Wp + (size_t)j * 4);
            __half* d = g_wp_h + (size_t)j * 4;
            *(__half2*)(d)     = __floats2half2_rn(v.x, v.y);
            *(__half2*)(d + 2) = __floats2half2_rn(v.z, v.w);
        }
    } else {
        int j = b - 1028;
        int f = j >> 9;
        int i = (j & 511) * 256 + tid;
        int n = i >> 7, c4 = (i & 127) << 2;
        float4 v = *(const float4*)(x + (size_t)n * 512 + c4);
        float4 s = *(const float4*)(&g_cm[0][f][c4]);
        __half* dst = g_xh + (size_t)f * NTOK * DINV + (size_t)n * 512 + c4;
        *(__half2*)(dst)     = __floats2half2_rn(v.x * s.x, v.y * s.y);
        *(__half2*)(dst + 2) = __floats2half2_rn(v.z * s.z, v.w * s.w);
    }
}

// ============================================================
// fp16 GEMM (unchanged from R7/R8)
// ============================================================
#define GH_BYTES (36864 * 2 + 512)

template <int MODE>
__global__ __launch_bounds__(256, 2) void gemm_h(
    const float* __restrict__ bias, float* __restrict__ Out)
{
    extern __shared__ __half smh[];
    float* sbias = (float*)(smh + 36864);
    const int f   = blockIdx.z;
    const int bm0 = blockIdx.y * 128;
    const int bn0 = blockIdx.x * 128;
    const int tid = threadIdx.x;
    const int warp = tid >> 5, lane = tid & 31;
    const int gid = lane >> 2, tig = lane & 3;
    const int wm = warp >> 2, wn = warp & 3;

    const __half* A  = (MODE == 0 ? g_xh : g_yh) + (size_t)f * NTOK * DINV + (size_t)bm0 * 512;
    const __half* Bw = (MODE == 0 ? g_wq_h : g_wp_h) + (size_t)bn0 * 512;

    uint32_t sb = smem_u32(smh);
    uint32_t Ab[2] = {sb, sb + 9216 * 2};
    uint32_t Bb[2] = {sb + 18432 * 2, sb + 27648 * 2};

    if (tid < 128) sbias[tid] = bias[bn0 + tid];

    stage_h(Ab[0], A, tid);
    stage_h(Bb[0], Bw, tid);
    CP_COMMIT();

    float d[4][4][4];
    #pragma unroll
    for (int mt = 0; mt < 4; mt++)
        #pragma unroll
        for (int nt = 0; nt < 4; nt++)
            #pragma unroll
            for (int q = 0; q < 4; q++) d[mt][nt][q] = 0.f;

    for (int c = 0; c < 8; c++) {
        if (c < 7) {
            stage_h(Ab[(c + 1) & 1], A + (c + 1) * 64, tid);
            stage_h(Bb[(c + 1) & 1], Bw + (c + 1) * 64, tid);
            CP_COMMIT();
            CP_WAIT1();
        } else {
            CP_WAIT0();
        }
        __syncthreads();
        const __half* At = (const __half*)(smh + (size_t)((c & 1) ? 9216 : 0));
        const __half* Bt = (const __half*)(smh + (size_t)((c & 1) ? 27648 : 18432));
        #pragma unroll
        for (int kk = 0; kk < 4; kk++) {
            uint32_t aa[4][4], bb[4][2];
            #pragma unroll
            for (int mt = 0; mt < 4; mt++) {
                const __half* p = At + (wm * 64 + mt * 16 + gid) * 72 + kk * 16 + tig * 2;
                aa[mt][0] = *(const uint32_t*)p;
                aa[mt][1] = *(const uint32_t*)(p + 8 * 72);
                aa[mt][2] = *(const uint32_t*)(p + 8);
                aa[mt][3] = *(const uint32_t*)(p + 8 * 72 + 8);
            }
            #pragma unroll
            for (int nt = 0; nt < 4; nt++) {
                const __half* p = Bt + (wn * 32 + nt * 8 + gid) * 72 + kk * 16 + tig * 2;
                bb[nt][0] = *(const uint32_t*)p;
                bb[nt][1] = *(const uint32_t*)(p + 8);
            }
            #pragma unroll
            for (int mt = 0; mt < 4; mt++)
                #pragma unroll
                for (int nt = 0; nt < 4; nt++)
                    mma_f16(d[mt][nt], aa[mt][0], aa[mt][1], aa[mt][2], aa[mt][3],
                            bb[nt][0], bb[nt][1]);
        }
        __syncthreads();
    }

    if (MODE == 1) {
        float* outp = Out + (size_t)f * NTOK * DINV;
        #pragma unroll
        for (int mt = 0; mt < 4; mt++) {
            int m0 = bm0 + wm * 64 + mt * 16 + gid;
            #pragma unroll
            for (int nt = 0; nt < 4; nt++) {
                int jl = wn * 32 + nt * 8 + tig * 2;
                float b0 = sbias[jl], b1 = sbias[jl + 1];
                float2 v0 = {d[mt][nt][0] + b0, d[mt][nt][1] + b1};
                float2 v1 = {d[mt][nt][2] + b0, d[mt][nt][3] + b1};
                *(float2*)(outp + (size_t)m0 * 512 + bn0 + jl)       = v0;
                *(float2*)(outp + (size_t)(m0 + 8) * 512 + bn0 + jl) = v1;
            }
        }
    } else if (bn0 < 1024) {
        int jb = bn0 + wn * 32;
        int tt = jb >> 9;
        int h  = (jb >> 6) & 7;
        int db = jb & 63;
        float mul = (tt == 0) ? 0.125f : 1.0f;
        __half* base = (tt == 0 ? g_qh : g_kh) + (size_t)((h * NFV + f) * NTOK) * HDV;
        #pragma unroll
        for (int mt = 0; mt < 4; mt++) {
            int m0 = bm0 + wm * 64 + mt * 16 + gid;
            #pragma unroll
            for (int nt = 0; nt < 4; nt++) {
                int jl = wn * 32 + nt * 8 + tig * 2;
                int dc = db + nt * 8 + tig * 2;
                float b0 = sbias[jl], b1 = sbias[jl + 1];
                __half2 h0 = __floats2half2_rn((d[mt][nt][0] + b0) * mul,
                                               (d[mt][nt][1] + b1) * mul);
                __half2 h1 = __floats2half2_rn((d[mt][nt][2] + b0) * mul,
                                               (d[mt][nt][3] + b1) * mul);
                *(__half2*)(base + (size_t)m0 * HDV + dc)       = h0;
                *(__half2*)(base + (size_t)(m0 + 8) * HDV + dc) = h1;
            }
        }
    } else {
        __syncthreads();
        __half* T = smh;
        #pragma unroll
        for (int mt = 0; mt < 4; mt++) {
            int mloc = wm * 64 + mt * 16 + gid;
            #pragma unroll
            for (int nt = 0; nt < 4; nt++) {
                int jl = wn * 32 + nt * 8 + tig * 2;
                float b0 = sbias[jl], b1 = sbias[jl + 1];
                T[jl * 136 + mloc]           = __float2half_rn(d[mt][nt][0] + b0);
                T[(jl + 1) * 136 + mloc]     = __float2half_rn(d[mt][nt][1] + b1);
                T[jl * 136 + mloc + 8]       = __float2half_rn(d[mt][nt][2] + b0);
                T[(jl + 1) * 136 + mloc + 8] = __float2half_rn(d[mt][nt][3] + b1);
            }
        }
        __syncthreads();
        int vbase = bn0 - 1024;
        #pragma unroll
        for (int t = 0; t < 8; t++) {
            int i = tid + t * 256;
            int jl = i >> 4, c8 = (i & 15) << 3;
            uint4 v = *(uint4*)&T[jl * 136 + c8];
            int vcol = vbase + jl;
            __half* dst = g_vT + (size_t)(((vcol >> 6) * NFV + f) * HDV + (vcol & 63)) * NTOK
                          + bm0 + c8;
            *(uint4*)dst = v;
        }
    }
}

// ============================================================
// attention: flash-style, 64-row blocks, 256 threads, 2 blocks/SM.
// warp: rg = warp&3 (16 rows), cgr = warp>>2 (64 of 128 cols / k-split).
// smem bytes: K0 0 | V0 18432 | K1 35840 | V1 54272 | Q 71680 (64x72 half)
//   CROW 80896 | INV1 81920 | LRED 82176 | INV2 82688 | tot 82944
// ored (2 x 64 x 66 fp32 = 33792B) aliases K0/V0 after compute.
// ============================================================
#define AB_K0   0
#define AB_V0   18432
#define AB_K1   35840
#define AB_V1   54272
#define AB_Q    71680
#define AB_CROW 80896
#define AB_INV1 81920
#define AB_LRED 82176
#define AB_INV2 82688
#define ATTN_SMEM_BYTES 82944

__global__ __launch_bounds__(256, 2) void attn_kernel(const float* __restrict__ cin)
{
    extern __shared__ char smc[];
    __half* Qs    = (__half*)(smc + AB_Q);
    float*  crow  = (float*)(smc + AB_CROW);
    float*  inv1s = (float*)(smc + AB_INV1);
    float*  lred  = (float*)(smc + AB_LRED);
    float*  inv2s = (float*)(smc + AB_INV2);
    float*  ored  = (float*)smc;

    const int tid = threadIdx.x;
    const int warp = tid >> 5, lane = tid & 31;
    const int gid = lane >> 2, tig = lane & 3;
    const int n0 = blockIdx.x * 64;
    const int hf = blockIdx.y;
    const int h = hf >> 2, f = hf & 3;
    const size_t hb = (size_t)hf * NTOK * HDV;

    uint32_t sb = smem_u32(smc);
    uint32_t kaddr[2] = {sb + AB_K0, sb + AB_K1};
    uint32_t vaddr[2] = {sb + AB_V0, sb + AB_V1};
    const __half* Kp  = g_kh + hb;
    const __half* VTp = g_vT + (size_t)hf * HDV * NTOK;

    // pass-1 prologue: K tiles 0,1
    stage_k(kaddr[0], Kp, tid);         CP_COMMIT();
    stage_k(kaddr[1], Kp + 8192, tid);  CP_COMMIT();

    // Q block (64 x 64 halves -> stride 72)
    #pragma unroll
    for (int i = tid; i < 512; i += 256) {
        int r = i >> 3, c8 = (i & 7) << 3;
        uint4 v = *(const uint4*)(g_qh + hb + (size_t)(n0 + r) * HDV + c8);
        *(uint4*)((char*)Qs + r * 144 + c8 * 2) = v;
    }
    crow[tid] = cin[(tid >> 6) * NTOK + n0 + (tid & 63)];
    __syncthreads();

    const int rg  = warp & 3;            // 4 row groups of 16
    const int cgr = warp >> 2;           // 2 col groups of 64
    const int r0 = rg * 16 + gid, r1 = r0 + 8;

    uint32_t aq0[4], aq1[4], aq2[4], aq3[4];
    {
        const __half* q0 = Qs + r0 * 72;
        const __half* q1 = Qs + r1 * 72;
        #pragma unroll
        for (int kk = 0; kk < 4; kk++) {
            aq0[kk] = *(const uint32_t*)&q0[kk * 16 + tig * 2];
            aq1[kk] = *(const uint32_t*)&q1[kk * 16 + tig * 2];
            aq2[kk] = *(const uint32_t*)&q0[kk * 16 + tig * 2 + 8];
            aq3[kk] = *(const uint32_t*)&q1[kk * 16 + tig * 2 + 8];
        }
    }
    float cr0[4], cr1[4];
    #pragma unroll
    for (int ff = 0; ff < 4; ff++) { cr0[ff] = crow[ff * 64 + r0]; cr1[ff] = crow[ff * 64 + r1]; }

    // ---- pass 1: s1 = sum exp(s) ----
    float l0 = 0.f, l1 = 0.f;
    for (int mt = 0; mt < 8; mt++) {
        if (mt < 6) { CP_WAIT1(); } else { CP_WAIT0(); }
        __syncthreads();
        const __half* KB = (const __half*)(smc + ((mt & 1) ? AB_K1 : AB_K0));
        #pragma unroll
        for (int nt = 0; nt < 8; nt++) {
            float s4[4] = {0.f, 0.f, 0.f, 0.f};
            #pragma unroll
            for (int kk = 0; kk < 4; kk++) {
                const __half* p = KB + (cgr * 64 + nt * 8 + gid) * 72 + kk * 16 + tig * 2;
                mma_f16(s4, aq0[kk], aq1[kk], aq2[kk], aq3[kk],
                        *(const uint32_t*)p, *(const uint32_t*)(p + 8));
            }
            l0 += __expf(fminf(s4[0], 80.f)) + __expf(fminf(s4[1], 80.f));
            l1 += __expf(fminf(s4[2], 80.f)) + __expf(fminf(s4[3], 80.f));
        }
        __syncthreads();
        if (mt < 6) {
            stage_k(kaddr[mt & 1], Kp + (size_t)(mt + 2) * 8192, tid);
            CP_COMMIT();
        }
    }
    l0 += __shfl_xor_sync(0xffffffffu, l0, 1);
    l0 += __shfl_xor_sync(0xffffffffu, l0, 2);
    l1 += __shfl_xor_sync(0xffffffffu, l1, 1);
    l1 += __shfl_xor_sync(0xffffffffu, l1, 2);
    if (tig == 0) { lred[cgr * 64 + r0] = l0; lred[cgr * 64 + r1] = l1; }

    // pass-2 prologue
    stage_k(kaddr[0], Kp, tid); stage_v(vaddr[0], VTp, tid); CP_COMMIT();
    __syncthreads();
    stage_k(kaddr[1], Kp + 8192, tid); stage_v(vaddr[1], VTp + 128, tid); CP_COMMIT();
    if (tid < 64) inv1s[tid] = 1.f / (lred[tid] + lred[64 + tid]);
    __syncthreads();

    const float i1r0 = inv1s[r0], i1r1 = inv1s[r1];
    const float4* cT = (const float4*)g_callT;

    // ---- pass 2: recompute scores, p in regs, PV ----
    float o[8][4];
    #pragma unroll
    for (int dt = 0; dt < 8; dt++)
        #pragma unroll
        for (int q = 0; q < 4; q++) o[dt][q] = 0.f;
    float s2l0 = 0.f, s2l1 = 0.f;

    for (int mt = 0; mt < 8; mt++) {
        if (mt < 6) { CP_WAIT1(); } else { CP_WAIT0(); }
        __syncthreads();
        const __half* KB = (const __half*)(smc + ((mt & 1) ? AB_K1 : AB_K0));
        const __half* VB = (const __half*)(smc + ((mt & 1) ? AB_V1 : AB_V0));

        uint32_t ph0[8], ph1[8];
        #pragma unroll
        for (int nt = 0; nt < 8; nt++) {
            float s4[4] = {0.f, 0.f, 0.f, 0.f};
            #pragma unroll
            for (int kk = 0; kk < 4; kk++) {
                const __half* p = KB + (cgr * 64 + nt * 8 + gid) * 72 + kk * 16 + tig * 2;
                mma_f16(s4, aq0[kk], aq1[kk], aq2[kk], aq3[kk],
                        *(const uint32_t*)p, *(const uint32_t*)(p + 8));
            }
            int c = mt * 128 + cgr * 64 + nt * 8 + tig * 2;
            float4 w0 = cT[c], w1 = cT[c + 1];
            float cA = cr0[0] * w0.x + cr0[1] * w0.y + cr0[2] * w0.z + cr0[3] * w0.w;
            float cB = cr0[0] * w1.x + cr0[1] * w1.y + cr0[2] * w1.z + cr0[3] * w1.w;
            float cC = cr1[0] * w0.x + cr1[1] * w0.y + cr1[2] * w0.z + cr1[3] * w0.w;
            float cD = cr1[0] * w1.x + cr1[1] * w1.y + cr1[2] * w1.z + cr1[3] * w1.w;
            float e0 = __expf(fminf(s4[0], 80.f));
            float e1 = __expf(fminf(s4[1], 80.f));
            float e2 = __expf(fminf(s4[2], 80.f));
            float e3 = __expf(fminf(s4[3], 80.f));
            float p00 = __expf(e0 * cA * i1r0);
            float p01 = __expf(e1 * cB * i1r0);
            float p10 = __expf(e2 * cC * i1r1);
            float p11 = __expf(e3 * cD * i1r1);
            s2l0 += p00 + p01;
            s2l1 += p10 + p11;
            __half2 hA = __floats2half2_rn(p00, p01);
            __half2 hB = __floats2half2_rn(p10, p11);
            ph0[nt] = *(uint32_t*)&hA;
            ph1[nt] = *(uint32_t*)&hB;
        }
        #pragma unroll
        for (int kb = 0; kb < 4; kb++) {
            uint32_t a0 = ph0[2 * kb], a1 = ph1[2 * kb];
            uint32_t a2 = ph0[2 * kb + 1], a3 = ph1[2 * kb + 1];
            #pragma unroll
            for (int dt = 0; dt < 8; dt++) {
                const __half* vp = VB + (dt * 8 + gid) * 136 + cgr * 64 + kb * 16 + tig * 2;
                mma_f16(o[dt], a0, a1, a2, a3,
                        *(const uint32_t*)vp, *(const uint32_t*)(vp + 8));
            }
        }
        __syncthreads();
        if (mt < 6) {
            stage_k(kaddr[mt & 1], Kp + (size_t)(mt + 2) * 8192, tid);
            stage_v(vaddr[mt & 1], VTp + (mt + 2) * 128, tid);
            CP_COMMIT();
        }
    }

    // s2 reduce
    s2l0 += __shfl_xor_sync(0xffffffffu, s2l0, 1);
    s2l0 += __shfl_xor_sync(0xffffffffu, s2l0, 2);
    s2l1 += __shfl_xor_sync(0xffffffffu, s2l1, 1);
    s2l1 += __shfl_xor_sync(0xffffffffu, s2l1, 2);
    if (tig == 0) { lred[cgr * 64 + r0] = s2l0; lred[cgr * 64 + r1] = s2l1; }
    __syncthreads();                     // K/V buffers free for ored now
    if (tid < 64) inv2s[tid] = 1.f / (lred[tid] + lred[64 + tid]);
    #pragma unroll
    for (int dt = 0; dt < 8; dt++) {
        float* dst0 = ored + cgr * 4224 + r0 * 66 + dt * 8 + tig * 2;
        float* dst1 = ored + cgr * 4224 + r1 * 66 + dt * 8 + tig * 2;
        dst0[0] = o[dt][0]; dst0[1] = o[dt][1];
        dst1[0] = o[dt][2]; dst1[1] = o[dt][3];
    }
    __syncthreads();

    // epilogue: reduce 2 cgr partials, scale by inv2 and cm1, write fp16 yhat
    const float* cm1p = &g_cm[1][f][h * 64];
    #pragma unroll
    for (int k = 0; k < 16; k++) {
        int t = tid + k * 256;
        int row = t >> 6, dim = t & 63;
        float v = ored[row * 66 + dim] + ored[4224 + row * 66 + dim];
        v *= inv2s[row] * cm1p[dim];
        g_yh[(size_t)f * NTOK * DINV + (size_t)(n0 + row) * DINV + h * 64 + dim] =
            __float2half_rn(v);
    }
}

// ============================================================
extern "C" void kernel_launch(void* const* d_in, const int* in_sizes, int n_in,
                              void* d_out, int out_size)
{
    const float* x      = (const float*)d_in[0];
    const float* compat = (const float*)d_in[1];
    const float* code   = (const float*)d_in[2];
    const float* wc     = (const float*)d_in[3];
    const float* Wqkv   = (const float*)d_in[4];
    const float* bqkv   = (const float*)d_in[5];
    const float* Wproj  = (const float*)d_in[6];
    const float* bproj  = (const float*)d_in[7];
    const float* lnqg   = (const float*)d_in[8];
    const float* lnqb   = (const float*)d_in[9];
    const float* lnpg   = (const float*)d_in[10];
    const float* lnpb   = (const float*)d_in[11];
    float* out = (float*)d_out;

    cudaFuncSetAttribute(attn_kernel,
                         cudaFuncAttributeMaxDynamicSharedMemorySize, ATTN_SMEM_BYTES);
    cudaFuncSetAttribute(gemm_h<0>,
                         cudaFuncAttributeMaxDynamicSharedMemorySize, GH_BYTES);
    cudaFuncSetAttribute(gemm_h<1>,
                         cudaFuncAttributeMaxDynamicSharedMemorySize, GH_BYTES);

    code_mod_kernel<<<1, 512>>>(wc, code, lnqg, lnqb, lnpg, lnpb);
    prep_all<<<3076, 256>>>(compat, Wqkv, Wproj, x);
    gemm_h<0><<<dim3(12, 8, 4), 256, GH_BYTES>>>(bqkv, nullptr);
    attn_kernel<<<dim3(16, 32), 256, ATTN_SMEM_BYTES>>>(compat);
    gemm_h<1><<<dim3(4, 8, 4), 256, GH_BYTES>>>(bproj, out);
}

// round 10
// speedup vs baseline: 2.1255x; 1.1183x over previous
#include <cuda_runtime.h>
#include <cuda_fp16.h>
#include <math.h>
#include <stdint.h>

#define NTOK 1024
#define DINV 512
#define NFV  4
#define NHV  8
#define HDV  64

// -------- scratch (device globals; no allocation allowed) --------
__device__ float  g_cm[2][NFV][DINV];                // [qkv|proj][f][d]
__device__ __half g_xh[NFV * NTOK * DINV];           // x * cm0, fp16
__device__ __half g_wq_h[3 * DINV * DINV];           // W_qkv fp16
__device__ __half g_wp_h[DINV * DINV];               // W_proj fp16
__device__ __half g_qh[NHV * NFV * NTOK * HDV];      // [hf][n][d], pre-scaled hd^-0.5
__device__ __half g_kh[NHV * NFV * NTOK * HDV];      // [hf][n][d]
__device__ __half g_vT[NHV * NFV * HDV * NTOK];      // [hf][d][n] transposed
__device__ __half g_yh[NFV * NTOK * DINV];           // yhat * cm1, fp16
__device__ float  g_callT[NTOK * NFV];               // [c][f] transposed compat

// ============================================================
// helpers
// ============================================================
__device__ __forceinline__ void mma_f16(float* d, uint32_t a0, uint32_t a1,
                                        uint32_t a2, uint32_t a3,
                                        uint32_t b0, uint32_t b1) {
    asm volatile(
        "mma.sync.aligned.m16n8k16.row.col.f32.f16.f16.f32 "
        "{%0,%1,%2,%3}, {%4,%5,%6,%7}, {%8,%9}, {%0,%1,%2,%3};"
        : "+f"(d[0]), "+f"(d[1]), "+f"(d[2]), "+f"(d[3])
        : "r"(a0), "r"(a1), "r"(a2), "r"(a3), "r"(b0), "r"(b1));
}

__device__ __forceinline__ void ldsm_x4(uint32_t& r0, uint32_t& r1,
                                        uint32_t& r2, uint32_t& r3, uint32_t addr) {
    asm volatile("ldmatrix.sync.aligned.m8n8.x4.shared.b16 {%0,%1,%2,%3}, [%4];"
                 : "=r"(r0), "=r"(r1), "=r"(r2), "=r"(r3) : "r"(addr));
}

__device__ __forceinline__ uint32_t smem_u32(const void* p) {
    uint32_t a;
    asm("{ .reg .u64 t; cvta.to.shared.u64 t, %1; cvt.u32.u64 %0, t; }" : "=r"(a) : "l"(p));
    return a;
}

__device__ __forceinline__ void cp_async16(uint32_t dst, const void* src) {
    asm volatile("cp.async.cg.shared.global [%0], [%1], 16;" :: "r"(dst), "l"(src) : "memory");
}
#define CP_COMMIT() asm volatile("cp.async.commit_group;" ::: "memory")
#define CP_WAIT0()  asm volatile("cp.async.wait_group 0;" ::: "memory")
#define CP_WAIT1()  asm volatile("cp.async.wait_group 1;" ::: "memory")

// attn: stage K tile (128 keys x 64 half dims, smem row stride 72 halves)
__device__ __forceinline__ void stage_k(uint32_t dstbase, const __half* src, int tid) {
    #pragma unroll
    for (int i = tid; i < 1024; i += 256) {
        int r = i >> 3, c8 = (i & 7) << 3;
        cp_async16(dstbase + (uint32_t)(r * 144 + c8 * 2), src + r * 64 + c8);
    }
}
// attn: stage V tile (transposed: 64 dim-rows x 128 half keys, stride 136 halves)
__device__ __forceinline__ void stage_v(uint32_t dstbase, const __half* srcT, int tid) {
    #pragma unroll
    for (int i = tid; i < 1024; i += 256) {
        int r = i >> 4, c16 = (i & 15) << 3;
        cp_async16(dstbase + (uint32_t)(r * 272 + c16 * 2), srcT + (size_t)r * NTOK + c16);
    }
}
// gemm: stage 128x64 half tile from 512-stride row-major, smem stride 72 halves
__device__ __forceinline__ void stage_h(uint32_t dstbase, const __half* src, int tid) {
    #pragma unroll
    for (int t = 0; t < 4; t++) {
        int i = tid + t * 256;
        int r = i >> 3, c8 = (i & 7) << 3;
        cp_async16(dstbase + (uint32_t)(r * 144 + c8 * 2), src + (size_t)r * 512 + c8);
    }
}

// ============================================================
// code_mod = LayerNorm((w_c @ code).T) * g + b, both variants
// ============================================================
__global__ __launch_bounds__(512) void code_mod_kernel(
    const float* __restrict__ wc, const float* __restrict__ code,
    const float* __restrict__ gq, const float* __restrict__ bq,
    const float* __restrict__ gp, const float* __restrict__ bp)
{
    int d = threadIdx.x;
    float t[NFV] = {0.f, 0.f, 0.f, 0.f};
    for (int k = 0; k < 128; k++) {
        float w = wc[d * 128 + k];
        #pragma unroll
        for (int f = 0; f < NFV; f++) t[f] += w * code[k * NFV + f];
    }
    __shared__ float red[512];
    float gqd = gq[d], bqd = bq[d], gpd = gp[d], bpd = bp[d];
    for (int f = 0; f < NFV; f++) {
        red[d] = t[f];
        __syncthreads();
        for (int s = 256; s > 0; s >>= 1) {
            if (d < s) red[d] += red[d + s];
            __syncthreads();
        }
        float mu = red[0] * (1.f / 512.f);
        __syncthreads();
        float dv = t[f] - mu;
        red[d] = dv * dv;
        __syncthreads();
        for (int s = 256; s > 0; s >>= 1) {
            if (d < s) red[d] += red[d + s];
            __syncthreads();
        }
        float var = red[0] * (1.f / 512.f);
        __syncthreads();
        float nrm = dv * rsqrtf(var + 1e-5f);
        g_cm[0][f][d] = nrm * gqd + bqd;
        g_cm[1][f][d] = nrm * gpd + bpd;
    }
}

// fused prep: callT (blocks 0..3), weight convert (4..1027), xh (1028..3075)
__global__ __launch_bounds__(256) void prep_all(
    const float* __restrict__ cin, const float* __restrict__ Wq,
    const float* __restrict__ Wp, const float* __restrict__ x)
{
    int b = blockIdx.x, tid = threadIdx.x;
    if (b < 4) {
        int c = b * 256 + tid;
        float4 v = make_float4(cin[c], cin[NTOK + c], cin[2 * NTOK + c], cin[3 * NTOK + c]);
        *(float4*)&g_callT[c * 4] = v;
    } else if (b < 1028) {
        int i = (b - 4) * 256 + tid;
        if (i < 196608) {
            float4 v = *(const float4*)(Wq + (size_t)i * 4);
            __half* d = g_wq_h + (size_t)i * 4;
            *(__half2*)(d)     = __floats2half2_rn(v.x, v.y);
            *(__half2*)(d + 2) = __floats2half2_rn(v.z, v.w);
        } else {
            int j = i - 196608;
            float4 v = *(const float4*)(Wp + (size_t)j * 4);
            __half* d = g_wp_h + (size_t)j * 4;
            *(__half2*)(d)     = __floats2half2_rn(v.x, v.y);
            *(__half2*)(d + 2) = __floats2half2_rn(v.z, v.w);
        }
    } else {
        int j = b - 1028;
        int f = j >> 9;
        int i = (j & 511) * 256 + tid;
        int n = i >> 7, c4 = (i & 127) << 2;
        float4 v = *(const float4*)(x + (size_t)n * 512 + c4);
        float4 s = *(const float4*)(&g_cm[0][f][c4]);
        __half* dst = g_xh + (size_t)f * NTOK * DINV + (size_t)n * 512 + c4;
        *(__half2*)(dst)     = __floats2half2_rn(v.x * s.x, v.y * s.y);
        *(__half2*)(dst + 2) = __floats2half2_rn(v.z * s.z, v.w * s.w);
    }
}

// ============================================================
// fp16 GEMM, ldmatrix operand feeding
// ============================================================
#define GH_BYTES (36864 * 2 + 512)

template <int MODE>
__global__ __launch_bounds__(256, 2) void gemm_h(
    const float* __restrict__ bias, float* __restrict__ Out)
{
    extern __shared__ __half smh[];
    float* sbias = (float*)(smh + 36864);
    const int f   = blockIdx.z;
    const int bm0 = blockIdx.y * 128;
    const int bn0 = blockIdx.x * 128;
    const int tid = threadIdx.x;
    const int warp = tid >> 5, lane = tid & 31;
    const int gid = lane >> 2, tig = lane & 3;
    const int wm = warp >> 2, wn = warp & 3;

    // ldmatrix per-lane offsets
    const int rA = (lane & 7) + (((lane >> 3) & 1) << 3);
    const int kA = (lane >> 4) << 3;
    const uint32_t aofs = (uint32_t)(rA * 144 + kA * 2);
    const int rB = (lane & 7) + ((lane >> 4) << 3);
    const int kB = ((lane >> 3) & 1) << 3;
    const uint32_t bofs = (uint32_t)(rB * 144 + kB * 2);

    const __half* A  = (MODE == 0 ? g_xh : g_yh) + (size_t)f * NTOK * DINV + (size_t)bm0 * 512;
    const __half* Bw = (MODE == 0 ? g_wq_h : g_wp_h) + (size_t)bn0 * 512;

    uint32_t sb = smem_u32(smh);
    uint32_t Ab[2] = {sb, sb + 9216 * 2};
    uint32_t Bb[2] = {sb + 18432 * 2, sb + 27648 * 2};

    if (tid < 128) sbias[tid] = bias[bn0 + tid];

    stage_h(Ab[0], A, tid);
    stage_h(Bb[0], Bw, tid);
    CP_COMMIT();

    float d[4][4][4];
    #pragma unroll
    for (int mt = 0; mt < 4; mt++)
        #pragma unroll
        for (int nt = 0; nt < 4; nt++)
            #pragma unroll
            for (int q = 0; q < 4; q++) d[mt][nt][q] = 0.f;

    for (int c = 0; c < 8; c++) {
        if (c < 7) {
            stage_h(Ab[(c + 1) & 1], A + (c + 1) * 64, tid);
            stage_h(Bb[(c + 1) & 1], Bw + (c + 1) * 64, tid);
            CP_COMMIT();
            CP_WAIT1();
        } else {
            CP_WAIT0();
        }
        __syncthreads();
        uint32_t atile = Ab[c & 1];
        uint32_t btile = Bb[c & 1];
        #pragma unroll
        for (int kk = 0; kk < 4; kk++) {
            uint32_t aa[4][4], bb[4][2];
            #pragma unroll
            for (int mt = 0; mt < 4; mt++)
                ldsm_x4(aa[mt][0], aa[mt][1], aa[mt][2], aa[mt][3],
                        atile + (uint32_t)((wm * 64 + mt * 16) * 144 + kk * 32) + aofs);
            #pragma unroll
            for (int ntp = 0; ntp < 2; ntp++)
                ldsm_x4(bb[ntp * 2][0], bb[ntp * 2][1], bb[ntp * 2 + 1][0], bb[ntp * 2 + 1][1],
                        btile + (uint32_t)((wn * 32 + ntp * 16) * 144 + kk * 32) + bofs);
            #pragma unroll
            for (int mt = 0; mt < 4; mt++)
                #pragma unroll
                for (int nt = 0; nt < 4; nt++)
                    mma_f16(d[mt][nt], aa[mt][0], aa[mt][1], aa[mt][2], aa[mt][3],
                            bb[nt][0], bb[nt][1]);
        }
        __syncthreads();
    }

    if (MODE == 1) {
        float* outp = Out + (size_t)f * NTOK * DINV;
        #pragma unroll
        for (int mt = 0; mt < 4; mt++) {
            int m0 = bm0 + wm * 64 + mt * 16 + gid;
            #pragma unroll
            for (int nt = 0; nt < 4; nt++) {
                int jl = wn * 32 + nt * 8 + tig * 2;
                float b0 = sbias[jl], b1 = sbias[jl + 1];
                float2 v0 = {d[mt][nt][0] + b0, d[mt][nt][1] + b1};
                float2 v1 = {d[mt][nt][2] + b0, d[mt][nt][3] + b1};
                *(float2*)(outp + (size_t)m0 * 512 + bn0 + jl)       = v0;
                *(float2*)(outp + (size_t)(m0 + 8) * 512 + bn0 + jl) = v1;
            }
        }
    } else if (bn0 < 1024) {
        int jb = bn0 + wn * 32;
        int tt = jb >> 9;
        int h  = (jb >> 6) & 7;
        int db = jb & 63;
        float mul = (tt == 0) ? 0.125f : 1.0f;
        __half* base = (tt == 0 ? g_qh : g_kh) + (size_t)((h * NFV + f) * NTOK) * HDV;
        #pragma unroll
        for (int mt = 0; mt < 4; mt++) {
            int m0 = bm0 + wm * 64 + mt * 16 + gid;
            #pragma unroll
            for (int nt = 0; nt < 4; nt++) {
                int jl = wn * 32 + nt * 8 + tig * 2;
                int dc = db + nt * 8 + tig * 2;
                float b0 = sbias[jl], b1 = sbias[jl + 1];
                __half2 h0 = __floats2half2_rn((d[mt][nt][0] + b0) * mul,
                                               (d[mt][nt][1] + b1) * mul);
                __half2 h1 = __floats2half2_rn((d[mt][nt][2] + b0) * mul,
                                               (d[mt][nt][3] + b1) * mul);
                *(__half2*)(base + (size_t)m0 * HDV + dc)       = h0;
                *(__half2*)(base + (size_t)(m0 + 8) * HDV + dc) = h1;
            }
        }
    } else {
        __syncthreads();
        __half* T = smh;
        #pragma unroll
        for (int mt = 0; mt < 4; mt++) {
            int mloc = wm * 64 + mt * 16 + gid;
            #pragma unroll
            for (int nt = 0; nt < 4; nt++) {
                int jl = wn * 32 + nt * 8 + tig * 2;
                float b0 = sbias[jl], b1 = sbias[jl + 1];
                T[jl * 136 + mloc]           = __float2half_rn(d[mt][nt][0] + b0);
                T[(jl + 1) * 136 + mloc]     = __float2half_rn(d[mt][nt][1] + b1);
                T[jl * 136 + mloc + 8]       = __float2half_rn(d[mt][nt][2] + b0);
                T[(jl + 1) * 136 + mloc + 8] = __float2half_rn(d[mt][nt][3] + b1);
            }
        }
        __syncthreads();
        int vbase = bn0 - 1024;
        #pragma unroll
        for (int t = 0; t < 8; t++) {
            int i = tid + t * 256;
            int jl = i >> 4, c8 = (i & 15) << 3;
            uint4 v = *(uint4*)&T[jl * 136 + c8];
            int vcol = vbase + jl;
            __half* dst = g_vT + (size_t)(((vcol >> 6) * NFV + f) * HDV + (vcol & 63)) * NTOK
                          + bm0 + c8;
            *(uint4*)dst = v;
        }
    }
}

// ============================================================
// attention: flash-style, 64-row blocks, 256 threads, 2 blocks/SM.
// ldmatrix fragment feeding; no clamps; inv1 folded into compat coeffs.
// ============================================================
#define AB_K0   0
#define AB_V0   18432
#define AB_K1   35840
#define AB_V1   54272
#define AB_Q    71680
#define AB_CROW 80896
#define AB_INV1 81920
#define AB_LRED 82176
#define AB_INV2 82688
#define ATTN_SMEM_BYTES 82944

__global__ __launch_bounds__(256, 2) void attn_kernel(const float* __restrict__ cin)
{
    extern __shared__ char smc[];
    __half* Qs    = (__half*)(smc + AB_Q);
    float*  crow  = (float*)(smc + AB_CROW);
    float*  inv1s = (float*)(smc + AB_INV1);
    float*  lred  = (float*)(smc + AB_LRED);
    float*  inv2s = (float*)(smc + AB_INV2);
    float*  ored  = (float*)smc;

    const int tid = threadIdx.x;
    const int warp = tid >> 5, lane = tid & 31;
    const int gid = lane >> 2, tig = lane & 3;
    const int n0 = blockIdx.x * 64;
    const int hf = blockIdx.y;
    const int h = hf >> 2, f = hf & 3;
    const size_t hb = (size_t)hf * NTOK * HDV;

    // ldmatrix per-lane offsets (B-type fragments)
    const int rB = (lane & 7) + ((lane >> 4) << 3);
    const int kB = ((lane >> 3) & 1) << 3;
    const uint32_t bofsK = (uint32_t)(rB * 144 + kB * 2);
    const uint32_t bofsV = (uint32_t)(rB * 272 + kB * 2);

    uint32_t sb = smem_u32(smc);
    uint32_t kaddr[2] = {sb + AB_K0, sb + AB_K1};
    uint32_t vaddr[2] = {sb + AB_V0, sb + AB_V1};
    const __half* Kp  = g_kh + hb;
    const __half* VTp = g_vT + (size_t)hf * HDV * NTOK;

    stage_k(kaddr[0], Kp, tid);         CP_COMMIT();
    stage_k(kaddr[1], Kp + 8192, tid);  CP_COMMIT();

    #pragma unroll
    for (int i = tid; i < 512; i += 256) {
        int r = i >> 3, c8 = (i & 7) << 3;
        uint4 v = *(const uint4*)(g_qh + hb + (size_t)(n0 + r) * HDV + c8);
        *(uint4*)((char*)Qs + r * 144 + c8 * 2) = v;
    }
    crow[tid] = cin[(tid >> 6) * NTOK + n0 + (tid & 63)];
    __syncthreads();

    const int rg  = warp & 3;            // 4 row groups of 16
    const int cgr = warp >> 2;           // 2 col groups of 64
    const int r0 = rg * 16 + gid, r1 = r0 + 8;

    uint32_t aq0[4], aq1[4], aq2[4], aq3[4];
    {
        const __half* q0 = Qs + r0 * 72;
        const __half* q1 = Qs + r1 * 72;
        #pragma unroll
        for (int kk = 0; kk < 4; kk++) {
            aq0[kk] = *(const uint32_t*)&q0[kk * 16 + tig * 2];
            aq1[kk] = *(const uint32_t*)&q1[kk * 16 + tig * 2];
            aq2[kk] = *(const uint32_t*)&q0[kk * 16 + tig * 2 + 8];
            aq3[kk] = *(const uint32_t*)&q1[kk * 16 + tig * 2 + 8];
        }
    }
    float cr0[4], cr1[4];
    #pragma unroll
    for (int ff = 0; ff < 4; ff++) { cr0[ff] = crow[ff * 64 + r0]; cr1[ff] = crow[ff * 64 + r1]; }

    // ---- pass 1: s1 = sum exp(s) ----
    float l0 = 0.f, l1 = 0.f;
    for (int mt = 0; mt < 8; mt++) {
        if (mt < 6) { CP_WAIT1(); } else { CP_WAIT0(); }
        __syncthreads();
        uint32_t kb_base = kaddr[mt & 1] + (uint32_t)(cgr * 64 * 144);
        #pragma unroll
        for (int ntp = 0; ntp < 4; ntp++) {
            float s4a[4] = {0.f, 0.f, 0.f, 0.f};
            float s4b[4] = {0.f, 0.f, 0.f, 0.f};
            #pragma unroll
            for (int kk = 0; kk < 4; kk++) {
                uint32_t b0, b1, b2, b3;
                ldsm_x4(b0, b1, b2, b3,
                        kb_base + (uint32_t)(ntp * 16 * 144 + kk * 32) + bofsK);
                mma_f16(s4a, aq0[kk], aq1[kk], aq2[kk], aq3[kk], b0, b1);
                mma_f16(s4b, aq0[kk], aq1[kk], aq2[kk], aq3[kk], b2, b3);
            }
            l0 += (__expf(s4a[0]) + __expf(s4a[1])) + (__expf(s4b[0]) + __expf(s4b[1]));
            l1 += (__expf(s4a[2]) + __expf(s4a[3])) + (__expf(s4b[2]) + __expf(s4b[3]));
        }
        __syncthreads();
        if (mt < 6) {
            stage_k(kaddr[mt & 1], Kp + (size_t)(mt + 2) * 8192, tid);
            CP_COMMIT();
        }
    }
    l0 += __shfl_xor_sync(0xffffffffu, l0, 1);
    l0 += __shfl_xor_sync(0xffffffffu, l0, 2);
    l1 += __shfl_xor_sync(0xffffffffu, l1, 1);
    l1 += __shfl_xor_sync(0xffffffffu, l1, 2);
    if (tig == 0) { lred[cgr * 64 + r0] = l0; lred[cgr * 64 + r1] = l1; }

    // pass-2 prologue
    stage_k(kaddr[0], Kp, tid); stage_v(vaddr[0], VTp, tid); CP_COMMIT();
    __syncthreads();
    stage_k(kaddr[1], Kp + 8192, tid); stage_v(vaddr[1], VTp + 128, tid); CP_COMMIT();
    if (tid < 64) inv1s[tid] = 1.f / (lred[tid] + lred[64 + tid]);
    __syncthreads();

    // fold inv1 into compat row coefficients
    {
        float i1r0 = inv1s[r0], i1r1 = inv1s[r1];
        #pragma unroll
        for (int ff = 0; ff < 4; ff++) { cr0[ff] *= i1r0; cr1[ff] *= i1r1; }
    }
    const float4* cT = (const float4*)g_callT;

    // ---- pass 2: recompute scores, p in regs, PV ----
    float o[8][4];
    #pragma unroll
    for (int dt = 0; dt < 8; dt++)
        #pragma unroll
        for (int q = 0; q < 4; q++) o[dt][q] = 0.f;
    float s2l0 = 0.f, s2l1 = 0.f;

    for (int mt = 0; mt < 8; mt++) {
        if (mt < 6) { CP_WAIT1(); } else { CP_WAIT0(); }
        __syncthreads();
        uint32_t kb_base = kaddr[mt & 1] + (uint32_t)(cgr * 64 * 144);
        uint32_t vb_base = vaddr[mt & 1] + (uint32_t)(cgr * 64 * 2);

        uint32_t ph0[8], ph1[8];
        #pragma unroll
        for (int ntp = 0; ntp < 4; ntp++) {
            float s4a[4] = {0.f, 0.f, 0.f, 0.f};
            float s4b[4] = {0.f, 0.f, 0.f, 0.f};
            #pragma unroll
            for (int kk = 0; kk < 4; kk++) {
                uint32_t b0, b1, b2, b3;
                ldsm_x4(b0, b1, b2, b3,
                        kb_base + (uint32_t)(ntp * 16 * 144 + kk * 32) + bofsK);
                mma_f16(s4a, aq0[kk], aq1[kk], aq2[kk], aq3[kk], b0, b1);
                mma_f16(s4b, aq0[kk], aq1[kk], aq2[kk], aq3[kk], b2, b3);
            }
            #pragma unroll
            for (int half_nt = 0; half_nt < 2; half_nt++) {
                int nt = ntp * 2 + half_nt;
                const float* s4 = half_nt ? s4b : s4a;
                int c = mt * 128 + cgr * 64 + nt * 8 + tig * 2;
                float4 w0 = cT[c], w1 = cT[c + 1];
                float cA = cr0[0] * w0.x + cr0[1] * w0.y + cr0[2] * w0.z + cr0[3] * w0.w;
                float cB = cr0[0] * w1.x + cr0[1] * w1.y + cr0[2] * w1.z + cr0[3] * w1.w;
                float cC = cr1[0] * w0.x + cr1[1] * w0.y + cr1[2] * w0.z + cr1[3] * w0.w;
                float cD = cr1[0] * w1.x + cr1[1] * w1.y + cr1[2] * w1.z + cr1[3] * w1.w;
                float p00 = __expf(__expf(s4[0]) * cA);
                float p01 = __expf(__expf(s4[1]) * cB);
                float p10 = __expf(__expf(s4[2]) * cC);
                float p11 = __expf(__expf(s4[3]) * cD);
                s2l0 += p00 + p01;
                s2l1 += p10 + p11;
                __half2 hA = __floats2half2_rn(p00, p01);
                __half2 hB = __floats2half2_rn(p10, p11);
                ph0[nt] = *(uint32_t*)&hA;
                ph1[nt] = *(uint32_t*)&hB;
            }
        }
        #pragma unroll
        for (int kb = 0; kb < 4; kb++) {
            uint32_t a0 = ph0[2 * kb], a1 = ph1[2 * kb];
            uint32_t a2 = ph0[2 * kb + 1], a3 = ph1[2 * kb + 1];
            #pragma unroll
            for (int dtp = 0; dtp < 4; dtp++) {
                uint32_t v0, v1, v2, v3;
                ldsm_x4(v0, v1, v2, v3,
                        vb_base + (uint32_t)(dtp * 16 * 272 + kb * 32) + bofsV);
                mma_f16(o[dtp * 2],     a0, a1, a2, a3, v0, v1);
                mma_f16(o[dtp * 2 + 1], a0, a1, a2, a3, v2, v3);
            }
        }
        __syncthreads();
        if (mt < 6) {
            stage_k(kaddr[mt & 1], Kp + (size_t)(mt + 2) * 8192, tid);
            stage_v(vaddr[mt & 1], VTp + (mt + 2) * 128, tid);
            CP_COMMIT();
        }
    }

    // s2 reduce
    s2l0 += __shfl_xor_sync(0xffffffffu, s2l0, 1);
    s2l0 += __shfl_xor_sync(0xffffffffu, s2l0, 2);
    s2l1 += __shfl_xor_sync(0xffffffffu, s2l1, 1);
    s2l1 += __shfl_xor_sync(0xffffffffu, s2l1, 2);
    if (tig == 0) { lred[cgr * 64 + r0] = s2l0; lred[cgr * 64 + r1] = s2l1; }
    __syncthreads();
    if (tid < 64) inv2s[tid] = 1.f / (lred[tid] + lred[64 + tid]);
    #pragma unroll
    for (int dt = 0; dt < 8; dt++) {
        float* dst0 = ored + cgr * 4224 + r0 * 66 + dt * 8 + tig * 2;
        float* dst1 = ored + cgr * 4224 + r1 * 66 + dt * 8 + tig * 2;
        dst0[0] = o[dt][0]; dst0[1] = o[dt][1];
        dst1[0] = o[dt][2]; dst1[1] = o[dt][3];
    }
    __syncthreads();

    const float* cm1p = &g_cm[1][f][h * 64];
    #pragma unroll
    for (int k = 0; k < 16; k++) {
        int t = tid + k * 256;
        int row = t >> 6, dim = t & 63;
        float v = ored[row * 66 + dim] + ored[4224 + row * 66 + dim];
        v *= inv2s[row] * cm1p[dim];
        g_yh[(size_t)f * NTOK * DINV + (size_t)(n0 + row) * DINV + h * 64 + dim] =
            __float2half_rn(v);
    }
}

// ============================================================
extern "C" void kernel_launch(void* const* d_in, const int* in_sizes, int n_in,
                              void* d_out, int out_size)
{
    const float* x      = (const float*)d_in[0];
    const float* compat = (const float*)d_in[1];
    const float* code   = (const float*)d_in[2];
    const float* wc     = (const float*)d_in[3];
    const float* Wqkv   = (const float*)d_in[4];
    const float* bqkv   = (const float*)d_in[5];
    const float* Wproj  = (const float*)d_in[6];
    const float* bproj  = (const float*)d_in[7];
    const float* lnqg   = (const float*)d_in[8];
    const float* lnqb   = (const float*)d_in[9];
    const float* lnpg   = (const float*)d_in[10];
    const float* lnpb   = (const float*)d_in[11];
    float* out = (float*)d_out;

    cudaFuncSetAttribute(attn_kernel,
                         cudaFuncAttributeMaxDynamicSharedMemorySize, ATTN_SMEM_BYTES);
    cudaFuncSetAttribute(gemm_h<0>,
                         cudaFuncAttributeMaxDynamicSharedMemorySize, GH_BYTES);
    cudaFuncSetAttribute(gemm_h<1>,
                         cudaFuncAttributeMaxDynamicSharedMemorySize, GH_BYTES);

    code_mod_kernel<<<1, 512>>>(wc, code, lnqg, lnqb, lnpg, lnpb);
    prep_all<<<3076, 256>>>(compat, Wqkv, Wproj, x);
    gemm_h<0><<<dim3(12, 8, 4), 256, GH_BYTES>>>(bqkv, nullptr);
    attn_kernel<<<dim3(16, 32), 256, ATTN_SMEM_BYTES>>>(compat);
    gemm_h<1><<<dim3(4, 8, 4), 256, GH_BYTES>>>(bproj, out);
}

// round 12
// speedup vs baseline: 2.2835x; 1.0743x over previous
#include <cuda_runtime.h>
#include <cuda_fp16.h>
#include <math.h>
#include <stdint.h>

#define NTOK 1024
#define DINV 512
#define NFV  4
#define NHV  8
#define HDV  64

#define LOG2E 1.44269504f

// -------- scratch (device globals; no allocation allowed) --------
__device__ float  g_cm[2][NFV][DINV];                // [qkv|proj][f][d]
__device__ __half g_xh[NFV * NTOK * DINV];           // x * cm0, fp16
__device__ __half g_wq_h[3 * DINV * DINV];           // W_qkv fp16
__device__ __half g_wp_h[DINV * DINV];               // W_proj fp16
__device__ __half g_qh[NHV * NFV * NTOK * HDV];      // [hf][n][d], scaled hd^-0.5 * log2e
__device__ __half g_kh[NHV * NFV * NTOK * HDV];      // [hf][n][d]
__device__ __half g_vT[NHV * NFV * HDV * NTOK];      // [hf][d][n] transposed
__device__ __half g_yh[NFV * NTOK * DINV];           // yhat * cm1, fp16
__device__ __half g_callTh[NTOK * 8];                // [c][f-pad8] half compat table

// ============================================================
// helpers
// ============================================================
__device__ __forceinline__ float ex2(float x) {
    float r;
    asm("ex2.approx.f32 %0, %1;" : "=f"(r) : "f"(x));
    return r;
}

__device__ __forceinline__ void mma_f16(float* d, uint32_t a0, uint32_t a1,
                                        uint32_t a2, uint32_t a3,
                                        uint32_t b0, uint32_t b1) {
    asm volatile(
        "mma.sync.aligned.m16n8k16.row.col.f32.f16.f16.f32 "
        "{%0,%1,%2,%3}, {%4,%5,%6,%7}, {%8,%9}, {%0,%1,%2,%3};"
        : "+f"(d[0]), "+f"(d[1]), "+f"(d[2]), "+f"(d[3])
        : "r"(a0), "r"(a1), "r"(a2), "r"(a3), "r"(b0), "r"(b1));
}

__device__ __forceinline__ void mma_f16_k8(float* d, uint32_t a0, uint32_t a1, uint32_t b0) {
    asm volatile(
        "mma.sync.aligned.m16n8k8.row.col.f32.f16.f16.f32 "
        "{%0,%1,%2,%3}, {%4,%5}, {%6}, {%0,%1,%2,%3};"
        : "+f"(d[0]), "+f"(d[1]), "+f"(d[2]), "+f"(d[3])
        : "r"(a0), "r"(a1), "r"(b0));
}

__device__ __forceinline__ void ldsm_x4(uint32_t& r0, uint32_t& r1,
                                        uint32_t& r2, uint32_t& r3, uint32_t addr) {
    asm volatile("ldmatrix.sync.aligned.m8n8.x4.shared.b16 {%0,%1,%2,%3}, [%4];"
                 : "=r"(r0), "=r"(r1), "=r"(r2), "=r"(r3) : "r"(addr));
}

__device__ __forceinline__ uint32_t smem_u32(const void* p) {
    uint32_t a;
    asm("{ .reg .u64 t; cvta.to.shared.u64 t, %1; cvt.u32.u64 %0, t; }" : "=r"(a) : "l"(p));
    return a;
}

__device__ __forceinline__ void cp_async16(uint32_t dst, const void* src) {
    asm volatile("cp.async.cg.shared.global [%0], [%1], 16;" :: "r"(dst), "l"(src) : "memory");
}
#define CP_COMMIT() asm volatile("cp.async.commit_group;" ::: "memory")
#define CP_WAIT0()  asm volatile("cp.async.wait_group 0;" ::: "memory")
#define CP_WAIT1()  asm volatile("cp.async.wait_group 1;" ::: "memory")

// attn: stage K tile (128 keys x 64 half dims, smem row stride 72 halves)
__device__ __forceinline__ void stage_k(uint32_t dstbase, const __half* src, int tid) {
    #pragma unroll
    for (int i = tid; i < 1024; i += 256) {
        int r = i >> 3, c8 = (i & 7) << 3;
        cp_async16(dstbase + (uint32_t)(r * 144 + c8 * 2), src + r * 64 + c8);
    }
}
// attn: stage V tile (transposed: 64 dim-rows x 128 half keys, stride 136 halves)
__device__ __forceinline__ void stage_v(uint32_t dstbase, const __half* srcT, int tid) {
    #pragma unroll
    for (int i = tid; i < 1024; i += 256) {
        int r = i >> 4, c16 = (i & 15) << 3;
        cp_async16(dstbase + (uint32_t)(r * 272 + c16 * 2), srcT + (size_t)r * NTOK + c16);
    }
}
// gemm: stage 128x64 half tile from 512-stride row-major, smem stride 72 halves
__device__ __forceinline__ void stage_h(uint32_t dstbase, const __half* src, int tid) {
    #pragma unroll
    for (int t = 0; t < 4; t++) {
        int i = tid + t * 256;
        int r = i >> 3, c8 = (i & 7) << 3;
        cp_async16(dstbase + (uint32_t)(r * 144 + c8 * 2), src + (size_t)r * 512 + c8);
    }
}

// ============================================================
// code_mod = LayerNorm((w_c @ code).T) * g + b, both variants
// ============================================================
__global__ __launch_bounds__(512) void code_mod_kernel(
    const float* __restrict__ wc, const float* __restrict__ code,
    const float* __restrict__ gq, const float* __restrict__ bq,
    const float* __restrict__ gp, const float* __restrict__ bp)
{
    int d = threadIdx.x;
    float t[NFV] = {0.f, 0.f, 0.f, 0.f};
    for (int k = 0; k < 128; k++) {
        float w = wc[d * 128 + k];
        #pragma unroll
        for (int f = 0; f < NFV; f++) t[f] += w * code[k * NFV + f];
    }
    __shared__ float red[512];
    float gqd = gq[d], bqd = bq[d], gpd = gp[d], bpd = bp[d];
    for (int f = 0; f < NFV; f++) {
        red[d] = t[f];
        __syncthreads();
        for (int s = 256; s > 0; s >>= 1) {
            if (d < s) red[d] += red[d + s];
            __syncthreads();
        }
        float mu = red[0] * (1.f / 512.f);
        __syncthreads();
        float dv = t[f] - mu;
        red[d] = dv * dv;
        __syncthreads();
        for (int s = 256; s > 0; s >>= 1) {
            if (d < s) red[d] += red[d + s];
            __syncthreads();
        }
        float var = red[0] * (1.f / 512.f);
        __syncthreads();
        float nrm = dv * rsqrtf(var + 1e-5f);
        g_cm[0][f][d] = nrm * gqd + bqd;
        g_cm[1][f][d] = nrm * gpd + bpd;
    }
}

// fused prep: callTh (blocks 0..3), weight convert (4..1027), xh (1028..3075)
__global__ __launch_bounds__(256) void prep_all(
    const float* __restrict__ cin, const float* __restrict__ Wq,
    const float* __restrict__ Wp, const float* __restrict__ x)
{
    int b = blockIdx.x, tid = threadIdx.x;
    if (b < 4) {
        int c = b * 256 + tid;
        __half2 w01 = __floats2half2_rn(cin[c], cin[NTOK + c]);
        __half2 w23 = __floats2half2_rn(cin[2 * NTOK + c], cin[3 * NTOK + c]);
        uint4 v;
        v.x = *(uint32_t*)&w01;
        v.y = *(uint32_t*)&w23;
        v.z = 0u; v.w = 0u;
        *(uint4*)&g_callTh[c * 8] = v;
    } else if (b < 1028) {
        int i = (b - 4) * 256 + tid;
        if (i < 196608) {
            float4 v = *(const float4*)(Wq + (size_t)i * 4);
            __half* d = g_wq_h + (size_t)i * 4;
            *(__half2*)(d)     = __floats2half2_rn(v.x, v.y);
            *(__half2*)(d + 2) = __floats2half2_rn(v.z, v.w);
        } else {
            int j = i - 196608;
            float4 v = *(const float4*)(Wp + (size_t)j * 4);
            __half* d = g_wp_h + (size_t)j * 4;
            *(__half2*)(d)     = __floats2half2_rn(v.x, v.y);
            *(__half2*)(d + 2) = __floats2half2_rn(v.z, v.w);
        }
    } else {
        int j = b - 1028;
        int f = j >> 9;
        int i = (j & 511) * 256 + tid;
        int n = i >> 7, c4 = (i & 127) << 2;
        float4 v = *(const float4*)(x + (size_t)n * 512 + c4);
        float4 s = *(const float4*)(&g_cm[0][f][c4]);
        __half* dst = g_xh + (size_t)f * NTOK * DINV + (size_t)n * 512 + c4;
        *(__half2*)(dst)     = __floats2half2_rn(v.x * s.x, v.y * s.y);
        *(__half2*)(dst + 2) = __floats2half2_rn(v.z * s.z, v.w * s.w);
    }
}

// ============================================================
// fp16 GEMM, ldmatrix operand feeding (q epilogue scaled by log2e)
// ============================================================
#define GH_BYTES (36864 * 2 + 512)

template <int MODE>
__global__ __launch_bounds__(256, 2) void gemm_h(
    const float* __restrict__ bias, float* __restrict__ Out)
{
    extern __shared__ __half smh[];
    float* sbias = (float*)(smh + 36864);
    const int f   = blockIdx.z;
    const int bm0 = blockIdx.y * 128;
    const int bn0 = blockIdx.x * 128;
    const int tid = threadIdx.x;
    const int warp = tid >> 5, lane = tid & 31;
    const int gid = lane >> 2, tig = lane & 3;
    const int wm = warp >> 2, wn = warp & 3;

    const int rA = (lane & 7) + (((lane >> 3) & 1) << 3);
    const int kA = (lane >> 4) << 3;
    const uint32_t aofs = (uint32_t)(rA * 144 + kA * 2);
    const int rB = (lane & 7) + ((lane >> 4) << 3);
    const int kB = ((lane >> 3) & 1) << 3;
    const uint32_t bofs = (uint32_t)(rB * 144 + kB * 2);

    const __half* A  = (MODE == 0 ? g_xh : g_yh) + (size_t)f * NTOK * DINV + (size_t)bm0 * 512;
    const __half* Bw = (MODE == 0 ? g_wq_h : g_wp_h) + (size_t)bn0 * 512;

    uint32_t sb = smem_u32(smh);
    uint32_t Ab[2] = {sb, sb + 9216 * 2};
    uint32_t Bb[2] = {sb + 18432 * 2, sb + 27648 * 2};

    if (tid < 128) sbias[tid] = bias[bn0 + tid];

    stage_h(Ab[0], A, tid);
    stage_h(Bb[0], Bw, tid);
    CP_COMMIT();

    float d[4][4][4];
    #pragma unroll
    for (int mt = 0; mt < 4; mt++)
        #pragma unroll
        for (int nt = 0; nt < 4; nt++)
            #pragma unroll
            for (int q = 0; q < 4; q++) d[mt][nt][q] = 0.f;

    for (int c = 0; c < 8; c++) {
        if (c < 7) {
            stage_h(Ab[(c + 1) & 1], A + (c + 1) * 64, tid);
            stage_h(Bb[(c + 1) & 1], Bw + (c + 1) * 64, tid);
            CP_COMMIT();
            CP_WAIT1();
        } else {
            CP_WAIT0();
        }
        __syncthreads();
        uint32_t atile = Ab[c & 1];
        uint32_t btile = Bb[c & 1];
        #pragma unroll
        for (int kk = 0; kk < 4; kk++) {
            uint32_t aa[4][4], bb[4][2];
            #pragma unroll
            for (int mt = 0; mt < 4; mt++)
                ldsm_x4(aa[mt][0], aa[mt][1], aa[mt][2], aa[mt][3],
                        atile + (uint32_t)((wm * 64 + mt * 16) * 144 + kk * 32) + aofs);
            #pragma unroll
            for (int ntp = 0; ntp < 2; ntp++)
                ldsm_x4(bb[ntp * 2][0], bb[ntp * 2][1], bb[ntp * 2 + 1][0], bb[ntp * 2 + 1][1],
                        btile + (uint32_t)((wn * 32 + ntp * 16) * 144 + kk * 32) + bofs);
            #pragma unroll
            for (int mt = 0; mt < 4; mt++)
                #pragma unroll
                for (int nt = 0; nt < 4; nt++)
                    mma_f16(d[mt][nt], aa[mt][0], aa[mt][1], aa[mt][2], aa[mt][3],
                            bb[nt][0], bb[nt][1]);
        }
        __syncthreads();
    }

    if (MODE == 1) {
        float* outp = Out + (size_t)f * NTOK * DINV;
        #pragma unroll
        for (int mt = 0; mt < 4; mt++) {
            int m0 = bm0 + wm * 64 + mt * 16 + gid;
            #pragma unroll
            for (int nt = 0; nt < 4; nt++) {
                int jl = wn * 32 + nt * 8 + tig * 2;
                float b0 = sbias[jl], b1 = sbias[jl + 1];
                float2 v0 = {d[mt][nt][0] + b0, d[mt][nt][1] + b1};
                float2 v1 = {d[mt][nt][2] + b0, d[mt][nt][3] + b1};
                *(float2*)(outp + (size_t)m0 * 512 + bn0 + jl)       = v0;
                *(float2*)(outp + (size_t)(m0 + 8) * 512 + bn0 + jl) = v1;
            }
        }
    } else if (bn0 < 1024) {
        int jb = bn0 + wn * 32;
        int tt = jb >> 9;
        int h  = (jb >> 6) & 7;
        int db = jb & 63;
        float mul = (tt == 0) ? (0.125f * LOG2E) : 1.0f;   // q in log2 domain
        __half* base = (tt == 0 ? g_qh : g_kh) + (size_t)((h * NFV + f) * NTOK) * HDV;
        #pragma unroll
        for (int mt = 0; mt < 4; mt++) {
            int m0 = bm0 + wm * 64 + mt * 16 + gid;
            #pragma unroll
            for (int nt = 0; nt < 4; nt++) {
                int jl = wn * 32 + nt * 8 + tig * 2;
                int dc = db + nt * 8 + tig * 2;
                float b0 = sbias[jl], b1 = sbias[jl + 1];
                __half2 h0 = __floats2half2_rn((d[mt][nt][0] + b0) * mul,
                                               (d[mt][nt][1] + b1) * mul);
                __half2 h1 = __floats2half2_rn((d[mt][nt][2] + b0) * mul,
                                               (d[mt][nt][3] + b1) * mul);
                *(__half2*)(base + (size_t)m0 * HDV + dc)       = h0;
                *(__half2*)(base + (size_t)(m0 + 8) * HDV + dc) = h1;
            }
        }
    } else {
        __syncthreads();
        __half* T = smh;
        #pragma unroll
        for (int mt = 0; mt < 4; mt++) {
            int mloc = wm * 64 + mt * 16 + gid;
            #pragma unroll
            for (int nt = 0; nt < 4; nt++) {
                int jl = wn * 32 + nt * 8 + tig * 2;
                float b0 = sbias[jl], b1 = sbias[jl + 1];
                T[jl * 136 + mloc]           = __float2half_rn(d[mt][nt][0] + b0);
                T[(jl + 1) * 136 + mloc]     = __float2half_rn(d[mt][nt][1] + b1);
                T[jl * 136 + mloc + 8]       = __float2half_rn(d[mt][nt][2] + b0);
                T[(jl + 1) * 136 + mloc + 8] = __float2half_rn(d[mt][nt][3] + b1);
            }
        }
        __syncthreads();
        int vbase = bn0 - 1024;
        #pragma unroll
        for (int t = 0; t < 8; t++) {
            int i = tid + t * 256;
            int jl = i >> 4, c8 = (i & 15) << 3;
            uint4 v = *(uint4*)&T[jl * 136 + c8];
            int vcol = vbase + jl;
            __half* dst = g_vT + (size_t)(((vcol >> 6) * NFV + f) * HDV + (vcol & 63)) * NTOK
                          + bm0 + c8;
            *(uint4*)dst = v;
        }
    }
}

// ============================================================
// attention: flash-style, 64-row blocks, 256 threads, 2 blocks/SM.
// compat via k8 MMA from smem half table; pure-EX2 exps (q in log2 domain).
// ============================================================
#define AB_K0   0
#define AB_V0   18432
#define AB_K1   35840
#define AB_V1   54272
#define AB_Q    71680
#define AB_CROW 80896
#define AB_INV1 81920
#define AB_LRED 82176
#define AB_INV2 82688
#define AB_WT   82944
#define ATTN_SMEM_BYTES 99328

__global__ __launch_bounds__(256, 2) void attn_kernel(const float* __restrict__ cin)
{
    extern __shared__ char smc[];
    __half* Qs    = (__half*)(smc + AB_Q);
    float*  crow  = (float*)(smc + AB_CROW);
    float*  inv1s = (float*)(smc + AB_INV1);
    float*  lred  = (float*)(smc + AB_LRED);
    float*  inv2s = (float*)(smc + AB_INV2);
    float*  ored  = (float*)smc;

    const int tid = threadIdx.x;
    const int warp = tid >> 5, lane = tid & 31;
    const int gid = lane >> 2, tig = lane & 3;
    const int n0 = blockIdx.x * 64;
    const int hf = blockIdx.y;
    const int h = hf >> 2, f = hf & 3;
    const size_t hb = (size_t)hf * NTOK * HDV;

    const int rB = (lane & 7) + ((lane >> 4) << 3);
    const int kB = ((lane >> 3) & 1) << 3;
    const uint32_t bofsK = (uint32_t)(rB * 144 + kB * 2);
    const uint32_t bofsV = (uint32_t)(rB * 272 + kB * 2);
    const int wrow = (lane & 7) + ((lane >> 3) << 3);    // 0..31 row within 4-tile group

    uint32_t sb = smem_u32(smc);
    uint32_t kaddr[2] = {sb + AB_K0, sb + AB_K1};
    uint32_t vaddr[2] = {sb + AB_V0, sb + AB_V1};
    uint32_t wt = sb + AB_WT;
    const __half* Kp  = g_kh + hb;
    const __half* VTp = g_vT + (size_t)hf * HDV * NTOK;

    // prologue: K0 + w-table in group A, K1 in group B
    stage_k(kaddr[0], Kp, tid);
    #pragma unroll
    for (int i = tid; i < 1024; i += 256)
        cp_async16(wt + (uint32_t)i * 16, g_callTh + i * 8);
    CP_COMMIT();
    stage_k(kaddr[1], Kp + 8192, tid);  CP_COMMIT();

    #pragma unroll
    for (int i = tid; i < 512; i += 256) {
        int r = i >> 3, c8 = (i & 7) << 3;
        uint4 v = *(const uint4*)(g_qh + hb + (size_t)(n0 + r) * HDV + c8);
        *(uint4*)((char*)Qs + r * 144 + c8 * 2) = v;
    }
    crow[tid] = cin[(tid >> 6) * NTOK + n0 + (tid & 63)];
    __syncthreads();

    const int rg  = warp & 3;            // 4 row groups of 16
    const int cgr = warp >> 2;           // 2 col groups of 64
    const int r0 = rg * 16 + gid, r1 = r0 + 8;

    uint32_t aq0[4], aq1[4], aq2[4], aq3[4];
    {
        const __half* q0 = Qs + r0 * 72;
        const __half* q1 = Qs + r1 * 72;
        #pragma unroll
        for (int kk = 0; kk < 4; kk++) {
            aq0[kk] = *(const uint32_t*)&q0[kk * 16 + tig * 2];
            aq1[kk] = *(const uint32_t*)&q1[kk * 16 + tig * 2];
            aq2[kk] = *(const uint32_t*)&q0[kk * 16 + tig * 2 + 8];
            aq3[kk] = *(const uint32_t*)&q1[kk * 16 + tig * 2 + 8];
        }
    }

    // ---- pass 1: s1 = sum exp(s)  (scores already in log2 domain) ----
    float l0 = 0.f, l1 = 0.f;
    for (int mt = 0; mt < 8; mt++) {
        if (mt < 6) { CP_WAIT1(); } else { CP_WAIT0(); }
        __syncthreads();
        uint32_t kb_base = kaddr[mt & 1] + (uint32_t)(cgr * 64 * 144);
        #pragma unroll
        for (int ntp = 0; ntp < 4; ntp++) {
            float s4a[4] = {0.f, 0.f, 0.f, 0.f};
            float s4b[4] = {0.f, 0.f, 0.f, 0.f};
            #pragma unroll
            for (int kk = 0; kk < 4; kk++) {
                uint32_t b0, b1, b2, b3;
                ldsm_x4(b0, b1, b2, b3,
                        kb_base + (uint32_t)(ntp * 16 * 144 + kk * 32) + bofsK);
                mma_f16(s4a, aq0[kk], aq1[kk], aq2[kk], aq3[kk], b0, b1);
                mma_f16(s4b, aq0[kk], aq1[kk], aq2[kk], aq3[kk], b2, b3);
            }
            l0 += (ex2(s4a[0]) + ex2(s4a[1])) + (ex2(s4b[0]) + ex2(s4b[1]));
            l1 += (ex2(s4a[2]) + ex2(s4a[3])) + (ex2(s4b[2]) + ex2(s4b[3]));
        }
        __syncthreads();
        if (mt < 6) {
            stage_k(kaddr[mt & 1], Kp + (size_t)(mt + 2) * 8192, tid);
            CP_COMMIT();
        }
    }
    l0 += __shfl_xor_sync(0xffffffffu, l0, 1);
    l0 += __shfl_xor_sync(0xffffffffu, l0, 2);
    l1 += __shfl_xor_sync(0xffffffffu, l1, 1);
    l1 += __shfl_xor_sync(0xffffffffu, l1, 2);
    if (tig == 0) { lred[cgr * 64 + r0] = l0; lred[cgr * 64 + r1] = l1; }

    // pass-2 prologue
    stage_k(kaddr[0], Kp, tid); stage_v(vaddr[0], VTp, tid); CP_COMMIT();
    __syncthreads();
    stage_k(kaddr[1], Kp + 8192, tid); stage_v(vaddr[1], VTp + 128, tid); CP_COMMIT();
    if (tid < 64) inv1s[tid] = 1.f / (lred[tid] + lred[64 + tid]);
    __syncthreads();

    // build compat A-fragment: rows scaled by inv1*log2e, half, f padded to 8
    uint32_t ca0u, ca1u;
    {
        float i1r0L = inv1s[r0] * LOG2E;
        float i1r1L = inv1s[r1] * LOG2E;
        __half2 a0, a1;
        if (tig < 2) {
            a0 = __floats2half2_rn(crow[(tig * 2) * 64 + r0] * i1r0L,
                                   crow[(tig * 2 + 1) * 64 + r0] * i1r0L);
            a1 = __floats2half2_rn(crow[(tig * 2) * 64 + r1] * i1r1L,
                                   crow[(tig * 2 + 1) * 64 + r1] * i1r1L);
        } else {
            a0 = __floats2half2_rn(0.f, 0.f);
            a1 = a0;
        }
        ca0u = *(uint32_t*)&a0;
        ca1u = *(uint32_t*)&a1;
    }

    // ---- pass 2: recompute scores, compat via k8 MMA, p in regs, PV ----
    float o[8][4];
    #pragma unroll
    for (int dt = 0; dt < 8; dt++)
        #pragma unroll
        for (int q = 0; q < 4; q++) o[dt][q] = 0.f;
    float s2l0 = 0.f, s2l1 = 0.f;

    for (int mt = 0; mt < 8; mt++) {
        if (mt < 6) { CP_WAIT1(); } else { CP_WAIT0(); }
        __syncthreads();
        uint32_t kb_base = kaddr[mt & 1] + (uint32_t)(cgr * 64 * 144);
        uint32_t vb_base = vaddr[mt & 1] + (uint32_t)(cgr * 64 * 2);

        // w-table fragments for this mt/cgr: 8 n8-tiles -> 2 ldsm.x4
        uint32_t bw[8];
        {
            int cbase = mt * 128 + cgr * 64;
            ldsm_x4(bw[0], bw[1], bw[2], bw[3], wt + (uint32_t)(cbase + wrow) * 16);
            ldsm_x4(bw[4], bw[5], bw[6], bw[7], wt + (uint32_t)(cbase + 32 + wrow) * 16);
        }

        uint32_t ph0[8], ph1[8];
        #pragma unroll
        for (int ntp = 0; ntp < 4; ntp++) {
            float s4a[4] = {0.f, 0.f, 0.f, 0.f};
            float s4b[4] = {0.f, 0.f, 0.f, 0.f};
            #pragma unroll
            for (int kk = 0; kk < 4; kk++) {
                uint32_t b0, b1, b2, b3;
                ldsm_x4(b0, b1, b2, b3,
                        kb_base + (uint32_t)(ntp * 16 * 144 + kk * 32) + bofsK);
                mma_f16(s4a, aq0[kk], aq1[kk], aq2[kk], aq3[kk], b0, b1);
                mma_f16(s4b, aq0[kk], aq1[kk], aq2[kk], aq3[kk], b2, b3);
            }
            float cc0[4] = {0.f, 0.f, 0.f, 0.f};
            float cc1[4] = {0.f, 0.f, 0.f, 0.f};
            mma_f16_k8(cc0, ca0u, ca1u, bw[ntp * 2]);
            mma_f16_k8(cc1, ca0u, ca1u, bw[ntp * 2 + 1]);

            float p00 = ex2(ex2(s4a[0]) * cc0[0]);
            float p01 = ex2(ex2(s4a[1]) * cc0[1]);
            float p10 = ex2(ex2(s4a[2]) * cc0[2]);
            float p11 = ex2(ex2(s4a[3]) * cc0[3]);
            float q00 = ex2(ex2(s4b[0]) * cc1[0]);
            float q01 = ex2(ex2(s4b[1]) * cc1[1]);
            float q10 = ex2(ex2(s4b[2]) * cc1[2]);
            float q11 = ex2(ex2(s4b[3]) * cc1[3]);
            s2l0 += (p00 + p01) + (q00 + q01);
            s2l1 += (p10 + p11) + (q10 + q11);
            __half2 hA = __floats2half2_rn(p00, p01);
            __half2 hB = __floats2half2_rn(p10, p11);
            __half2 hC = __floats2half2_rn(q00, q01);
            __half2 hD = __floats2half2_rn(q10, q11);
            ph0[ntp * 2]     = *(uint32_t*)&hA;
            ph1[ntp * 2]     = *(uint32_t*)&hB;
            ph0[ntp * 2 + 1] = *(uint32_t*)&hC;
            ph1[ntp * 2 + 1] = *(uint32_t*)&hD;
        }
        #pragma unroll
        for (int kb = 0; kb < 4; kb++) {
            uint32_t a0 = ph0[2 * kb], a1 = ph1[2 * kb];
            uint32_t a2 = ph0[2 * kb + 1], a3 = ph1[2 * kb + 1];
            #pragma unroll
            for (int dtp = 0; dtp < 4; dtp++) {
                uint32_t v0, v1, v2, v3;
                ldsm_x4(v0, v1, v2, v3,
                        vb_base + (uint32_t)(dtp * 16 * 272 + kb * 32) + bofsV);
                mma_f16(o[dtp * 2],     a0, a1, a2, a3, v0, v1);
                mma_f16(o[dtp * 2 + 1], a0, a1, a2, a3, v2, v3);
            }
        }
        __syncthreads();
        if (mt < 6) {
            stage_k(kaddr[mt & 1], Kp + (size_t)(mt + 2) * 8192, tid);
            stage_v(vaddr[mt & 1], VTp + (mt + 2) * 128, tid);
            CP_COMMIT();
        }
    }

    // s2 reduce
    s2l0 += __shfl_xor_sync(0xffffffffu, s2l0, 1);
    s2l0 += __shfl_xor_sync(0xffffffffu, s2l0, 2);
    s2l1 += __shfl_xor_sync(0xffffffffu, s2l1, 1);
    s2l1 += __shfl_xor_sync(0xffffffffu, s2l1, 2);
    if (tig == 0) { lred[cgr * 64 + r0] = s2l0; lred[cgr * 64 + r1] = s2l1; }
    __syncthreads();
    if (tid < 64) inv2s[tid] = 1.f / (lred[tid] + lred[64 + tid]);
    #pragma unroll
    for (int dt = 0; dt < 8; dt++) {
        float* dst0 = ored + cgr * 4224 + r0 * 66 + dt * 8 + tig * 2;
        float* dst1 = ored + cgr * 4224 + r1 * 66 + dt * 8 + tig * 2;
        dst0[0] = o[dt][0]; dst0[1] = o[dt][1];
        dst1[0] = o[dt][2]; dst1[1] = o[dt][3];
    }
    __syncthreads();

    const float* cm1p = &g_cm[1][f][h * 64];
    #pragma unroll
    for (int k = 0; k < 16; k++) {
        int t = tid + k * 256;
        int row = t >> 6, dim = t & 63;
        float v = ored[row * 66 + dim] + ored[4224 + row * 66 + dim];
        v *= inv2s[row] * cm1p[dim];
        g_yh[(size_t)f * NTOK * DINV + (size_t)(n0 + row) * DINV + h * 64 + dim] =
            __float2half_rn(v);
    }
}

// ============================================================
extern "C" void kernel_launch(void* const* d_in, const int* in_sizes, int n_in,
                              void* d_out, int out_size)
{
    const float* x      = (const float*)d_in[0];
    const float* compat = (const float*)d_in[1];
    const float* code   = (const float*)d_in[2];
    const float* wc     = (const float*)d_in[3];
    const float* Wqkv   = (const float*)d_in[4];
    const float* bqkv   = (const float*)d_in[5];
    const float* Wproj  = (const float*)d_in[6];
    const float* bproj  = (const float*)d_in[7];
    const float* lnqg   = (const float*)d_in[8];
    const float* lnqb   = (const float*)d_in[9];
    const float* lnpg   = (const float*)d_in[10];
    const float* lnpb   = (const float*)d_in[11];
    float* out = (float*)d_out;

    cudaFuncSetAttribute(attn_kernel,
                         cudaFuncAttributeMaxDynamicSharedMemorySize, ATTN_SMEM_BYTES);
    cudaFuncSetAttribute(gemm_h<0>,
                         cudaFuncAttributeMaxDynamicSharedMemorySize, GH_BYTES);
    cudaFuncSetAttribute(gemm_h<1>,
                         cudaFuncAttributeMaxDynamicSharedMemorySize, GH_BYTES);

    code_mod_kernel<<<1, 512>>>(wc, code, lnqg, lnqb, lnpg, lnpb);
    prep_all<<<3076, 256>>>(compat, Wqkv, Wproj, x);
    gemm_h<0><<<dim3(12, 8, 4), 256, GH_BYTES>>>(bqkv, nullptr);
    attn_kernel<<<dim3(16, 32), 256, ATTN_SMEM_BYTES>>>(compat);
    gemm_h<1><<<dim3(4, 8, 4), 256, GH_BYTES>>>(bproj, out);
}

// round 13
// speedup vs baseline: 3.0520x; 1.3366x over previous
#include <cuda_runtime.h>
#include <cuda_fp16.h>
#include <math.h>
#include <stdint.h>

#define NTOK 1024
#define DINV 512
#define NFV  4
#define NHV  8
#define HDV  64

#define LOG2E 1.44269504f

// -------- scratch (device globals; no allocation allowed) --------
__device__ float  g_cm[2][NFV][DINV];                // [qkv|proj][f][d]
__device__ __half g_xh[NFV * NTOK * DINV];           // x * cm0, fp16
__device__ __half g_wq_h[3 * DINV * DINV];           // W_qkv fp16
__device__ __half g_wp_h[DINV * DINV];               // W_proj fp16
__device__ __half g_qh[NHV * NFV * NTOK * HDV];      // [hf][n][d], scaled hd^-0.5 * log2e
__device__ __half g_kh[NHV * NFV * NTOK * HDV];      // [hf][n][d]
__device__ __half g_vT[NHV * NFV * HDV * NTOK];      // [hf][d][n] transposed
__device__ __half g_yh[NFV * NTOK * DINV];           // yhat * cm1, fp16
__device__ __half g_callTh[NTOK * 8];                // [c][f-pad8] half compat table

// ============================================================
// helpers
// ============================================================
__device__ __forceinline__ float ex2(float x) {
    float r;
    asm("ex2.approx.f32 %0, %1;" : "=f"(r) : "f"(x));
    return r;
}

__device__ __forceinline__ void mma_f16(float* d, uint32_t a0, uint32_t a1,
                                        uint32_t a2, uint32_t a3,
                                        uint32_t b0, uint32_t b1) {
    asm volatile(
        "mma.sync.aligned.m16n8k16.row.col.f32.f16.f16.f32 "
        "{%0,%1,%2,%3}, {%4,%5,%6,%7}, {%8,%9}, {%0,%1,%2,%3};"
        : "+f"(d[0]), "+f"(d[1]), "+f"(d[2]), "+f"(d[3])
        : "r"(a0), "r"(a1), "r"(a2), "r"(a3), "r"(b0), "r"(b1));
}

__device__ __forceinline__ void mma_f16_k8(float* d, uint32_t a0, uint32_t a1, uint32_t b0) {
    asm volatile(
        "mma.sync.aligned.m16n8k8.row.col.f32.f16.f16.f32 "
        "{%0,%1,%2,%3}, {%4,%5}, {%6}, {%0,%1,%2,%3};"
        : "+f"(d[0]), "+f"(d[1]), "+f"(d[2]), "+f"(d[3])
        : "r"(a0), "r"(a1), "r"(b0));
}

__device__ __forceinline__ void ldsm_x4(uint32_t& r0, uint32_t& r1,
                                        uint32_t& r2, uint32_t& r3, uint32_t addr) {
    asm volatile("ldmatrix.sync.aligned.m8n8.x4.shared.b16 {%0,%1,%2,%3}, [%4];"
                 : "=r"(r0), "=r"(r1), "=r"(r2), "=r"(r3) : "r"(addr));
}

__device__ __forceinline__ uint32_t smem_u32(const void* p) {
    uint32_t a;
    asm("{ .reg .u64 t; cvta.to.shared.u64 t, %1; cvt.u32.u64 %0, t; }" : "=r"(a) : "l"(p));
    return a;
}

__device__ __forceinline__ void cp_async16(uint32_t dst, const void* src) {
    asm volatile("cp.async.cg.shared.global [%0], [%1], 16;" :: "r"(dst), "l"(src) : "memory");
}
#define CP_COMMIT() asm volatile("cp.async.commit_group;" ::: "memory")
#define CP_WAIT0()  asm volatile("cp.async.wait_group 0;" ::: "memory")
#define CP_WAIT1()  asm volatile("cp.async.wait_group 1;" ::: "memory")

// attn: stage K tile (128 keys x 64 half dims, smem row stride 72 halves)
__device__ __forceinline__ void stage_k(uint32_t dstbase, const __half* src, int tid) {
    #pragma unroll
    for (int i = tid; i < 1024; i += 256) {
        int r = i >> 3, c8 = (i & 7) << 3;
        cp_async16(dstbase + (uint32_t)(r * 144 + c8 * 2), src + r * 64 + c8);
    }
}
// attn: stage V tile (transposed: 64 dim-rows x 128 half keys, stride 136 halves)
__device__ __forceinline__ void stage_v(uint32_t dstbase, const __half* srcT, int tid) {
    #pragma unroll
    for (int i = tid; i < 1024; i += 256) {
        int r = i >> 4, c16 = (i & 15) << 3;
        cp_async16(dstbase + (uint32_t)(r * 272 + c16 * 2), srcT + (size_t)r * NTOK + c16);
    }
}
// gemm: stage 128x64 half tile from 512-stride row-major, smem stride 72 halves
__device__ __forceinline__ void stage_h(uint32_t dstbase, const __half* src, int tid) {
    #pragma unroll
    for (int t = 0; t < 4; t++) {
        int i = tid + t * 256;
        int r = i >> 3, c8 = (i & 7) << 3;
        cp_async16(dstbase + (uint32_t)(r * 144 + c8 * 2), src + (size_t)r * 512 + c8);
    }
}

// ============================================================
// code_mod = LayerNorm((w_c @ code).T) * g + b  (coalesced warp-per-row)
// ============================================================
__global__ __launch_bounds__(512) void code_mod_kernel(
    const float* __restrict__ wc, const float* __restrict__ code,
    const float* __restrict__ gq, const float* __restrict__ bq,
    const float* __restrict__ gp, const float* __restrict__ bp)
{
    __shared__ float codes[512];
    __shared__ float tsh[NFV][512];
    __shared__ float red[512];
    const int tid = threadIdx.x;
    const int warp = tid >> 5, lane = tid & 31;

    codes[tid] = code[tid];
    __syncthreads();

    const float* cp = &codes[lane * 16];
    for (int i = 0; i < 32; i++) {
        int d = warp * 32 + i;
        float4 w = *(const float4*)(wc + (size_t)d * 128 + lane * 4);
        float t0 = w.x * cp[0] + w.y * cp[4] + w.z * cp[8]  + w.w * cp[12];
        float t1 = w.x * cp[1] + w.y * cp[5] + w.z * cp[9]  + w.w * cp[13];
        float t2 = w.x * cp[2] + w.y * cp[6] + w.z * cp[10] + w.w * cp[14];
        float t3 = w.x * cp[3] + w.y * cp[7] + w.z * cp[11] + w.w * cp[15];
        #pragma unroll
        for (int o = 16; o; o >>= 1) {
            t0 += __shfl_xor_sync(0xffffffffu, t0, o);
            t1 += __shfl_xor_sync(0xffffffffu, t1, o);
            t2 += __shfl_xor_sync(0xffffffffu, t2, o);
            t3 += __shfl_xor_sync(0xffffffffu, t3, o);
        }
        if (lane == 0) {
            tsh[0][d] = t0; tsh[1][d] = t1; tsh[2][d] = t2; tsh[3][d] = t3;
        }
    }
    __syncthreads();

    float gqd = gq[tid], bqd = bq[tid], gpd = gp[tid], bpd = bp[tid];
    for (int f = 0; f < NFV; f++) {
        float t = tsh[f][tid];
        red[tid] = t;
        __syncthreads();
        for (int s = 256; s > 0; s >>= 1) {
            if (tid < s) red[tid] += red[tid + s];
            __syncthreads();
        }
        float mu = red[0] * (1.f / 512.f);
        __syncthreads();
        float dv = t - mu;
        red[tid] = dv * dv;
        __syncthreads();
        for (int s = 256; s > 0; s >>= 1) {
            if (tid < s) red[tid] += red[tid + s];
            __syncthreads();
        }
        float var = red[0] * (1.f / 512.f);
        __syncthreads();
        float nrm = dv * rsqrtf(var + 1e-5f);
        g_cm[0][f][tid] = nrm * gqd + bqd;
        g_cm[1][f][tid] = nrm * gpd + bpd;
    }
}

// fused prep: callTh (blocks 0..3), weight convert (4..1027), xh (1028..3075)
__global__ __launch_bounds__(256) void prep_all(
    const float* __restrict__ cin, const float* __restrict__ Wq,
    const float* __restrict__ Wp, const float* __restrict__ x)
{
    int b = blockIdx.x, tid = threadIdx.x;
    if (b < 4) {
        int c = b * 256 + tid;
        __half2 w01 = __floats2half2_rn(cin[c], cin[NTOK + c]);
        __half2 w23 = __floats2half2_rn(cin[2 * NTOK + c], cin[3 * NTOK + c]);
        uint4 v;
        v.x = *(uint32_t*)&w01;
        v.y = *(uint32_t*)&w23;
        v.z = 0u; v.w = 0u;
        *(uint4*)&g_callTh[c * 8] = v;
    } else if (b < 1028) {
        int i = (b - 4) * 256 + tid;
        if (i < 196608) {
            float4 v = *(const float4*)(Wq + (size_t)i * 4);
            __half* d = g_wq_h + (size_t)i * 4;
            *(__half2*)(d)     = __floats2half2_rn(v.x, v.y);
            *(__half2*)(d + 2) = __floats2half2_rn(v.z, v.w);
        } else {
            int j = i - 196608;
            float4 v = *(const float4*)(Wp + (size_t)j * 4);
            __half* d = g_wp_h + (size_t)j * 4;
            *(__half2*)(d)     = __floats2half2_rn(v.x, v.y);
            *(__half2*)(d + 2) = __floats2half2_rn(v.z, v.w);
        }
    } else {
        int j = b - 1028;
        int f = j >> 9;
        int i = (j & 511) * 256 + tid;
        int n = i >> 7, c4 = (i & 127) << 2;
        float4 v = *(const float4*)(x + (size_t)n * 512 + c4);
        float4 s = *(const float4*)(&g_cm[0][f][c4]);
        __half* dst = g_xh + (size_t)f * NTOK * DINV + (size_t)n * 512 + c4;
        *(__half2*)(dst)     = __floats2half2_rn(v.x * s.x, v.y * s.y);
        *(__half2*)(dst + 2) = __floats2half2_rn(v.z * s.z, v.w * s.w);
    }
}

// ============================================================
// fp16 GEMM, ldmatrix operand feeding (q epilogue scaled by log2e)
// ============================================================
#define GH_BYTES (36864 * 2 + 512)

template <int MODE>
__global__ __launch_bounds__(256, 2) void gemm_h(
    const float* __restrict__ bias, float* __restrict__ Out)
{
    extern __shared__ __half smh[];
    float* sbias = (float*)(smh + 36864);
    const int f   = blockIdx.z;
    const int bm0 = blockIdx.y * 128;
    const int bn0 = blockIdx.x * 128;
    const int tid = threadIdx.x;
    const int warp = tid >> 5, lane = tid & 31;
    const int gid = lane >> 2, tig = lane & 3;
    const int wm = warp >> 2, wn = warp & 3;

    const int rA = (lane & 7) + (((lane >> 3) & 1) << 3);
    const int kA = (lane >> 4) << 3;
    const uint32_t aofs = (uint32_t)(rA * 144 + kA * 2);
    const int rB = (lane & 7) + ((lane >> 4) << 3);
    const int kB = ((lane >> 3) & 1) << 3;
    const uint32_t bofs = (uint32_t)(rB * 144 + kB * 2);

    const __half* A  = (MODE == 0 ? g_xh : g_yh) + (size_t)f * NTOK * DINV + (size_t)bm0 * 512;
    const __half* Bw = (MODE == 0 ? g_wq_h : g_wp_h) + (size_t)bn0 * 512;

    uint32_t sb = smem_u32(smh);
    uint32_t Ab[2] = {sb, sb + 9216 * 2};
    uint32_t Bb[2] = {sb + 18432 * 2, sb + 27648 * 2};

    if (tid < 128) sbias[tid] = bias[bn0 + tid];

    stage_h(Ab[0], A, tid);
    stage_h(Bb[0], Bw, tid);
    CP_COMMIT();

    float d[4][4][4];
    #pragma unroll
    for (int mt = 0; mt < 4; mt++)
        #pragma unroll
        for (int nt = 0; nt < 4; nt++)
            #pragma unroll
            for (int q = 0; q < 4; q++) d[mt][nt][q] = 0.f;

    for (int c = 0; c < 8; c++) {
        if (c < 7) {
            stage_h(Ab[(c + 1) & 1], A + (c + 1) * 64, tid);
            stage_h(Bb[(c + 1) & 1], Bw + (c + 1) * 64, tid);
            CP_COMMIT();
            CP_WAIT1();
        } else {
            CP_WAIT0();
        }
        __syncthreads();
        uint32_t atile = Ab[c & 1];
        uint32_t btile = Bb[c & 1];
        #pragma unroll
        for (int kk = 0; kk < 4; kk++) {
            uint32_t aa[4][4], bb[4][2];
            #pragma unroll
            for (int mt = 0; mt < 4; mt++)
                ldsm_x4(aa[mt][0], aa[mt][1], aa[mt][2], aa[mt][3],
                        atile + (uint32_t)((wm * 64 + mt * 16) * 144 + kk * 32) + aofs);
            #pragma unroll
            for (int ntp = 0; ntp < 2; ntp++)
                ldsm_x4(bb[ntp * 2][0], bb[ntp * 2][1], bb[ntp * 2 + 1][0], bb[ntp * 2 + 1][1],
                        btile + (uint32_t)((wn * 32 + ntp * 16) * 144 + kk * 32) + bofs);
            #pragma unroll
            for (int mt = 0; mt < 4; mt++)
                #pragma unroll
                for (int nt = 0; nt < 4; nt++)
                    mma_f16(d[mt][nt], aa[mt][0], aa[mt][1], aa[mt][2], aa[mt][3],
                            bb[nt][0], bb[nt][1]);
        }
        __syncthreads();
    }

    if (MODE == 1) {
        float* outp = Out + (size_t)f * NTOK * DINV;
        #pragma unroll
        for (int mt = 0; mt < 4; mt++) {
            int m0 = bm0 + wm * 64 + mt * 16 + gid;
            #pragma unroll
            for (int nt = 0; nt < 4; nt++) {
                int jl = wn * 32 + nt * 8 + tig * 2;
                float b0 = sbias[jl], b1 = sbias[jl + 1];
                float2 v0 = {d[mt][nt][0] + b0, d[mt][nt][1] + b1};
                float2 v1 = {d[mt][nt][2] + b0, d[mt][nt][3] + b1};
                *(float2*)(outp + (size_t)m0 * 512 + bn0 + jl)       = v0;
                *(float2*)(outp + (size_t)(m0 + 8) * 512 + bn0 + jl) = v1;
            }
        }
    } else if (bn0 < 1024) {
        int jb = bn0 + wn * 32;
        int tt = jb >> 9;
        int h  = (jb >> 6) & 7;
        int db = jb & 63;
        float mul = (tt == 0) ? (0.125f * LOG2E) : 1.0f;   // q in log2 domain
        __half* base = (tt == 0 ? g_qh : g_kh) + (size_t)((h * NFV + f) * NTOK) * HDV;
        #pragma unroll
        for (int mt = 0; mt < 4; mt++) {
            int m0 = bm0 + wm * 64 + mt * 16 + gid;
            #pragma unroll
            for (int nt = 0; nt < 4; nt++) {
                int jl = wn * 32 + nt * 8 + tig * 2;
                int dc = db + nt * 8 + tig * 2;
                float b0 = sbias[jl], b1 = sbias[jl + 1];
                __half2 h0 = __floats2half2_rn((d[mt][nt][0] + b0) * mul,
                                               (d[mt][nt][1] + b1) * mul);
                __half2 h1 = __floats2half2_rn((d[mt][nt][2] + b0) * mul,
                                               (d[mt][nt][3] + b1) * mul);
                *(__half2*)(base + (size_t)m0 * HDV + dc)       = h0;
                *(__half2*)(base + (size_t)(m0 + 8) * HDV + dc) = h1;
            }
        }
    } else {
        __syncthreads();
        __half* T = smh;
        #pragma unroll
        for (int mt = 0; mt < 4; mt++) {
            int mloc = wm * 64 + mt * 16 + gid;
            #pragma unroll
            for (int nt = 0; nt < 4; nt++) {
                int jl = wn * 32 + nt * 8 + tig * 2;
                float b0 = sbias[jl], b1 = sbias[jl + 1];
                T[jl * 136 + mloc]           = __float2half_rn(d[mt][nt][0] + b0);
                T[(jl + 1) * 136 + mloc]     = __float2half_rn(d[mt][nt][1] + b1);
                T[jl * 136 + mloc + 8]       = __float2half_rn(d[mt][nt][2] + b0);
                T[(jl + 1) * 136 + mloc + 8] = __float2half_rn(d[mt][nt][3] + b1);
            }
        }
        __syncthreads();
        int vbase = bn0 - 1024;
        #pragma unroll
        for (int t = 0; t < 8; t++) {
            int i = tid + t * 256;
            int jl = i >> 4, c8 = (i & 15) << 3;
            uint4 v = *(uint4*)&T[jl * 136 + c8];
            int vcol = vbase + jl;
            __half* dst = g_vT + (size_t)(((vcol >> 6) * NFV + f) * HDV + (vcol & 63)) * NTOK
                          + bm0 + c8;
            *(uint4*)dst = v;
        }
    }
}

// ============================================================
// attention: flash-style, 128-row blocks (single wave), 256 threads,
// 2 blocks/SM. Warp owns 16 full rows -> register-only softmax state.
// smem: K0 0 | K1 18432 | V0 36864 | V1 54272 | Q 71680 | WT 90112
// ============================================================
#define AT_K0   0
#define AT_K1   18432
#define AT_V0   36864
#define AT_V1   54272
#define AT_Q    71680
#define AT_WT   90112
#define ATTN_SMEM_BYTES 106496

__global__ __launch_bounds__(256, 2) void attn_kernel(const float* __restrict__ cin)
{
    extern __shared__ char smc[];
    __half* Qs = (__half*)(smc + AT_Q);

    const int tid = threadIdx.x;
    const int warp = tid >> 5, lane = tid & 31;
    const int gid = lane >> 2, tig = lane & 3;
    const int n0 = blockIdx.x * 128;
    const int hf = blockIdx.y;
    const int h = hf >> 2, f = hf & 3;
    const size_t hb = (size_t)hf * NTOK * HDV;

    const int rB = (lane & 7) + ((lane >> 4) << 3);
    const int kB = ((lane >> 3) & 1) << 3;
    const uint32_t bofsK = (uint32_t)(rB * 144 + kB * 2);
    const uint32_t bofsV = (uint32_t)(rB * 272 + kB * 2);

    uint32_t sb = smem_u32(smc);
    uint32_t kaddr[2] = {sb + AT_K0, sb + AT_K1};
    uint32_t vaddr[2] = {sb + AT_V0, sb + AT_V1};
    uint32_t wt = sb + AT_WT;
    const __half* Kp  = g_kh + hb;
    const __half* VTp = g_vT + (size_t)hf * HDV * NTOK;

    // prologue: K0 + WT; K1
    stage_k(kaddr[0], Kp, tid);
    #pragma unroll
    for (int i = tid; i < 1024; i += 256)
        cp_async16(wt + (uint32_t)i * 16, g_callTh + i * 8);
    CP_COMMIT();
    stage_k(kaddr[1], Kp + 8192, tid);  CP_COMMIT();

    // Q: 128 rows x 64 halves -> stride 72
    #pragma unroll
    for (int i = tid; i < 1024; i += 256) {
        int r = i >> 3, c8 = (i & 7) << 3;
        uint4 v = *(const uint4*)(g_qh + hb + (size_t)(n0 + r) * HDV + c8);
        *(uint4*)((char*)Qs + r * 144 + c8 * 2) = v;
    }
    __syncthreads();

    const int r0 = warp * 16 + gid, r1 = r0 + 8;

    uint32_t aq0[4], aq1[4], aq2[4], aq3[4];
    {
        const __half* q0 = Qs + r0 * 72;
        const __half* q1 = Qs + r1 * 72;
        #pragma unroll
        for (int kk = 0; kk < 4; kk++) {
            aq0[kk] = *(const uint32_t*)&q0[kk * 16 + tig * 2];
            aq1[kk] = *(const uint32_t*)&q1[kk * 16 + tig * 2];
            aq2[kk] = *(const uint32_t*)&q0[kk * 16 + tig * 2 + 8];
            aq3[kk] = *(const uint32_t*)&q1[kk * 16 + tig * 2 + 8];
        }
    }

    // ---- pass 1: s1 = sum exp(s)  (scores in log2 domain) ----
    float l0 = 0.f, l1 = 0.f;
    for (int mt = 0; mt < 8; mt++) {
        if (mt < 6) { CP_WAIT1(); } else { CP_WAIT0(); }
        __syncthreads();
        uint32_t kb_base = kaddr[mt & 1];
        #pragma unroll
        for (int ntp = 0; ntp < 8; ntp++) {
            float s4a[4] = {0.f, 0.f, 0.f, 0.f};
            float s4b[4] = {0.f, 0.f, 0.f, 0.f};
            #pragma unroll
            for (int kk = 0; kk < 4; kk++) {
                uint32_t b0, b1, b2, b3;
                ldsm_x4(b0, b1, b2, b3,
                        kb_base + (uint32_t)(ntp * 16 * 144 + kk * 32) + bofsK);
                mma_f16(s4a, aq0[kk], aq1[kk], aq2[kk], aq3[kk], b0, b1);
                mma_f16(s4b, aq0[kk], aq1[kk], aq2[kk], aq3[kk], b2, b3);
            }
            l0 += (ex2(s4a[0]) + ex2(s4a[1])) + (ex2(s4b[0]) + ex2(s4b[1]));
            l1 += (ex2(s4a[2]) + ex2(s4a[3])) + (ex2(s4b[2]) + ex2(s4b[3]));
        }
        __syncthreads();
        if (mt < 6) {
            stage_k(kaddr[mt & 1], Kp + (size_t)(mt + 2) * 8192, tid);
            CP_COMMIT();
        }
    }
    // register-only row-sum reduce (quad over tig)
    l0 += __shfl_xor_sync(0xffffffffu, l0, 1);
    l0 += __shfl_xor_sync(0xffffffffu, l0, 2);
    l1 += __shfl_xor_sync(0xffffffffu, l1, 1);
    l1 += __shfl_xor_sync(0xffffffffu, l1, 2);
    const float i1r0 = 1.f / l0, i1r1 = 1.f / l1;

    // pass-2 prologue (K buffers free: all warps past mt=7 compute sync)
    stage_k(kaddr[0], Kp, tid); stage_v(vaddr[0], VTp, tid); CP_COMMIT();
    stage_k(kaddr[1], Kp + 8192, tid); stage_v(vaddr[1], VTp + 128, tid); CP_COMMIT();

    // compat A-fragment: rows scaled by inv1*log2e, half, f padded to 8
    uint32_t ca0u, ca1u;
    {
        __half2 a0, a1;
        if (tig < 2) {
            float c00 = cin[(tig * 2) * NTOK + n0 + r0];
            float c01 = cin[(tig * 2 + 1) * NTOK + n0 + r0];
            float c10 = cin[(tig * 2) * NTOK + n0 + r1];
            float c11 = cin[(tig * 2 + 1) * NTOK + n0 + r1];
            a0 = __floats2half2_rn(c00 * i1r0 * LOG2E, c01 * i1r0 * LOG2E);
            a1 = __floats2half2_rn(c10 * i1r1 * LOG2E, c11 * i1r1 * LOG2E);
        } else {
            a0 = __floats2half2_rn(0.f, 0.f);
            a1 = a0;
        }
        ca0u = *(uint32_t*)&a0;
        ca1u = *(uint32_t*)&a1;
    }

    // ---- pass 2: recompute scores, compat via k8 MMA, p in regs, PV ----
    float o[8][4];
    #pragma unroll
    for (int dt = 0; dt < 8; dt++)
        #pragma unroll
        for (int q = 0; q < 4; q++) o[dt][q] = 0.f;
    float s2l0 = 0.f, s2l1 = 0.f;

    for (int mt = 0; mt < 8; mt++) {
        if (mt < 6) { CP_WAIT1(); } else { CP_WAIT0(); }
        __syncthreads();
        uint32_t kb_base = kaddr[mt & 1];
        uint32_t vb_base = vaddr[mt & 1];

        #pragma unroll
        for (int half = 0; half < 2; half++) {
            // w-table fragments: 8 n8-tiles for this 64-col half
            uint32_t bw[8];
            {
                int cbase = mt * 128 + half * 64;
                ldsm_x4(bw[0], bw[1], bw[2], bw[3], wt + (uint32_t)(cbase + lane) * 16);
                ldsm_x4(bw[4], bw[5], bw[6], bw[7], wt + (uint32_t)(cbase + 32 + lane) * 16);
            }
            uint32_t ph0[8], ph1[8];
            #pragma unroll
            for (int ntp = 0; ntp < 4; ntp++) {
                float s4a[4] = {0.f, 0.f, 0.f, 0.f};
                float s4b[4] = {0.f, 0.f, 0.f, 0.f};
                #pragma unroll
                for (int kk = 0; kk < 4; kk++) {
                    uint32_t b0, b1, b2, b3;
                    ldsm_x4(b0, b1, b2, b3,
                            kb_base + (uint32_t)((half * 64 + ntp * 16) * 144 + kk * 32) + bofsK);
                    mma_f16(s4a, aq0[kk], aq1[kk], aq2[kk], aq3[kk], b0, b1);
                    mma_f16(s4b, aq0[kk], aq1[kk], aq2[kk], aq3[kk], b2, b3);
                }
                float cc0[4] = {0.f, 0.f, 0.f, 0.f};
                float cc1[4] = {0.f, 0.f, 0.f, 0.f};
                mma_f16_k8(cc0, ca0u, ca1u, bw[ntp * 2]);
                mma_f16_k8(cc1, ca0u, ca1u, bw[ntp * 2 + 1]);

                float p00 = ex2(ex2(s4a[0]) * cc0[0]);
                float p01 = ex2(ex2(s4a[1]) * cc0[1]);
                float p10 = ex2(ex2(s4a[2]) * cc0[2]);
                float p11 = ex2(ex2(s4a[3]) * cc0[3]);
                float q00 = ex2(ex2(s4b[0]) * cc1[0]);
                float q01 = ex2(ex2(s4b[1]) * cc1[1]);
                float q10 = ex2(ex2(s4b[2]) * cc1[2]);
                float q11 = ex2(ex2(s4b[3]) * cc1[3]);
                s2l0 += (p00 + p01) + (q00 + q01);
                s2l1 += (p10 + p11) + (q10 + q11);
                __half2 hA = __floats2half2_rn(p00, p01);
                __half2 hB = __floats2half2_rn(p10, p11);
                __half2 hC = __floats2half2_rn(q00, q01);
                __half2 hD = __floats2half2_rn(q10, q11);
                ph0[ntp * 2]     = *(uint32_t*)&hA;
                ph1[ntp * 2]     = *(uint32_t*)&hB;
                ph0[ntp * 2 + 1] = *(uint32_t*)&hC;
                ph1[ntp * 2 + 1] = *(uint32_t*)&hD;
            }
            #pragma unroll
            for (int kb = 0; kb < 4; kb++) {
                uint32_t a0 = ph0[2 * kb], a1 = ph1[2 * kb];
                uint32_t a2 = ph0[2 * kb + 1], a3 = ph1[2 * kb + 1];
                #pragma unroll
                for (int dtp = 0; dtp < 4; dtp++) {
                    uint32_t v0, v1, v2, v3;
                    ldsm_x4(v0, v1, v2, v3,
                            vb_base + (uint32_t)(dtp * 16 * 272 + (half * 4 + kb) * 32) + bofsV);
                    mma_f16(o[dtp * 2],     a0, a1, a2, a3, v0, v1);
                    mma_f16(o[dtp * 2 + 1], a0, a1, a2, a3, v2, v3);
                }
            }
        }
        __syncthreads();
        if (mt < 6) {
            stage_k(kaddr[mt & 1], Kp + (size_t)(mt + 2) * 8192, tid);
            stage_v(vaddr[mt & 1], VTp + (mt + 2) * 128, tid);
            CP_COMMIT();
        }
    }

    // register-only s2 reduce + direct epilogue
    s2l0 += __shfl_xor_sync(0xffffffffu, s2l0, 1);
    s2l0 += __shfl_xor_sync(0xffffffffu, s2l0, 2);
    s2l1 += __shfl_xor_sync(0xffffffffu, s2l1, 1);
    s2l1 += __shfl_xor_sync(0xffffffffu, s2l1, 2);
    const float i2r0 = 1.f / s2l0, i2r1 = 1.f / s2l1;

    const float* cm1p = &g_cm[1][f][h * 64];
    __half* yp0 = g_yh + (size_t)f * NTOK * DINV + (size_t)(n0 + r0) * DINV + h * 64;
    __half* yp1 = g_yh + (size_t)f * NTOK * DINV + (size_t)(n0 + r1) * DINV + h * 64;
    #pragma unroll
    for (int dt = 0; dt < 8; dt++) {
        int dc = dt * 8 + tig * 2;
        float2 cc = *(const float2*)&cm1p[dc];
        *(__half2*)(yp0 + dc) = __floats2half2_rn(o[dt][0] * i2r0 * cc.x,
                                                  o[dt][1] * i2r0 * cc.y);
        *(__half2*)(yp1 + dc) = __floats2half2_rn(o[dt][2] * i2r1 * cc.x,
                                                  o[dt][3] * i2r1 * cc.y);
    }
}

// ============================================================
extern "C" void kernel_launch(void* const* d_in, const int* in_sizes, int n_in,
                              void* d_out, int out_size)
{
    const float* x      = (const float*)d_in[0];
    const float* compat = (const float*)d_in[1];
    const float* code   = (const float*)d_in[2];
    const float* wc     = (const float*)d_in[3];
    const float* Wqkv   = (const float*)d_in[4];
    const float* bqkv   = (const float*)d_in[5];
    const float* Wproj  = (const float*)d_in[6];
    const float* bproj  = (const float*)d_in[7];
    const float* lnqg   = (const float*)d_in[8];
    const float* lnqb   = (const float*)d_in[9];
    const float* lnpg   = (const float*)d_in[10];
    const float* lnpb   = (const float*)d_in[11];
    float* out = (float*)d_out;

    cudaFuncSetAttribute(attn_kernel,
                         cudaFuncAttributeMaxDynamicSharedMemorySize, ATTN_SMEM_BYTES);
    cudaFuncSetAttribute(gemm_h<0>,
                         cudaFuncAttributeMaxDynamicSharedMemorySize, GH_BYTES);
    cudaFuncSetAttribute(gemm_h<1>,
                         cudaFuncAttributeMaxDynamicSharedMemorySize, GH_BYTES);

    code_mod_kernel<<<1, 512>>>(wc, code, lnqg, lnqb, lnpg, lnpb);
    prep_all<<<3076, 256>>>(compat, Wqkv, Wproj, x);
    gemm_h<0><<<dim3(12, 8, 4), 256, GH_BYTES>>>(bqkv, nullptr);
    attn_kernel<<<dim3(8, 32), 256, ATTN_SMEM_BYTES>>>(compat);
    gemm_h<1><<<dim3(4, 8, 4), 256, GH_BYTES>>>(bproj, out);
}

// round 14
// speedup vs baseline: 3.0985x; 1.0152x over previous
#include <cuda_runtime.h>
#include <cuda_fp16.h>
#include <math.h>
#include <stdint.h>

#define NTOK 1024
#define DINV 512
#define NFV  4
#define NHV  8
#define HDV  64

#define LOG2E 1.44269504f

// -------- scratch (device globals; no allocation allowed) --------
__device__ float  g_cm[2][NFV][DINV];                // [qkv|proj][f][d]
__device__ __half g_xh[NFV * NTOK * DINV];           // x * cm0, fp16
__device__ __half g_wq_h[3 * DINV * DINV];           // W_qkv fp16
__device__ __half g_wp_h[DINV * DINV];               // W_proj fp16
__device__ __half g_qh[NHV * NFV * NTOK * HDV];      // [hf][n][d], scaled hd^-0.5 * log2e
__device__ __half g_kh[NHV * NFV * NTOK * HDV];      // [hf][n][d]
__device__ __half g_vT[NHV * NFV * HDV * NTOK];      // [hf][d][n] transposed
__device__ __half g_yh[NFV * NTOK * DINV];           // yhat * cm1, fp16
__device__ __half g_callTh[NTOK * 8];                // [c][f-pad8] half compat table

// ============================================================
// helpers
// ============================================================
__device__ __forceinline__ float ex2(float x) {
    float r;
    asm("ex2.approx.f32 %0, %1;" : "=f"(r) : "f"(x));
    return r;
}
__device__ __forceinline__ uint32_t ex2h2(uint32_t x) {
    uint32_t r;
    asm("ex2.approx.f16x2 %0, %1;" : "=r"(r) : "r"(x));
    return r;
}
__device__ __forceinline__ uint32_t packh2(float a, float b) {
    __half2 h = __floats2half2_rn(a, b);
    return *(uint32_t*)&h;
}
__device__ __forceinline__ uint32_t hmul2u(uint32_t a, uint32_t b) {
    uint32_t r;
    asm("mul.f16x2 %0, %1, %2;" : "=r"(r) : "r"(a), "r"(b));
    return r;
}
__device__ __forceinline__ float2 h2f2(uint32_t x) {
    __half2 h = *(__half2*)&x;
    return __half22float2(h);
}

__device__ __forceinline__ void mma_f16(float* d, uint32_t a0, uint32_t a1,
                                        uint32_t a2, uint32_t a3,
                                        uint32_t b0, uint32_t b1) {
    asm volatile(
        "mma.sync.aligned.m16n8k16.row.col.f32.f16.f16.f32 "
        "{%0,%1,%2,%3}, {%4,%5,%6,%7}, {%8,%9}, {%0,%1,%2,%3};"
        : "+f"(d[0]), "+f"(d[1]), "+f"(d[2]), "+f"(d[3])
        : "r"(a0), "r"(a1), "r"(a2), "r"(a3), "r"(b0), "r"(b1));
}

__device__ __forceinline__ void mma_f16_k8(float* d, uint32_t a0, uint32_t a1, uint32_t b0) {
    asm volatile(
        "mma.sync.aligned.m16n8k8.row.col.f32.f16.f16.f32 "
        "{%0,%1,%2,%3}, {%4,%5}, {%6}, {%0,%1,%2,%3};"
        : "+f"(d[0]), "+f"(d[1]), "+f"(d[2]), "+f"(d[3])
        : "r"(a0), "r"(a1), "r"(b0));
}

__device__ __forceinline__ void ldsm_x4(uint32_t& r0, uint32_t& r1,
                                        uint32_t& r2, uint32_t& r3, uint32_t addr) {
    asm volatile("ldmatrix.sync.aligned.m8n8.x4.shared.b16 {%0,%1,%2,%3}, [%4];"
                 : "=r"(r0), "=r"(r1), "=r"(r2), "=r"(r3) : "r"(addr));
}

__device__ __forceinline__ uint32_t smem_u32(const void* p) {
    uint32_t a;
    asm("{ .reg .u64 t; cvta.to.shared.u64 t, %1; cvt.u32.u64 %0, t; }" : "=r"(a) : "l"(p));
    return a;
}

__device__ __forceinline__ void cp_async16(uint32_t dst, const void* src) {
    asm volatile("cp.async.cg.shared.global [%0], [%1], 16;" :: "r"(dst), "l"(src) : "memory");
}
#define CP_COMMIT() asm volatile("cp.async.commit_group;" ::: "memory")
#define CP_WAIT0()  asm volatile("cp.async.wait_group 0;" ::: "memory")
#define CP_WAIT1()  asm volatile("cp.async.wait_group 1;" ::: "memory")

// attn: stage K tile (128 keys x 64 half dims, smem row stride 72 halves)
__device__ __forceinline__ void stage_k(uint32_t dstbase, const __half* src, int tid) {
    #pragma unroll
    for (int i = tid; i < 1024; i += 256) {
        int r = i >> 3, c8 = (i & 7) << 3;
        cp_async16(dstbase + (uint32_t)(r * 144 + c8 * 2), src + r * 64 + c8);
    }
}
// attn: stage V tile (transposed: 64 dim-rows x 128 half keys, stride 136 halves)
__device__ __forceinline__ void stage_v(uint32_t dstbase, const __half* srcT, int tid) {
    #pragma unroll
    for (int i = tid; i < 1024; i += 256) {
        int r = i >> 4, c16 = (i & 15) << 3;
        cp_async16(dstbase + (uint32_t)(r * 272 + c16 * 2), srcT + (size_t)r * NTOK + c16);
    }
}
// gemm: stage 128x64 half tile from 512-stride row-major, smem stride 72 halves
__device__ __forceinline__ void stage_h(uint32_t dstbase, const __half* src, int tid) {
    #pragma unroll
    for (int t = 0; t < 4; t++) {
        int i = tid + t * 256;
        int r = i >> 3, c8 = (i & 7) << 3;
        cp_async16(dstbase + (uint32_t)(r * 144 + c8 * 2), src + (size_t)r * 512 + c8);
    }
}

// ============================================================
// code_mod = LayerNorm((w_c @ code).T) * g + b  (coalesced warp-per-row)
// ============================================================
__global__ __launch_bounds__(512) void code_mod_kernel(
    const float* __restrict__ wc, const float* __restrict__ code,
    const float* __restrict__ gq, const float* __restrict__ bq,
    const float* __restrict__ gp, const float* __restrict__ bp)
{
    __shared__ float codes[512];
    __shared__ float tsh[NFV][512];
    __shared__ float red[512];
    const int tid = threadIdx.x;
    const int warp = tid >> 5, lane = tid & 31;

    codes[tid] = code[tid];
    __syncthreads();

    const float* cp = &codes[lane * 16];
    for (int i = 0; i < 32; i++) {
        int d = warp * 32 + i;
        float4 w = *(const float4*)(wc + (size_t)d * 128 + lane * 4);
        float t0 = w.x * cp[0] + w.y * cp[4] + w.z * cp[8]  + w.w * cp[12];
        float t1 = w.x * cp[1] + w.y * cp[5] + w.z * cp[9]  + w.w * cp[13];
        float t2 = w.x * cp[2] + w.y * cp[6] + w.z * cp[10] + w.w * cp[14];
        float t3 = w.x * cp[3] + w.y * cp[7] + w.z * cp[11] + w.w * cp[15];
        #pragma unroll
        for (int o = 16; o; o >>= 1) {
            t0 += __shfl_xor_sync(0xffffffffu, t0, o);
            t1 += __shfl_xor_sync(0xffffffffu, t1, o);
            t2 += __shfl_xor_sync(0xffffffffu, t2, o);
            t3 += __shfl_xor_sync(0xffffffffu, t3, o);
        }
        if (lane == 0) {
            tsh[0][d] = t0; tsh[1][d] = t1; tsh[2][d] = t2; tsh[3][d] = t3;
        }
    }
    __syncthreads();

    float gqd = gq[tid], bqd = bq[tid], gpd = gp[tid], bpd = bp[tid];
    for (int f = 0; f < NFV; f++) {
        float t = tsh[f][tid];
        red[tid] = t;
        __syncthreads();
        for (int s = 256; s > 0; s >>= 1) {
            if (tid < s) red[tid] += red[tid + s];
            __syncthreads();
        }
        float mu = red[0] * (1.f / 512.f);
        __syncthreads();
        float dv = t - mu;
        red[tid] = dv * dv;
        __syncthreads();
        for (int s = 256; s > 0; s >>= 1) {
            if (tid < s) red[tid] += red[tid + s];
            __syncthreads();
        }
        float var = red[0] * (1.f / 512.f);
        __syncthreads();
        float nrm = dv * rsqrtf(var + 1e-5f);
        g_cm[0][f][tid] = nrm * gqd + bqd;
        g_cm[1][f][tid] = nrm * gpd + bpd;
    }
}

// fused prep: callTh (blocks 0..3), weight convert (4..1027), xh (1028..3075)
__global__ __launch_bounds__(256) void prep_all(
    const float* __restrict__ cin, const float* __restrict__ Wq,
    const float* __restrict__ Wp, const float* __restrict__ x)
{
    int b = blockIdx.x, tid = threadIdx.x;
    if (b < 4) {
        int c = b * 256 + tid;
        __half2 w01 = __floats2half2_rn(cin[c], cin[NTOK + c]);
        __half2 w23 = __floats2half2_rn(cin[2 * NTOK + c], cin[3 * NTOK + c]);
        uint4 v;
        v.x = *(uint32_t*)&w01;
        v.y = *(uint32_t*)&w23;
        v.z = 0u; v.w = 0u;
        *(uint4*)&g_callTh[c * 8] = v;
    } else if (b < 1028) {
        int i = (b - 4) * 256 + tid;
        if (i < 196608) {
            float4 v = *(const float4*)(Wq + (size_t)i * 4);
            __half* d = g_wq_h + (size_t)i * 4;
            *(__half2*)(d)     = __floats2half2_rn(v.x, v.y);
            *(__half2*)(d + 2) = __floats2half2_rn(v.z, v.w);
        } else {
            int j = i - 196608;
            float4 v = *(const float4*)(Wp + (size_t)j * 4);
            __half* d = g_wp_h + (size_t)j * 4;
            *(__half2*)(d)     = __floats2half2_rn(v.x, v.y);
            *(__half2*)(d + 2) = __floats2half2_rn(v.z, v.w);
        }
    } else {
        int j = b - 1028;
        int f = j >> 9;
        int i = (j & 511) * 256 + tid;
        int n = i >> 7, c4 = (i & 127) << 2;
        float4 v = *(const float4*)(x + (size_t)n * 512 + c4);
        float4 s = *(const float4*)(&g_cm[0][f][c4]);
        __half* dst = g_xh + (size_t)f * NTOK * DINV + (size_t)n * 512 + c4;
        *(__half2*)(dst)     = __floats2half2_rn(v.x * s.x, v.y * s.y);
        *(__half2*)(dst + 2) = __floats2half2_rn(v.z * s.z, v.w * s.w);
    }
}

// ============================================================
// fp16 GEMM, ldmatrix operand feeding (q epilogue scaled by log2e)
// ============================================================
#define GH_BYTES (36864 * 2 + 512)

template <int MODE>
__global__ __launch_bounds__(256, 2) void gemm_h(
    const float* __restrict__ bias, float* __restrict__ Out)
{
    extern __shared__ __half smh[];
    float* sbias = (float*)(smh + 36864);
    const int f   = blockIdx.z;
    const int bm0 = blockIdx.y * 128;
    const int bn0 = blockIdx.x * 128;
    const int tid = threadIdx.x;
    const int warp = tid >> 5, lane = tid & 31;
    const int gid = lane >> 2, tig = lane & 3;
    const int wm = warp >> 2, wn = warp & 3;

    const int rA = (lane & 7) + (((lane >> 3) & 1) << 3);
    const int kA = (lane >> 4) << 3;
    const uint32_t aofs = (uint32_t)(rA * 144 + kA * 2);
    const int rB = (lane & 7) + ((lane >> 4) << 3);
    const int kB = ((lane >> 3) & 1) << 3;
    const uint32_t bofs = (uint32_t)(rB * 144 + kB * 2);

    const __half* A  = (MODE == 0 ? g_xh : g_yh) + (size_t)f * NTOK * DINV + (size_t)bm0 * 512;
    const __half* Bw = (MODE == 0 ? g_wq_h : g_wp_h) + (size_t)bn0 * 512;

    uint32_t sb = smem_u32(smh);
    uint32_t Ab[2] = {sb, sb + 9216 * 2};
    uint32_t Bb[2] = {sb + 18432 * 2, sb + 27648 * 2};

    if (tid < 128) sbias[tid] = bias[bn0 + tid];

    stage_h(Ab[0], A, tid);
    stage_h(Bb[0], Bw, tid);
    CP_COMMIT();

    float d[4][4][4];
    #pragma unroll
    for (int mt = 0; mt < 4; mt++)
        #pragma unroll
        for (int nt = 0; nt < 4; nt++)
            #pragma unroll
            for (int q = 0; q < 4; q++) d[mt][nt][q] = 0.f;

    for (int c = 0; c < 8; c++) {
        if (c < 7) {
            stage_h(Ab[(c + 1) & 1], A + (c + 1) * 64, tid);
            stage_h(Bb[(c + 1) & 1], Bw + (c + 1) * 64, tid);
            CP_COMMIT();
            CP_WAIT1();
        } else {
            CP_WAIT0();
        }
        __syncthreads();
        uint32_t atile = Ab[c & 1];
        uint32_t btile = Bb[c & 1];
        #pragma unroll
        for (int kk = 0; kk < 4; kk++) {
            uint32_t aa[4][4], bb[4][2];
            #pragma unroll
            for (int mt = 0; mt < 4; mt++)
                ldsm_x4(aa[mt][0], aa[mt][1], aa[mt][2], aa[mt][3],
                        atile + (uint32_t)((wm * 64 + mt * 16) * 144 + kk * 32) + aofs);
            #pragma unroll
            for (int ntp = 0; ntp < 2; ntp++)
                ldsm_x4(bb[ntp * 2][0], bb[ntp * 2][1], bb[ntp * 2 + 1][0], bb[ntp * 2 + 1][1],
                        btile + (uint32_t)((wn * 32 + ntp * 16) * 144 + kk * 32) + bofs);
            #pragma unroll
            for (int mt = 0; mt < 4; mt++)
                #pragma unroll
                for (int nt = 0; nt < 4; nt++)
                    mma_f16(d[mt][nt], aa[mt][0], aa[mt][1], aa[mt][2], aa[mt][3],
                            bb[nt][0], bb[nt][1]);
        }
        __syncthreads();
    }

    if (MODE == 1) {
        float* outp = Out + (size_t)f * NTOK * DINV;
        #pragma unroll
        for (int mt = 0; mt < 4; mt++) {
            int m0 = bm0 + wm * 64 + mt * 16 + gid;
            #pragma unroll
            for (int nt = 0; nt < 4; nt++) {
                int jl = wn * 32 + nt * 8 + tig * 2;
                float b0 = sbias[jl], b1 = sbias[jl + 1];
                float2 v0 = {d[mt][nt][0] + b0, d[mt][nt][1] + b1};
                float2 v1 = {d[mt][nt][2] + b0, d[mt][nt][3] + b1};
                *(float2*)(outp + (size_t)m0 * 512 + bn0 + jl)       = v0;
                *(float2*)(outp + (size_t)(m0 + 8) * 512 + bn0 + jl) = v1;
            }
        }
    } else if (bn0 < 1024) {
        int jb = bn0 + wn * 32;
        int tt = jb >> 9;
        int h  = (jb >> 6) & 7;
        int db = jb & 63;
        float mul = (tt == 0) ? (0.125f * LOG2E) : 1.0f;   // q in log2 domain
        __half* base = (tt == 0 ? g_qh : g_kh) + (size_t)((h * NFV + f) * NTOK) * HDV;
        #pragma unroll
        for (int mt = 0; mt < 4; mt++) {
            int m0 = bm0 + wm * 64 + mt * 16 + gid;
            #pragma unroll
            for (int nt = 0; nt < 4; nt++) {
                int jl = wn * 32 + nt * 8 + tig * 2;
                int dc = db + nt * 8 + tig * 2;
                float b0 = sbias[jl], b1 = sbias[jl + 1];
                __half2 h0 = __floats2half2_rn((d[mt][nt][0] + b0) * mul,
                                               (d[mt][nt][1] + b1) * mul);
                __half2 h1 = __floats2half2_rn((d[mt][nt][2] + b0) * mul,
                                               (d[mt][nt][3] + b1) * mul);
                *(__half2*)(base + (size_t)m0 * HDV + dc)       = h0;
                *(__half2*)(base + (size_t)(m0 + 8) * HDV + dc) = h1;
            }
        }
    } else {
        __syncthreads();
        __half* T = smh;
        #pragma unroll
        for (int mt = 0; mt < 4; mt++) {
            int mloc = wm * 64 + mt * 16 + gid;
            #pragma unroll
            for (int nt = 0; nt < 4; nt++) {
                int jl = wn * 32 + nt * 8 + tig * 2;
                float b0 = sbias[jl], b1 = sbias[jl + 1];
                T[jl * 136 + mloc]           = __float2half_rn(d[mt][nt][0] + b0);
                T[(jl + 1) * 136 + mloc]     = __float2half_rn(d[mt][nt][1] + b1);
                T[jl * 136 + mloc + 8]       = __float2half_rn(d[mt][nt][2] + b0);
                T[(jl + 1) * 136 + mloc + 8] = __float2half_rn(d[mt][nt][3] + b1);
            }
        }
        __syncthreads();
        int vbase = bn0 - 1024;
        #pragma unroll
        for (int t = 0; t < 8; t++) {
            int i = tid + t * 256;
            int jl = i >> 4, c8 = (i & 15) << 3;
            uint4 v = *(uint4*)&T[jl * 136 + c8];
            int vcol = vbase + jl;
            __half* dst = g_vT + (size_t)(((vcol >> 6) * NFV + f) * HDV + (vcol & 63)) * NTOK
                          + bm0 + c8;
            *(uint4*)dst = v;
        }
    }
}

// ============================================================
// attention: flash-style, 128-row blocks (single wave), 256 threads,
// 2 blocks/SM. Register-only softmax state; f16x2 EX2 path.
// smem: K0 0 | K1 18432 | V0 36864 | V1 54272 | Q 71680 | WT 90112
// ============================================================
#define AT_K0   0
#define AT_K1   18432
#define AT_V0   36864
#define AT_V1   54272
#define AT_Q    71680
#define AT_WT   90112
#define ATTN_SMEM_BYTES 106496

__global__ __launch_bounds__(256, 2) void attn_kernel(const float* __restrict__ cin)
{
    extern __shared__ char smc[];
    __half* Qs = (__half*)(smc + AT_Q);

    const int tid = threadIdx.x;
    const int warp = tid >> 5, lane = tid & 31;
    const int gid = lane >> 2, tig = lane & 3;
    const int n0 = blockIdx.x * 128;
    const int hf = blockIdx.y;
    const int h = hf >> 2, f = hf & 3;
    const size_t hb = (size_t)hf * NTOK * HDV;

    const int rB = (lane & 7) + ((lane >> 4) << 3);
    const int kB = ((lane >> 3) & 1) << 3;
    const uint32_t bofsK = (uint32_t)(rB * 144 + kB * 2);
    const uint32_t bofsV = (uint32_t)(rB * 272 + kB * 2);

    uint32_t sb = smem_u32(smc);
    uint32_t kaddr[2] = {sb + AT_K0, sb + AT_K1};
    uint32_t vaddr[2] = {sb + AT_V0, sb + AT_V1};
    uint32_t wt = sb + AT_WT;
    const __half* Kp  = g_kh + hb;
    const __half* VTp = g_vT + (size_t)hf * HDV * NTOK;

    // prologue: K0 + WT; K1
    stage_k(kaddr[0], Kp, tid);
    #pragma unroll
    for (int i = tid; i < 1024; i += 256)
        cp_async16(wt + (uint32_t)i * 16, g_callTh + i * 8);
    CP_COMMIT();
    stage_k(kaddr[1], Kp + 8192, tid);  CP_COMMIT();

    // Q: 128 rows x 64 halves -> stride 72
    #pragma unroll
    for (int i = tid; i < 1024; i += 256) {
        int r = i >> 3, c8 = (i & 7) << 3;
        uint4 v = *(const uint4*)(g_qh + hb + (size_t)(n0 + r) * HDV + c8);
        *(uint4*)((char*)Qs + r * 144 + c8 * 2) = v;
    }
    __syncthreads();

    const int r0 = warp * 16 + gid, r1 = r0 + 8;

    uint32_t aq0[4], aq1[4], aq2[4], aq3[4];
    {
        const __half* q0 = Qs + r0 * 72;
        const __half* q1 = Qs + r1 * 72;
        #pragma unroll
        for (int kk = 0; kk < 4; kk++) {
            aq0[kk] = *(const uint32_t*)&q0[kk * 16 + tig * 2];
            aq1[kk] = *(const uint32_t*)&q1[kk * 16 + tig * 2];
            aq2[kk] = *(const uint32_t*)&q0[kk * 16 + tig * 2 + 8];
            aq3[kk] = *(const uint32_t*)&q1[kk * 16 + tig * 2 + 8];
        }
    }

    // ---- pass 1: s1 = sum exp(s)  (scores in log2 domain, f16x2 EX2) ----
    float l0 = 0.f, l1 = 0.f;
    for (int mt = 0; mt < 8; mt++) {
        if (mt < 6) { CP_WAIT1(); } else { CP_WAIT0(); }
        __syncthreads();
        uint32_t kb_base = kaddr[mt & 1];
        #pragma unroll
        for (int ntp = 0; ntp < 8; ntp++) {
            float s4a[4] = {0.f, 0.f, 0.f, 0.f};
            float s4b[4] = {0.f, 0.f, 0.f, 0.f};
            #pragma unroll
            for (int kk = 0; kk < 4; kk++) {
                uint32_t b0, b1, b2, b3;
                ldsm_x4(b0, b1, b2, b3,
                        kb_base + (uint32_t)(ntp * 16 * 144 + kk * 32) + bofsK);
                mma_f16(s4a, aq0[kk], aq1[kk], aq2[kk], aq3[kk], b0, b1);
                mma_f16(s4b, aq0[kk], aq1[kk], aq2[kk], aq3[kk], b2, b3);
            }
            float2 eA0 = h2f2(ex2h2(packh2(s4a[0], s4a[1])));
            float2 eA1 = h2f2(ex2h2(packh2(s4a[2], s4a[3])));
            float2 eB0 = h2f2(ex2h2(packh2(s4b[0], s4b[1])));
            float2 eB1 = h2f2(ex2h2(packh2(s4b[2], s4b[3])));
            l0 += (eA0.x + eA0.y) + (eB0.x + eB0.y);
            l1 += (eA1.x + eA1.y) + (eB1.x + eB1.y);
        }
        __syncthreads();
        if (mt < 6) {
            stage_k(kaddr[mt & 1], Kp + (size_t)(mt + 2) * 8192, tid);
            CP_COMMIT();
        }
    }
    l0 += __shfl_xor_sync(0xffffffffu, l0, 1);
    l0 += __shfl_xor_sync(0xffffffffu, l0, 2);
    l1 += __shfl_xor_sync(0xffffffffu, l1, 1);
    l1 += __shfl_xor_sync(0xffffffffu, l1, 2);
    const float i1r0 = 1.f / l0, i1r1 = 1.f / l1;

    // pass-2 prologue
    stage_k(kaddr[0], Kp, tid); stage_v(vaddr[0], VTp, tid); CP_COMMIT();
    stage_k(kaddr[1], Kp + 8192, tid); stage_v(vaddr[1], VTp + 128, tid); CP_COMMIT();

    // compat A-fragment: rows scaled by inv1*log2e, half, f padded to 8
    uint32_t ca0u, ca1u;
    {
        __half2 a0, a1;
        if (tig < 2) {
            float c00 = cin[(tig * 2) * NTOK + n0 + r0];
            float c01 = cin[(tig * 2 + 1) * NTOK + n0 + r0];
            float c10 = cin[(tig * 2) * NTOK + n0 + r1];
            float c11 = cin[(tig * 2 + 1) * NTOK + n0 + r1];
            a0 = __floats2half2_rn(c00 * i1r0 * LOG2E, c01 * i1r0 * LOG2E);
            a1 = __floats2half2_rn(c10 * i1r1 * LOG2E, c11 * i1r1 * LOG2E);
        } else {
            a0 = __floats2half2_rn(0.f, 0.f);
            a1 = a0;
        }
        ca0u = *(uint32_t*)&a0;
        ca1u = *(uint32_t*)&a1;
    }

    // ---- pass 2: recompute scores, compat via k8 MMA, f16x2 exp chain, PV ----
    float o[8][4];
    #pragma unroll
    for (int dt = 0; dt < 8; dt++)
        #pragma unroll
        for (int q = 0; q < 4; q++) o[dt][q] = 0.f;
    float s2l0 = 0.f, s2l1 = 0.f;

    for (int mt = 0; mt < 8; mt++) {
        if (mt < 6) { CP_WAIT1(); } else { CP_WAIT0(); }
        __syncthreads();
        uint32_t kb_base = kaddr[mt & 1];
        uint32_t vb_base = vaddr[mt & 1];

        #pragma unroll
        for (int half = 0; half < 2; half++) {
            uint32_t bw[8];
            {
                int cbase = mt * 128 + half * 64;
                ldsm_x4(bw[0], bw[1], bw[2], bw[3], wt + (uint32_t)(cbase + lane) * 16);
                ldsm_x4(bw[4], bw[5], bw[6], bw[7], wt + (uint32_t)(cbase + 32 + lane) * 16);
            }
            uint32_t ph0[8], ph1[8];
            #pragma unroll
            for (int ntp = 0; ntp < 4; ntp++) {
                float s4a[4] = {0.f, 0.f, 0.f, 0.f};
                float s4b[4] = {0.f, 0.f, 0.f, 0.f};
                #pragma unroll
                for (int kk = 0; kk < 4; kk++) {
                    uint32_t b0, b1, b2, b3;
                    ldsm_x4(b0, b1, b2, b3,
                            kb_base + (uint32_t)((half * 64 + ntp * 16) * 144 + kk * 32) + bofsK);
                    mma_f16(s4a, aq0[kk], aq1[kk], aq2[kk], aq3[kk], b0, b1);
                    mma_f16(s4b, aq0[kk], aq1[kk], aq2[kk], aq3[kk], b2, b3);
                }
                float cc0[4] = {0.f, 0.f, 0.f, 0.f};
                float cc1[4] = {0.f, 0.f, 0.f, 0.f};
                mma_f16_k8(cc0, ca0u, ca1u, bw[ntp * 2]);
                mma_f16_k8(cc1, ca0u, ca1u, bw[ntp * 2 + 1]);

                // row0 pair (cols c,c+1): e = 2^s, u = e*cc (f16x2), p = 2^u
                uint32_t pA = ex2h2(hmul2u(ex2h2(packh2(s4a[0], s4a[1])),
                                           packh2(cc0[0], cc0[1])));
                uint32_t pB = ex2h2(hmul2u(ex2h2(packh2(s4a[2], s4a[3])),
                                           packh2(cc0[2], cc0[3])));
                uint32_t pC = ex2h2(hmul2u(ex2h2(packh2(s4b[0], s4b[1])),
                                           packh2(cc1[0], cc1[1])));
                uint32_t pD = ex2h2(hmul2u(ex2h2(packh2(s4b[2], s4b[3])),
                                           packh2(cc1[2], cc1[3])));
                float2 fA = h2f2(pA), fB = h2f2(pB), fC = h2f2(pC), fD = h2f2(pD);
                s2l0 += (fA.x + fA.y) + (fC.x + fC.y);
                s2l1 += (fB.x + fB.y) + (fD.x + fD.y);
                ph0[ntp * 2]     = pA;
                ph1[ntp * 2]     = pB;
                ph0[ntp * 2 + 1] = pC;
                ph1[ntp * 2 + 1] = pD;
            }
            #pragma unroll
            for (int kb = 0; kb < 4; kb++) {
                uint32_t a0 = ph0[2 * kb], a1 = ph1[2 * kb];
                uint32_t a2 = ph0[2 * kb + 1], a3 = ph1[2 * kb + 1];
                #pragma unroll
                for (int dtp = 0; dtp < 4; dtp++) {
                    uint32_t v0, v1, v2, v3;
                    ldsm_x4(v0, v1, v2, v3,
                            vb_base + (uint32_t)(dtp * 16 * 272 + (half * 4 + kb) * 32) + bofsV);
                    mma_f16(o[dtp * 2],     a0, a1, a2, a3, v0, v1);
                    mma_f16(o[dtp * 2 + 1], a0, a1, a2, a3, v2, v3);
                }
            }
        }
        __syncthreads();
        if (mt < 6) {
            stage_k(kaddr[mt & 1], Kp + (size_t)(mt + 2) * 8192, tid);
            stage_v(vaddr[mt & 1], VTp + (mt + 2) * 128, tid);
            CP_COMMIT();
        }
    }

    // register-only s2 reduce + direct epilogue
    s2l0 += __shfl_xor_sync(0xffffffffu, s2l0, 1);
    s2l0 += __shfl_xor_sync(0xffffffffu, s2l0, 2);
    s2l1 += __shfl_xor_sync(0xffffffffu, s2l1, 1);
    s2l1 += __shfl_xor_sync(0xffffffffu, s2l1, 2);
    const float i2r0 = 1.f / s2l0, i2r1 = 1.f / s2l1;

    const float* cm1p = &g_cm[1][f][h * 64];
    __half* yp0 = g_yh + (size_t)f * NTOK * DINV + (size_t)(n0 + r0) * DINV + h * 64;
    __half* yp1 = g_yh + (size_t)f * NTOK * DINV + (size_t)(n0 + r1) * DINV + h * 64;
    #pragma unroll
    for (int dt = 0; dt < 8; dt++) {
        int dc = dt * 8 + tig * 2;
        float2 cc = *(const float2*)&cm1p[dc];
        *(__half2*)(yp0 + dc) = __floats2half2_rn(o[dt][0] * i2r0 * cc.x,
                                                  o[dt][1] * i2r0 * cc.y);
        *(__half2*)(yp1 + dc) = __floats2half2_rn(o[dt][2] * i2r1 * cc.x,
                                                  o[dt][3] * i2r1 * cc.y);
    }
}

// ============================================================
extern "C" void kernel_launch(void* const* d_in, const int* in_sizes, int n_in,
                              void* d_out, int out_size)
{
    const float* x      = (const float*)d_in[0];
    const float* compat = (const float*)d_in[1];
    const float* code   = (const float*)d_in[2];
    const float* wc     = (const float*)d_in[3];
    const float* Wqkv   = (const float*)d_in[4];
    const float* bqkv   = (const float*)d_in[5];
    const float* Wproj  = (const float*)d_in[6];
    const float* bproj  = (const float*)d_in[7];
    const float* lnqg   = (const float*)d_in[8];
    const float* lnqb   = (const float*)d_in[9];
    const float* lnpg   = (const float*)d_in[10];
    const float* lnpb   = (const float*)d_in[11];
    float* out = (float*)d_out;

    cudaFuncSetAttribute(attn_kernel,
                         cudaFuncAttributeMaxDynamicSharedMemorySize, ATTN_SMEM_BYTES);
    cudaFuncSetAttribute(gemm_h<0>,
                         cudaFuncAttributeMaxDynamicSharedMemorySize, GH_BYTES);
    cudaFuncSetAttribute(gemm_h<1>,
                         cudaFuncAttributeMaxDynamicSharedMemorySize, GH_BYTES);

    code_mod_kernel<<<1, 512>>>(wc, code, lnqg, lnqb, lnpg, lnpb);
    prep_all<<<3076, 256>>>(compat, Wqkv, Wproj, x);
    gemm_h<0><<<dim3(12, 8, 4), 256, GH_BYTES>>>(bqkv, nullptr);
    attn_kernel<<<dim3(8, 32), 256, ATTN_SMEM_BYTES>>>(compat);
    gemm_h<1><<<dim3(4, 8, 4), 256, GH_BYTES>>>(bproj, out);
}